// round 4
// baseline (speedup 1.0000x reference)
#include <cuda_runtime.h>
#include <math.h>

// Problem constants (fixed by the reference)
#define NROWS_MAX 65536
#define DD 64
#define dH 32
#define HH 512
#define LL 8
#define KK 10

// ---------------------------------------------------------------------------
// Static device scratch (allocation-free rule: __device__ globals)
// ---------------------------------------------------------------------------
__device__ __align__(16) float g_X[2][NROWS_MAX * DD];     // ping-pong flow state
__device__ __align__(16) float g_H0[2][NROWS_MAX * HH];    // MLP hidden 0 (s,t)
__device__ __align__(16) float g_H1[2][NROWS_MAX * HH];    // MLP hidden 1 (s,t)
__device__ float g_det[NROWS_MAX];
__device__ float g_part[256 * 128];                        // batchnorm partials
__device__ __align__(16) float g_mu[DD];
__device__ __align__(16) float g_rstd[DD];

// ---------------------------------------------------------------------------
// f32x2 packed-FMA helpers (Blackwell sm_103a: 2x fp32 rate on the fma pipe)
// ---------------------------------------------------------------------------
__device__ __forceinline__ unsigned long long pk2(float x, float y) {
    unsigned long long r;
    asm("mov.b64 %0, {%1, %2};" : "=l"(r) : "f"(x), "f"(y));
    return r;
}
__device__ __forceinline__ void ffma2(unsigned long long& d,
                                      unsigned long long a,
                                      unsigned long long b) {
    asm("fma.rn.f32x2 %0, %1, %2, %0;" : "+l"(d) : "l"(a), "l"(b));
}
__device__ __forceinline__ float2 upk2(unsigned long long v) {
    float2 r;
    asm("mov.b64 {%0, %1}, %2;" : "=f"(r.x), "=f"(r.y) : "l"(v));
    return r;
}

// ---------------------------------------------------------------------------
// Copy x[:, :64] (row stride 65) into g_X[0]
// ---------------------------------------------------------------------------
__global__ void copy_in_kernel(const float* __restrict__ x,
                               float* __restrict__ X, int N) {
    int idx = blockIdx.x * 256 + threadIdx.x;
    if (idx < N * DD) {
        int i = idx >> 6;
        int j = idx & 63;
        X[idx] = x[(size_t)i * (DD + 1) + j];
    }
}

// ---------------------------------------------------------------------------
// Batchnorm statistics: pass 1 (per-block partial sums per column)
// grid = 256 blocks x 256 threads; each block handles rowsPerBlock rows.
// ---------------------------------------------------------------------------
__global__ __launch_bounds__(256) void stats1_kernel(
    const float* __restrict__ X, float* __restrict__ part, int rowsPerBlock) {
    int tid = threadIdx.x;
    int c = tid & 63;
    int rg = tid >> 6;  // 0..3
    size_t base = (size_t)blockIdx.x * rowsPerBlock;
    float s = 0.f, q = 0.f;
    for (int r = rg; r < rowsPerBlock; r += 4) {
        float v = X[(base + r) * DD + c];
        s += v;
        q += v * v;
    }
    __shared__ float ss[256], sq[256];
    ss[tid] = s;
    sq[tid] = q;
    __syncthreads();
    if (tid < 64) {
        float S = ss[tid] + ss[tid + 64] + ss[tid + 128] + ss[tid + 192];
        float Q = sq[tid] + sq[tid + 64] + sq[tid + 128] + sq[tid + 192];
        part[blockIdx.x * 128 + tid] = S;
        part[blockIdx.x * 128 + 64 + tid] = Q;
    }
}

// pass 2: finalize mu / rstd (64 threads)
__global__ void stats2_kernel(const float* __restrict__ part, int nb,
                              float invN, float* __restrict__ muArr,
                              float* __restrict__ rstdArr) {
    int c = threadIdx.x;
    float s = 0.f, q = 0.f;
    for (int b = 0; b < nb; b++) {
        s += part[b * 128 + c];
        q += part[b * 128 + 64 + c];
    }
    float m = s * invN;
    float var = q * invN - m * m;
    muArr[c] = m;
    rstdArr[c] = rsqrtf(var + 1e-5f);
}

// ---------------------------------------------------------------------------
// Generic GEMM C = relu(A @ W^T + b), f32x2 inner loop.
// A: (N x K) with row stride lda (optionally batchnorm-normalized on load)
// W: (Nout x K) row-major. blockIdx.z selects the s(0)/t(1) problem.
// Tile: BM=128, BN=128, BK=16, 256 threads, 8x8 per thread.
// ---------------------------------------------------------------------------
template <bool NORM>
__global__ __launch_bounds__(256, 2) void gemm_f2_kernel(
    const float* __restrict__ A0, const float* __restrict__ A1, int lda,
    const float* __restrict__ W0p, const float* __restrict__ W1p,
    const float* __restrict__ b0p, const float* __restrict__ b1p,
    float* __restrict__ C0, float* __restrict__ C1, int ldc, int K,
    const float* __restrict__ mu, const float* __restrict__ rstd) {
    const int z = blockIdx.z;
    const float* A = z ? A1 : A0;
    const float* W = z ? W1p : W0p;
    const float* bias = z ? b1p : b0p;
    float* C = z ? C1 : C0;

    __shared__ __align__(16) float As[16][132];
    __shared__ __align__(16) float Bs[16][132];

    const int tid = threadIdx.x;
    const int tx = tid & 15;
    const int ty = tid >> 4;
    const size_t row0 = (size_t)blockIdx.y * 128;
    const int col0 = blockIdx.x * 128;

    const int lr = tid >> 2;        // 0..63
    const int lk = (tid & 3) << 2;  // 0,4,8,12

    unsigned long long acc[8][4];
#pragma unroll
    for (int m = 0; m < 8; m++)
#pragma unroll
        for (int p = 0; p < 4; p++) acc[m][p] = 0ull;

    for (int k0 = 0; k0 < K; k0 += 16) {
        // load A tile (128 x 16), optionally normalized
#pragma unroll
        for (int it = 0; it < 2; ++it) {
            int r = lr + it * 64;
            float4 v = *(const float4*)(A + (row0 + r) * lda + k0 + lk);
            if (NORM) {
                int kg = k0 + lk;
                v.x = (v.x - mu[kg + 0]) * rstd[kg + 0];
                v.y = (v.y - mu[kg + 1]) * rstd[kg + 1];
                v.z = (v.z - mu[kg + 2]) * rstd[kg + 2];
                v.w = (v.w - mu[kg + 3]) * rstd[kg + 3];
            }
            As[lk + 0][r] = v.x;
            As[lk + 1][r] = v.y;
            As[lk + 2][r] = v.z;
            As[lk + 3][r] = v.w;
        }
        // load W tile (128 outputs x 16 k)
#pragma unroll
        for (int it = 0; it < 2; ++it) {
            int n = lr + it * 64;
            float4 v = *(const float4*)(W + (size_t)(col0 + n) * K + k0 + lk);
            Bs[lk + 0][n] = v.x;
            Bs[lk + 1][n] = v.y;
            Bs[lk + 2][n] = v.z;
            Bs[lk + 3][n] = v.w;
        }
        __syncthreads();
#pragma unroll
        for (int kk = 0; kk < 16; ++kk) {
            float4 a0 = *(const float4*)&As[kk][ty * 8];
            float4 a1 = *(const float4*)&As[kk][ty * 8 + 4];
            ulonglong2 bq0 = *(const ulonglong2*)&Bs[kk][tx * 8];
            ulonglong2 bq1 = *(const ulonglong2*)&Bs[kk][tx * 8 + 4];
            unsigned long long bp0 = bq0.x, bp1 = bq0.y, bp2 = bq1.x,
                               bp3 = bq1.y;
            float av[8] = {a0.x, a0.y, a0.z, a0.w, a1.x, a1.y, a1.z, a1.w};
#pragma unroll
            for (int m = 0; m < 8; m++) {
                unsigned long long am = pk2(av[m], av[m]);
                ffma2(acc[m][0], am, bp0);
                ffma2(acc[m][1], am, bp1);
                ffma2(acc[m][2], am, bp2);
                ffma2(acc[m][3], am, bp3);
            }
        }
        __syncthreads();
    }
    // epilogue: bias + relu
#pragma unroll
    for (int m = 0; m < 8; m++) {
        size_t row = row0 + ty * 8 + m;
        float* cr = C + row * ldc + col0 + tx * 8;
#pragma unroll
        for (int p = 0; p < 4; p++) {
            float2 v = upk2(acc[m][p]);
            int c = tx * 8 + 2 * p;
            v.x = fmaxf(v.x + bias[col0 + c], 0.f);
            v.y = fmaxf(v.y + bias[col0 + c + 1], 0.f);
            *(float2*)(cr + 2 * p) = v;
        }
    }
}

// ---------------------------------------------------------------------------
// GEMM3 + coupling, fully fused.
// Computes s = H1s @ sW2^T + sb2 and t = H1t @ tW2^T + tb2 (BN=64 = s||t),
// then in the epilogue:
//   x1n -> Xnext[:, :32], y2 = x2n*exp(s)+t -> Xnext[:, 32:], det += sum(s)
// Tile: BM=128, BN=64, K=512, 128 threads (ty 0..15, tx 0..7), 8x8/thread.
// ---------------------------------------------------------------------------
__global__ __launch_bounds__(128) void gemm3_couple_kernel(
    const float* __restrict__ H1s, const float* __restrict__ H1t,
    const float* __restrict__ W2s, const float* __restrict__ W2t,
    const float* __restrict__ b2s, const float* __restrict__ b2t,
    const float* __restrict__ X, float* __restrict__ Xn,
    const float* __restrict__ mu, const float* __restrict__ rstd,
    float* __restrict__ det, int x1off, int first) {
    __shared__ __align__(16) float smem[128 * 65];  // 33280 B
    float(*As_s)[132] = (float(*)[132])smem;
    float(*As_t)[132] = (float(*)[132])(smem + 16 * 132);
    float(*Bsm)[68] = (float(*)[68])(smem + 32 * 132);

    const int tid = threadIdx.x;
    const int tx = tid & 7;
    const int ty = tid >> 3;
    const size_t row0 = (size_t)blockIdx.x * 128;
    const int lr = tid >> 2;        // 0..31
    const int lk = (tid & 3) << 2;  // 0,4,8,12

    unsigned long long acc[8][4];
#pragma unroll
    for (int m = 0; m < 8; m++)
#pragma unroll
        for (int p = 0; p < 4; p++) acc[m][p] = 0ull;

    for (int k0 = 0; k0 < HH; k0 += 16) {
#pragma unroll
        for (int j = 0; j < 4; ++j) {
            int r = lr + j * 32;
            float4 vs = *(const float4*)(H1s + (row0 + r) * HH + k0 + lk);
            float4 vt = *(const float4*)(H1t + (row0 + r) * HH + k0 + lk);
            As_s[lk + 0][r] = vs.x;
            As_s[lk + 1][r] = vs.y;
            As_s[lk + 2][r] = vs.z;
            As_s[lk + 3][r] = vs.w;
            As_t[lk + 0][r] = vt.x;
            As_t[lk + 1][r] = vt.y;
            As_t[lk + 2][r] = vt.z;
            As_t[lk + 3][r] = vt.w;
        }
        {
            int n = lr;  // 0..31
            float4 v = *(const float4*)(W2s + (size_t)n * HH + k0 + lk);
            Bsm[lk + 0][n] = v.x;
            Bsm[lk + 1][n] = v.y;
            Bsm[lk + 2][n] = v.z;
            Bsm[lk + 3][n] = v.w;
            float4 w = *(const float4*)(W2t + (size_t)n * HH + k0 + lk);
            Bsm[lk + 0][32 + n] = w.x;
            Bsm[lk + 1][32 + n] = w.y;
            Bsm[lk + 2][32 + n] = w.z;
            Bsm[lk + 3][32 + n] = w.w;
        }
        __syncthreads();
        const float(*Aw)[132] = (tx < 4) ? As_s : As_t;
#pragma unroll
        for (int kk = 0; kk < 16; ++kk) {
            float4 a0 = *(const float4*)&Aw[kk][ty * 8];
            float4 a1 = *(const float4*)&Aw[kk][ty * 8 + 4];
            ulonglong2 bq0 = *(const ulonglong2*)&Bsm[kk][tx * 8];
            ulonglong2 bq1 = *(const ulonglong2*)&Bsm[kk][tx * 8 + 4];
            unsigned long long bp0 = bq0.x, bp1 = bq0.y, bp2 = bq1.x,
                               bp3 = bq1.y;
            float av[8] = {a0.x, a0.y, a0.z, a0.w, a1.x, a1.y, a1.z, a1.w};
#pragma unroll
            for (int m = 0; m < 8; m++) {
                unsigned long long am = pk2(av[m], av[m]);
                ffma2(acc[m][0], am, bp0);
                ffma2(acc[m][1], am, bp1);
                ffma2(acc[m][2], am, bp2);
                ffma2(acc[m][3], am, bp3);
            }
        }
        __syncthreads();
    }

    // write s|t tile (+bias) to smem (pitch 65 to avoid bank conflicts)
    float* Cs = smem;  // reuse; safe: loop ended with __syncthreads()
    {
        int colb = tx * 8;
#pragma unroll
        for (int p = 0; p < 4; p++) {
            int c = colb + 2 * p;
            float blo = (c < 32) ? b2s[c] : b2t[c - 32];
            float bhi = (c + 1 < 32) ? b2s[c + 1] : b2t[c + 1 - 32];
#pragma unroll
            for (int m = 0; m < 8; m++) {
                float2 v = upk2(acc[m][p]);
                Cs[(ty * 8 + m) * 65 + c] = v.x + blo;
                Cs[(ty * 8 + m) * 65 + c + 1] = v.y + bhi;
            }
        }
    }
    __syncthreads();

    // coupling: one thread per row
    {
        int r = tid;
        size_t grow = row0 + r;
        const float* xr = X + grow * DD;
        float* xo = Xn + grow * DD;
        int x2off = dH - x1off;  // {0,32} -> {32,0}
        float ssum = 0.f;
#pragma unroll 4
        for (int j = 0; j < dH; j++) {
            float s = Cs[r * 65 + j];
            float t = Cs[r * 65 + 32 + j];
            float x1 = xr[x1off + j];
            float x2 = xr[x2off + j];
            xo[j] = (x1 - mu[x1off + j]) * rstd[x1off + j];
            float x2n = (x2 - mu[x2off + j]) * rstd[x2off + j];
            xo[dH + j] = x2n * expf(s) + t;
            ssum += s;
        }
        det[grow] = first ? ssum : (det[grow] + ssum);
    }
}

// ---------------------------------------------------------------------------
// GMM log-likelihood + copy y out; one thread per row.
// ---------------------------------------------------------------------------
__global__ __launch_bounds__(256) void gmm_kernel(
    const float* __restrict__ X, const float* __restrict__ means,
    const float* __restrict__ det, float* __restrict__ out, int N, int full) {
    __shared__ float sm[KK * DD];
    int tid = threadIdx.x;
    for (int i = tid; i < KK * DD; i += 256) sm[i] = means[i];
    __syncthreads();

    size_t i = (size_t)blockIdx.x * 256 + tid;
    float4 y4[16];
    const float4* xr = (const float4*)(X + i * DD);
#pragma unroll
    for (int q = 0; q < 16; q++) y4[q] = xr[q];
    float4* yo = (float4*)(out + i * DD);
#pragma unroll
    for (int q = 0; q < 16; q++) yo[q] = y4[q];

    if (!full) return;

    const float CD = (float)(64.0 * 1.8378770664093453);  // D*log(2*pi)
    float lp[KK];
    float mx = -1e30f;
#pragma unroll
    for (int k = 0; k < KK; k++) {
        const float* mrow = sm + k * DD;
        float accv = 0.f;
#pragma unroll
        for (int q = 0; q < 16; q++) {
            float4 m4 = *(const float4*)(mrow + q * 4);
            float dx = y4[q].x - m4.x;
            accv += dx * dx;
            dx = y4[q].y - m4.y;
            accv += dx * dx;
            dx = y4[q].z - m4.z;
            accv += dx * dx;
            dx = y4[q].w - m4.w;
            accv += dx * dx;
        }
        float v = -0.5f * (accv + CD);
        lp[k] = v;
        mx = fmaxf(mx, v);
    }
    float se = 0.f;
#pragma unroll
    for (int k = 0; k < KK; k++) se += expf(lp[k] - mx);
    float ll = mx + logf(se) - logf((float)KK);

    size_t oll = (size_t)N * DD + 1;
    out[oll + i] = ll;
    out[oll + N + i] = det[i];
}

// Final scalar reductions: loss, ll.mean, det_s.mean
__global__ void final_reduce_kernel(float* __restrict__ out, int N) {
    int tid = threadIdx.x;
    size_t oll = (size_t)N * DD + 1;
    size_t odet = oll + N;
    float sll = 0.f, sdet = 0.f;
    for (int i = tid; i < N; i += 1024) {
        sll += out[oll + i];
        sdet += out[odet + i];
    }
    __shared__ float a[1024], b[1024];
    a[tid] = sll;
    b[tid] = sdet;
    __syncthreads();
    for (int s = 512; s > 0; s >>= 1) {
        if (tid < s) {
            a[tid] += a[tid + s];
            b[tid] += b[tid + s];
        }
        __syncthreads();
    }
    if (tid == 0) {
        float llm = a[0] / (float)N;
        float dm = b[0] / (float)N;
        out[(size_t)N * DD] = -(dm + llm);  // loss
        out[odet + N] = llm;                // log_likelihood.mean()
        out[odet + N + 1] = dm;             // det_s.mean()
    }
}

// ---------------------------------------------------------------------------
// Host launcher
// ---------------------------------------------------------------------------
static float* symaddr(const void* s) {
    void* p = nullptr;
    cudaGetSymbolAddress(&p, s);
    return (float*)p;
}

extern "C" void kernel_launch(void* const* d_in, const int* in_sizes, int n_in,
                              void* d_out, int out_size) {
    const float* x = (const float*)d_in[0];
    const float* sW0 = (const float*)d_in[1];
    const float* sb0 = (const float*)d_in[2];
    const float* sW1 = (const float*)d_in[3];
    const float* sb1 = (const float*)d_in[4];
    const float* sW2 = (const float*)d_in[5];
    const float* sb2 = (const float*)d_in[6];
    const float* tW0 = (const float*)d_in[7];
    const float* tb0 = (const float*)d_in[8];
    const float* tW1 = (const float*)d_in[9];
    const float* tb1 = (const float*)d_in[10];
    const float* tW2 = (const float*)d_in[11];
    const float* tb2 = (const float*)d_in[12];
    const float* means = (const float*)d_in[13];
    float* out = (float*)d_out;

    const int N = in_sizes[0] / (DD + 1);
    const int full = (out_size >= (long long)N * DD + 2 * N + 3) ? 1 : 0;

    float* X = symaddr(g_X);
    float* H0 = symaddr(g_H0);
    float* H1 = symaddr(g_H1);
    float* det = symaddr(g_det);
    float* part = symaddr(g_part);
    float* mu = symaddr(g_mu);
    float* rstd = symaddr(g_rstd);

    const size_t XS = (size_t)N * DD;
    const size_t HS = (size_t)N * HH;

    copy_in_kernel<<<(N * DD + 255) / 256, 256>>>(x, X, N);

    int cur = 0;
    for (int l = 0; l < LL; l++) {
        float* Xc = X + (size_t)cur * XS;
        float* Xnext = X + (size_t)(cur ^ 1) * XS;
        stats1_kernel<<<256, 256>>>(Xc, part, N / 256);
        stats2_kernel<<<1, 64>>>(part, 256, 1.0f / (float)N, mu, rstd);

        const int x1off = (l & 1) ? dH : 0;

        // GEMM1: (N x 32) -> (N x 512), normalized A, relu. z = s/t.
        gemm_f2_kernel<true><<<dim3(HH / 128, N / 128, 2), 256>>>(
            Xc + x1off, Xc + x1off, DD,
            sW0 + (size_t)l * HH * dH, tW0 + (size_t)l * HH * dH,
            sb0 + (size_t)l * HH, tb0 + (size_t)l * HH,
            H0, H0 + HS, HH, dH, mu + x1off, rstd + x1off);

        // GEMM2: (N x 512) -> (N x 512), relu. z = s/t.
        gemm_f2_kernel<false><<<dim3(HH / 128, N / 128, 2), 256>>>(
            H0, H0 + HS, HH,
            sW1 + (size_t)l * HH * HH, tW1 + (size_t)l * HH * HH,
            sb1 + (size_t)l * HH, tb1 + (size_t)l * HH,
            H1, H1 + HS, HH, HH, nullptr, nullptr);

        // GEMM3 (s||t) + full coupling epilogue
        gemm3_couple_kernel<<<N / 128, 128>>>(
            H1, H1 + HS,
            sW2 + (size_t)l * dH * HH, tW2 + (size_t)l * dH * HH,
            sb2 + (size_t)l * dH, tb2 + (size_t)l * dH,
            Xc, Xnext, mu, rstd, det, x1off, (l == 0) ? 1 : 0);

        cur ^= 1;
    }

    gmm_kernel<<<N / 256, 256>>>(X + (size_t)cur * XS, means, det, out, N,
                                 full);
    if (full) final_reduce_kernel<<<1, 1024>>>(out, N);
}

// round 5
// speedup vs baseline: 1.0022x; 1.0022x over previous
#include <cuda_runtime.h>
#include <math.h>

// Problem constants (fixed by the reference)
#define NROWS_MAX 65536
#define DD 64
#define dH 32
#define HH 512
#define LL 8
#define KK 10

// ---------------------------------------------------------------------------
// Static device scratch (allocation-free rule: __device__ globals)
// ---------------------------------------------------------------------------
__device__ __align__(16) float g_X[2][NROWS_MAX * DD];     // ping-pong flow state
__device__ __align__(16) float g_H0[2][NROWS_MAX * HH];    // MLP hidden 0 (s,t)
__device__ __align__(16) float g_H1[2][NROWS_MAX * HH];    // MLP hidden 1 (s,t)
__device__ float g_det[NROWS_MAX];
__device__ float g_part[256 * 128];                        // batchnorm partials
__device__ __align__(16) float g_mu[DD];
__device__ __align__(16) float g_rstd[DD];

// ---------------------------------------------------------------------------
// f32x2 packed-FMA helpers (Blackwell sm_103a: 2x fp32 rate on the fma pipe)
// ---------------------------------------------------------------------------
__device__ __forceinline__ unsigned long long pk2(float x, float y) {
    unsigned long long r;
    asm("mov.b64 %0, {%1, %2};" : "=l"(r) : "f"(x), "f"(y));
    return r;
}
__device__ __forceinline__ void ffma2(unsigned long long& d,
                                      unsigned long long a,
                                      unsigned long long b) {
    asm("fma.rn.f32x2 %0, %1, %2, %0;" : "+l"(d) : "l"(a), "l"(b));
}
__device__ __forceinline__ float2 upk2(unsigned long long v) {
    float2 r;
    asm("mov.b64 {%0, %1}, %2;" : "=f"(r.x), "=f"(r.y) : "l"(v));
    return r;
}

// ---------------------------------------------------------------------------
// Copy x[:, :64] (row stride 65) into g_X[0]
// ---------------------------------------------------------------------------
__global__ void copy_in_kernel(const float* __restrict__ x,
                               float* __restrict__ X, int N) {
    int idx = blockIdx.x * 256 + threadIdx.x;
    if (idx < N * DD) {
        int i = idx >> 6;
        int j = idx & 63;
        X[idx] = x[(size_t)i * (DD + 1) + j];
    }
}

// ---------------------------------------------------------------------------
// Batchnorm statistics: pass 1 (per-block partial sums per column)
// grid = 256 blocks x 256 threads; each block handles rowsPerBlock rows.
// ---------------------------------------------------------------------------
__global__ __launch_bounds__(256) void stats1_kernel(
    const float* __restrict__ X, float* __restrict__ part, int rowsPerBlock) {
    int tid = threadIdx.x;
    int c = tid & 63;
    int rg = tid >> 6;  // 0..3
    size_t base = (size_t)blockIdx.x * rowsPerBlock;
    float s = 0.f, q = 0.f;
    for (int r = rg; r < rowsPerBlock; r += 4) {
        float v = X[(base + r) * DD + c];
        s += v;
        q += v * v;
    }
    __shared__ float ss[256], sq[256];
    ss[tid] = s;
    sq[tid] = q;
    __syncthreads();
    if (tid < 64) {
        float S = ss[tid] + ss[tid + 64] + ss[tid + 128] + ss[tid + 192];
        float Q = sq[tid] + sq[tid + 64] + sq[tid + 128] + sq[tid + 192];
        part[blockIdx.x * 128 + tid] = S;
        part[blockIdx.x * 128 + 64 + tid] = Q;
    }
}

// pass 2: finalize mu / rstd (64 threads)
__global__ void stats2_kernel(const float* __restrict__ part, int nb,
                              float invN, float* __restrict__ muArr,
                              float* __restrict__ rstdArr) {
    int c = threadIdx.x;
    float s = 0.f, q = 0.f;
    for (int b = 0; b < nb; b++) {
        s += part[b * 128 + c];
        q += part[b * 128 + 64 + c];
    }
    float m = s * invN;
    float var = q * invN - m * m;
    muArr[c] = m;
    rstdArr[c] = rsqrtf(var + 1e-5f);
}

// ---------------------------------------------------------------------------
// Generic GEMM C = relu(A @ W^T + b), f32x2 inner loop.
// A: (N x K) with row stride lda (optionally batchnorm-normalized on load)
// W: (Nout x K) row-major. blockIdx.z selects the s(0)/t(1) problem.
// Tile: BM=128, BN=128, BK=16, 256 threads, 8x8 per thread.
// ---------------------------------------------------------------------------
template <bool NORM>
__global__ __launch_bounds__(256, 2) void gemm_f2_kernel(
    const float* __restrict__ A0, const float* __restrict__ A1, int lda,
    const float* __restrict__ W0p, const float* __restrict__ W1p,
    const float* __restrict__ b0p, const float* __restrict__ b1p,
    float* __restrict__ C0, float* __restrict__ C1, int ldc, int K,
    const float* __restrict__ mu, const float* __restrict__ rstd) {
    const int z = blockIdx.z;
    const float* A = z ? A1 : A0;
    const float* W = z ? W1p : W0p;
    const float* bias = z ? b1p : b0p;
    float* C = z ? C1 : C0;

    __shared__ __align__(16) float As[16][132];
    __shared__ __align__(16) float Bs[16][132];

    const int tid = threadIdx.x;
    const int tx = tid & 15;
    const int ty = tid >> 4;
    const size_t row0 = (size_t)blockIdx.y * 128;
    const int col0 = blockIdx.x * 128;

    const int lr = tid >> 2;        // 0..63
    const int lk = (tid & 3) << 2;  // 0,4,8,12

    unsigned long long acc[8][4];
#pragma unroll
    for (int m = 0; m < 8; m++)
#pragma unroll
        for (int p = 0; p < 4; p++) acc[m][p] = 0ull;

    for (int k0 = 0; k0 < K; k0 += 16) {
        // load A tile (128 x 16), optionally normalized
#pragma unroll
        for (int it = 0; it < 2; ++it) {
            int r = lr + it * 64;
            float4 v = *(const float4*)(A + (row0 + r) * lda + k0 + lk);
            if (NORM) {
                int kg = k0 + lk;
                v.x = (v.x - mu[kg + 0]) * rstd[kg + 0];
                v.y = (v.y - mu[kg + 1]) * rstd[kg + 1];
                v.z = (v.z - mu[kg + 2]) * rstd[kg + 2];
                v.w = (v.w - mu[kg + 3]) * rstd[kg + 3];
            }
            As[lk + 0][r] = v.x;
            As[lk + 1][r] = v.y;
            As[lk + 2][r] = v.z;
            As[lk + 3][r] = v.w;
        }
        // load W tile (128 outputs x 16 k)
#pragma unroll
        for (int it = 0; it < 2; ++it) {
            int n = lr + it * 64;
            float4 v = *(const float4*)(W + (size_t)(col0 + n) * K + k0 + lk);
            Bs[lk + 0][n] = v.x;
            Bs[lk + 1][n] = v.y;
            Bs[lk + 2][n] = v.z;
            Bs[lk + 3][n] = v.w;
        }
        __syncthreads();
#pragma unroll
        for (int kk = 0; kk < 16; ++kk) {
            float4 a0 = *(const float4*)&As[kk][ty * 8];
            float4 a1 = *(const float4*)&As[kk][ty * 8 + 4];
            ulonglong2 bq0 = *(const ulonglong2*)&Bs[kk][tx * 8];
            ulonglong2 bq1 = *(const ulonglong2*)&Bs[kk][tx * 8 + 4];
            unsigned long long bp0 = bq0.x, bp1 = bq0.y, bp2 = bq1.x,
                               bp3 = bq1.y;
            float av[8] = {a0.x, a0.y, a0.z, a0.w, a1.x, a1.y, a1.z, a1.w};
#pragma unroll
            for (int m = 0; m < 8; m++) {
                unsigned long long am = pk2(av[m], av[m]);
                ffma2(acc[m][0], am, bp0);
                ffma2(acc[m][1], am, bp1);
                ffma2(acc[m][2], am, bp2);
                ffma2(acc[m][3], am, bp3);
            }
        }
        __syncthreads();
    }
    // epilogue: bias + relu
#pragma unroll
    for (int m = 0; m < 8; m++) {
        size_t row = row0 + ty * 8 + m;
        float* cr = C + row * ldc + col0 + tx * 8;
#pragma unroll
        for (int p = 0; p < 4; p++) {
            float2 v = upk2(acc[m][p]);
            int c = tx * 8 + 2 * p;
            v.x = fmaxf(v.x + bias[col0 + c], 0.f);
            v.y = fmaxf(v.y + bias[col0 + c + 1], 0.f);
            *(float2*)(cr + 2 * p) = v;
        }
    }
}

// ---------------------------------------------------------------------------
// GEMM3 + coupling, fully fused.
// Computes s = H1s @ sW2^T + sb2 and t = H1t @ tW2^T + tb2 (BN=64 = s||t),
// then in the epilogue:
//   x1n -> Xnext[:, :32], y2 = x2n*exp(s)+t -> Xnext[:, 32:], det += sum(s)
// Tile: BM=128, BN=64, K=512, 128 threads (ty 0..15, tx 0..7), 8x8/thread.
// ---------------------------------------------------------------------------
__global__ __launch_bounds__(128) void gemm3_couple_kernel(
    const float* __restrict__ H1s, const float* __restrict__ H1t,
    const float* __restrict__ W2s, const float* __restrict__ W2t,
    const float* __restrict__ b2s, const float* __restrict__ b2t,
    const float* __restrict__ X, float* __restrict__ Xn,
    const float* __restrict__ mu, const float* __restrict__ rstd,
    float* __restrict__ det, int x1off, int first) {
    __shared__ __align__(16) float smem[128 * 65];  // 33280 B
    float(*As_s)[132] = (float(*)[132])smem;
    float(*As_t)[132] = (float(*)[132])(smem + 16 * 132);
    float(*Bsm)[68] = (float(*)[68])(smem + 32 * 132);

    const int tid = threadIdx.x;
    const int tx = tid & 7;
    const int ty = tid >> 3;
    const size_t row0 = (size_t)blockIdx.x * 128;
    const int lr = tid >> 2;        // 0..31
    const int lk = (tid & 3) << 2;  // 0,4,8,12

    unsigned long long acc[8][4];
#pragma unroll
    for (int m = 0; m < 8; m++)
#pragma unroll
        for (int p = 0; p < 4; p++) acc[m][p] = 0ull;

    for (int k0 = 0; k0 < HH; k0 += 16) {
#pragma unroll
        for (int j = 0; j < 4; ++j) {
            int r = lr + j * 32;
            float4 vs = *(const float4*)(H1s + (row0 + r) * HH + k0 + lk);
            float4 vt = *(const float4*)(H1t + (row0 + r) * HH + k0 + lk);
            As_s[lk + 0][r] = vs.x;
            As_s[lk + 1][r] = vs.y;
            As_s[lk + 2][r] = vs.z;
            As_s[lk + 3][r] = vs.w;
            As_t[lk + 0][r] = vt.x;
            As_t[lk + 1][r] = vt.y;
            As_t[lk + 2][r] = vt.z;
            As_t[lk + 3][r] = vt.w;
        }
        {
            int n = lr;  // 0..31
            float4 v = *(const float4*)(W2s + (size_t)n * HH + k0 + lk);
            Bsm[lk + 0][n] = v.x;
            Bsm[lk + 1][n] = v.y;
            Bsm[lk + 2][n] = v.z;
            Bsm[lk + 3][n] = v.w;
            float4 w = *(const float4*)(W2t + (size_t)n * HH + k0 + lk);
            Bsm[lk + 0][32 + n] = w.x;
            Bsm[lk + 1][32 + n] = w.y;
            Bsm[lk + 2][32 + n] = w.z;
            Bsm[lk + 3][32 + n] = w.w;
        }
        __syncthreads();
        const float(*Aw)[132] = (tx < 4) ? As_s : As_t;
#pragma unroll
        for (int kk = 0; kk < 16; ++kk) {
            float4 a0 = *(const float4*)&Aw[kk][ty * 8];
            float4 a1 = *(const float4*)&Aw[kk][ty * 8 + 4];
            ulonglong2 bq0 = *(const ulonglong2*)&Bsm[kk][tx * 8];
            ulonglong2 bq1 = *(const ulonglong2*)&Bsm[kk][tx * 8 + 4];
            unsigned long long bp0 = bq0.x, bp1 = bq0.y, bp2 = bq1.x,
                               bp3 = bq1.y;
            float av[8] = {a0.x, a0.y, a0.z, a0.w, a1.x, a1.y, a1.z, a1.w};
#pragma unroll
            for (int m = 0; m < 8; m++) {
                unsigned long long am = pk2(av[m], av[m]);
                ffma2(acc[m][0], am, bp0);
                ffma2(acc[m][1], am, bp1);
                ffma2(acc[m][2], am, bp2);
                ffma2(acc[m][3], am, bp3);
            }
        }
        __syncthreads();
    }

    // write s|t tile (+bias) to smem (pitch 65 to avoid bank conflicts)
    float* Cs = smem;  // reuse; safe: loop ended with __syncthreads()
    {
        int colb = tx * 8;
#pragma unroll
        for (int p = 0; p < 4; p++) {
            int c = colb + 2 * p;
            float blo = (c < 32) ? b2s[c] : b2t[c - 32];
            float bhi = (c + 1 < 32) ? b2s[c + 1] : b2t[c + 1 - 32];
#pragma unroll
            for (int m = 0; m < 8; m++) {
                float2 v = upk2(acc[m][p]);
                Cs[(ty * 8 + m) * 65 + c] = v.x + blo;
                Cs[(ty * 8 + m) * 65 + c + 1] = v.y + bhi;
            }
        }
    }
    __syncthreads();

    // coupling: one thread per row
    {
        int r = tid;
        size_t grow = row0 + r;
        const float* xr = X + grow * DD;
        float* xo = Xn + grow * DD;
        int x2off = dH - x1off;  // {0,32} -> {32,0}
        float ssum = 0.f;
#pragma unroll 4
        for (int j = 0; j < dH; j++) {
            float s = Cs[r * 65 + j];
            float t = Cs[r * 65 + 32 + j];
            float x1 = xr[x1off + j];
            float x2 = xr[x2off + j];
            xo[j] = (x1 - mu[x1off + j]) * rstd[x1off + j];
            float x2n = (x2 - mu[x2off + j]) * rstd[x2off + j];
            xo[dH + j] = x2n * expf(s) + t;
            ssum += s;
        }
        det[grow] = first ? ssum : (det[grow] + ssum);
    }
}

// ---------------------------------------------------------------------------
// GMM log-likelihood + copy y out; one thread per row.
// ---------------------------------------------------------------------------
__global__ __launch_bounds__(256) void gmm_kernel(
    const float* __restrict__ X, const float* __restrict__ means,
    const float* __restrict__ det, float* __restrict__ out, int N, int full) {
    __shared__ float sm[KK * DD];
    int tid = threadIdx.x;
    for (int i = tid; i < KK * DD; i += 256) sm[i] = means[i];
    __syncthreads();

    size_t i = (size_t)blockIdx.x * 256 + tid;
    float4 y4[16];
    const float4* xr = (const float4*)(X + i * DD);
#pragma unroll
    for (int q = 0; q < 16; q++) y4[q] = xr[q];
    float4* yo = (float4*)(out + i * DD);
#pragma unroll
    for (int q = 0; q < 16; q++) yo[q] = y4[q];

    if (!full) return;

    const float CD = (float)(64.0 * 1.8378770664093453);  // D*log(2*pi)
    float lp[KK];
    float mx = -1e30f;
#pragma unroll
    for (int k = 0; k < KK; k++) {
        const float* mrow = sm + k * DD;
        float accv = 0.f;
#pragma unroll
        for (int q = 0; q < 16; q++) {
            float4 m4 = *(const float4*)(mrow + q * 4);
            float dx = y4[q].x - m4.x;
            accv += dx * dx;
            dx = y4[q].y - m4.y;
            accv += dx * dx;
            dx = y4[q].z - m4.z;
            accv += dx * dx;
            dx = y4[q].w - m4.w;
            accv += dx * dx;
        }
        float v = -0.5f * (accv + CD);
        lp[k] = v;
        mx = fmaxf(mx, v);
    }
    float se = 0.f;
#pragma unroll
    for (int k = 0; k < KK; k++) se += expf(lp[k] - mx);
    float ll = mx + logf(se) - logf((float)KK);

    size_t oll = (size_t)N * DD + 1;
    out[oll + i] = ll;
    out[oll + N + i] = det[i];
}

// Final scalar reductions: loss, ll.mean, det_s.mean
__global__ void final_reduce_kernel(float* __restrict__ out, int N) {
    int tid = threadIdx.x;
    size_t oll = (size_t)N * DD + 1;
    size_t odet = oll + N;
    float sll = 0.f, sdet = 0.f;
    for (int i = tid; i < N; i += 1024) {
        sll += out[oll + i];
        sdet += out[odet + i];
    }
    __shared__ float a[1024], b[1024];
    a[tid] = sll;
    b[tid] = sdet;
    __syncthreads();
    for (int s = 512; s > 0; s >>= 1) {
        if (tid < s) {
            a[tid] += a[tid + s];
            b[tid] += b[tid + s];
        }
        __syncthreads();
    }
    if (tid == 0) {
        float llm = a[0] / (float)N;
        float dm = b[0] / (float)N;
        out[(size_t)N * DD] = -(dm + llm);  // loss
        out[odet + N] = llm;                // log_likelihood.mean()
        out[odet + N + 1] = dm;             // det_s.mean()
    }
}

// ---------------------------------------------------------------------------
// Host launcher
// ---------------------------------------------------------------------------
static float* symaddr(const void* s) {
    void* p = nullptr;
    cudaGetSymbolAddress(&p, s);
    return (float*)p;
}

extern "C" void kernel_launch(void* const* d_in, const int* in_sizes, int n_in,
                              void* d_out, int out_size) {
    const float* x = (const float*)d_in[0];
    const float* sW0 = (const float*)d_in[1];
    const float* sb0 = (const float*)d_in[2];
    const float* sW1 = (const float*)d_in[3];
    const float* sb1 = (const float*)d_in[4];
    const float* sW2 = (const float*)d_in[5];
    const float* sb2 = (const float*)d_in[6];
    const float* tW0 = (const float*)d_in[7];
    const float* tb0 = (const float*)d_in[8];
    const float* tW1 = (const float*)d_in[9];
    const float* tb1 = (const float*)d_in[10];
    const float* tW2 = (const float*)d_in[11];
    const float* tb2 = (const float*)d_in[12];
    const float* means = (const float*)d_in[13];
    float* out = (float*)d_out;

    const int N = in_sizes[0] / (DD + 1);
    const int full = (out_size >= (long long)N * DD + 2 * N + 3) ? 1 : 0;

    float* X = symaddr(g_X);
    float* H0 = symaddr(g_H0);
    float* H1 = symaddr(g_H1);
    float* det = symaddr(g_det);
    float* part = symaddr(g_part);
    float* mu = symaddr(g_mu);
    float* rstd = symaddr(g_rstd);

    const size_t XS = (size_t)N * DD;
    const size_t HS = (size_t)N * HH;

    copy_in_kernel<<<(N * DD + 255) / 256, 256>>>(x, X, N);

    int cur = 0;
    for (int l = 0; l < LL; l++) {
        float* Xc = X + (size_t)cur * XS;
        float* Xnext = X + (size_t)(cur ^ 1) * XS;
        stats1_kernel<<<256, 256>>>(Xc, part, N / 256);
        stats2_kernel<<<1, 64>>>(part, 256, 1.0f / (float)N, mu, rstd);

        const int x1off = (l & 1) ? dH : 0;

        // GEMM1: (N x 32) -> (N x 512), normalized A, relu. z = s/t.
        gemm_f2_kernel<true><<<dim3(HH / 128, N / 128, 2), 256>>>(
            Xc + x1off, Xc + x1off, DD,
            sW0 + (size_t)l * HH * dH, tW0 + (size_t)l * HH * dH,
            sb0 + (size_t)l * HH, tb0 + (size_t)l * HH,
            H0, H0 + HS, HH, dH, mu + x1off, rstd + x1off);

        // GEMM2: (N x 512) -> (N x 512), relu. z = s/t.
        gemm_f2_kernel<false><<<dim3(HH / 128, N / 128, 2), 256>>>(
            H0, H0 + HS, HH,
            sW1 + (size_t)l * HH * HH, tW1 + (size_t)l * HH * HH,
            sb1 + (size_t)l * HH, tb1 + (size_t)l * HH,
            H1, H1 + HS, HH, HH, nullptr, nullptr);

        // GEMM3 (s||t) + full coupling epilogue
        gemm3_couple_kernel<<<N / 128, 128>>>(
            H1, H1 + HS,
            sW2 + (size_t)l * dH * HH, tW2 + (size_t)l * dH * HH,
            sb2 + (size_t)l * dH, tb2 + (size_t)l * dH,
            Xc, Xnext, mu, rstd, det, x1off, (l == 0) ? 1 : 0);

        cur ^= 1;
    }

    gmm_kernel<<<N / 256, 256>>>(X + (size_t)cur * XS, means, det, out, N,
                                 full);
    if (full) final_reduce_kernel<<<1, 1024>>>(out, N);
}

// round 7
// speedup vs baseline: 1.3092x; 1.3064x over previous
#include <cuda_runtime.h>
#include <math.h>
#include <stdint.h>

// Problem constants (fixed by the reference)
#define NROWS_MAX 65536
#define DD 64
#define dH 32
#define HH 512
#define LL 8
#define KK 10

// ---------------------------------------------------------------------------
// Static device scratch (allocation-free rule: __device__ globals)
// ---------------------------------------------------------------------------
__device__ __align__(16) float g_X[2][NROWS_MAX * DD];   // ping-pong flow state
__device__ __align__(16) float g_H0[2][NROWS_MAX * HH];  // hidden 0 (s,t)
__device__ __align__(16) float g_H1[2][NROWS_MAX * HH];  // hidden 1 (s,t)
__device__ float g_det[NROWS_MAX];
__device__ float g_part[256 * 128];
__device__ __align__(16) float g_mu[DD];
__device__ __align__(16) float g_rstd[DD];

// ---------------------------------------------------------------------------
// tf32 helpers (portable PTX, no "a"-features)
// ---------------------------------------------------------------------------
__device__ __forceinline__ float tf32r(float x) {
    float r;
    asm("cvt.rna.tf32.f32 %0, %1;" : "=f"(r) : "f"(x));
    return r;
}

__device__ __forceinline__ void mma_tf32(float* c, const uint32_t* a,
                                         const uint32_t* b) {
    asm volatile(
        "mma.sync.aligned.m16n8k8.row.col.f32.tf32.tf32.f32 "
        "{%0,%1,%2,%3}, {%4,%5,%6,%7}, {%8,%9}, {%0,%1,%2,%3};"
        : "+f"(c[0]), "+f"(c[1]), "+f"(c[2]), "+f"(c[3])
        : "r"(a[0]), "r"(a[1]), "r"(a[2]), "r"(a[3]), "r"(b[0]), "r"(b[1]));
}

// split v -> (hi, lo) both tf32-representable; hi+lo ~ 22 mantissa bits
__device__ __forceinline__ void split4(float4 v, float4& h, float4& l) {
    h.x = tf32r(v.x); h.y = tf32r(v.y); h.z = tf32r(v.z); h.w = tf32r(v.w);
    l.x = tf32r(v.x - h.x); l.y = tf32r(v.y - h.y);
    l.z = tf32r(v.z - h.z); l.w = tf32r(v.w - h.w);
}

// ---------------------------------------------------------------------------
// small kernels (unchanged, correctness-proven)
// ---------------------------------------------------------------------------
__global__ void copy_in_kernel(const float* __restrict__ x,
                               float* __restrict__ X, int N) {
    int idx = blockIdx.x * 256 + threadIdx.x;
    if (idx < N * DD) {
        int i = idx >> 6;
        int j = idx & 63;
        X[idx] = x[(size_t)i * (DD + 1) + j];
    }
}

__global__ __launch_bounds__(256) void stats1_kernel(
    const float* __restrict__ X, float* __restrict__ part, int rowsPerBlock) {
    int tid = threadIdx.x;
    int c = tid & 63;
    int rg = tid >> 6;
    size_t base = (size_t)blockIdx.x * rowsPerBlock;
    float s = 0.f, q = 0.f;
    for (int r = rg; r < rowsPerBlock; r += 4) {
        float v = X[(base + r) * DD + c];
        s += v;
        q += v * v;
    }
    __shared__ float ss[256], sq[256];
    ss[tid] = s;
    sq[tid] = q;
    __syncthreads();
    if (tid < 64) {
        float S = ss[tid] + ss[tid + 64] + ss[tid + 128] + ss[tid + 192];
        float Q = sq[tid] + sq[tid + 64] + sq[tid + 128] + sq[tid + 192];
        part[blockIdx.x * 128 + tid] = S;
        part[blockIdx.x * 128 + 64 + tid] = Q;
    }
}

__global__ void stats2_kernel(const float* __restrict__ part, int nb,
                              float invN, float* __restrict__ muArr,
                              float* __restrict__ rstdArr) {
    int c = threadIdx.x;
    float s = 0.f, q = 0.f;
    for (int b = 0; b < nb; b++) {
        s += part[b * 128 + c];
        q += part[b * 128 + 64 + c];
    }
    float m = s * invN;
    float var = q * invN - m * m;
    muArr[c] = m;
    rstdArr[c] = rsqrtf(var + 1e-5f);
}

// ---------------------------------------------------------------------------
// mma.sync tf32x3 GEMM: C = relu(A @ W^T + b)
// BM=128, BN=128, BK=16, 256 threads (8 warps, 2m x 4n), warp tile 64x32.
// smem: 2 stages x [Ah, Al, Bh, Bl] tiles of 128x20 floats = 81920 B.
// Double-buffered: reg-staged gmem loads, split hi/lo on smem store.
// ---------------------------------------------------------------------------
#define TIF 2560  // floats per tile (128*20)
#define SMEMG (2 * 4 * TIF * 4)

template <int KDIM, bool NORM>
__global__ __launch_bounds__(256, 2) void mma_gemm_kernel(
    const float* __restrict__ A0, const float* __restrict__ A1, int lda,
    const float* __restrict__ W0, const float* __restrict__ W1,
    const float* __restrict__ b0, const float* __restrict__ b1,
    float* __restrict__ C0, float* __restrict__ C1,
    const float* __restrict__ mu, const float* __restrict__ rstd) {
    extern __shared__ float sm[];
    const int z = blockIdx.z;
    const float* A = z ? A1 : A0;
    const float* W = z ? W1 : W0;
    const float* bias = z ? b1 : b0;
    float* C = z ? C1 : C0;

    const int tid = threadIdx.x;
    const int wid = tid >> 5, lane = tid & 31;
    const int wm = wid & 1, wn = wid >> 1;
    const size_t row0 = (size_t)blockIdx.y * 128;
    const int col0 = blockIdx.x * 128;

    constexpr int NCH = KDIM / 16;

    // fill indexing: 2 float4 per thread per matrix
    const int r_a[2] = {tid >> 2, (tid >> 2) + 64};
    const int c4f = (tid & 3) << 2;

    float4 rA[2], rB[2];
    auto loadregs = [&](int k0) {
#pragma unroll
        for (int q = 0; q < 2; ++q) {
            rA[q] = *(const float4*)(A + (row0 + r_a[q]) * lda + k0 + c4f);
            rB[q] =
                *(const float4*)(W + (size_t)(col0 + r_a[q]) * KDIM + k0 + c4f);
        }
    };
    auto storeregs = [&](int st, int k0) {
        float* Ah = sm + st * 4 * TIF;
        float* Al = Ah + TIF;
        float* Bh = Ah + 2 * TIF;
        float* Bl = Ah + 3 * TIF;
#pragma unroll
        for (int q = 0; q < 2; ++q) {
            float4 v = rA[q];
            if (NORM) {
                float4 m4 = *(const float4*)(mu + k0 + c4f);
                float4 s4 = *(const float4*)(rstd + k0 + c4f);
                v.x = (v.x - m4.x) * s4.x;
                v.y = (v.y - m4.y) * s4.y;
                v.z = (v.z - m4.z) * s4.z;
                v.w = (v.w - m4.w) * s4.w;
            }
            float4 h, l;
            split4(v, h, l);
            *(float4*)(Ah + r_a[q] * 20 + c4f) = h;
            *(float4*)(Al + r_a[q] * 20 + c4f) = l;
            split4(rB[q], h, l);
            *(float4*)(Bh + r_a[q] * 20 + c4f) = h;
            *(float4*)(Bl + r_a[q] * 20 + c4f) = l;
        }
    };

    float acc[4][4][4];
#pragma unroll
    for (int mt = 0; mt < 4; mt++)
#pragma unroll
        for (int nt = 0; nt < 4; nt++)
#pragma unroll
            for (int e = 0; e < 4; e++) acc[mt][nt][e] = 0.f;

    loadregs(0);
    storeregs(0, 0);

    for (int i = 0; i < NCH; ++i) {
        const int st = i & 1;
        if (i + 1 < NCH) loadregs((i + 1) * 16);
        __syncthreads();
        const float* Ah = sm + st * 4 * TIF;
        const float* Al = Ah + TIF;
        const float* Bh = Ah + 2 * TIF;
        const float* Bl = Ah + 3 * TIF;
#pragma unroll
        for (int kk = 0; kk < 16; kk += 8) {
            uint32_t ah[4][4], al[4][4];
#pragma unroll
            for (int mt = 0; mt < 4; mt++) {
                int r0 = wm * 64 + mt * 16 + (lane >> 2);
                const float* p = Ah + r0 * 20 + kk + (lane & 3);
                ah[mt][0] = __float_as_uint(p[0]);
                ah[mt][1] = __float_as_uint(p[160]);
                ah[mt][2] = __float_as_uint(p[4]);
                ah[mt][3] = __float_as_uint(p[164]);
                const float* q = Al + r0 * 20 + kk + (lane & 3);
                al[mt][0] = __float_as_uint(q[0]);
                al[mt][1] = __float_as_uint(q[160]);
                al[mt][2] = __float_as_uint(q[4]);
                al[mt][3] = __float_as_uint(q[164]);
            }
#pragma unroll
            for (int nt = 0; nt < 4; nt++) {
                int nr = wn * 32 + nt * 8 + (lane >> 2);
                const float* pb = Bh + nr * 20 + kk + (lane & 3);
                uint32_t bh[2] = {__float_as_uint(pb[0]),
                                  __float_as_uint(pb[4])};
                const float* qb = Bl + nr * 20 + kk + (lane & 3);
                uint32_t bl[2] = {__float_as_uint(qb[0]),
                                  __float_as_uint(qb[4])};
#pragma unroll
                for (int mt = 0; mt < 4; mt++) {
                    mma_tf32(acc[mt][nt], ah[mt], bh);
                    mma_tf32(acc[mt][nt], ah[mt], bl);
                    mma_tf32(acc[mt][nt], al[mt], bh);
                }
            }
        }
        if (i + 1 < NCH) storeregs(st ^ 1, (i + 1) * 16);
    }

    // epilogue: bias + relu, direct to gmem
#pragma unroll
    for (int mt = 0; mt < 4; mt++) {
        size_t r0 = row0 + wm * 64 + mt * 16 + (lane >> 2);
#pragma unroll
        for (int nt = 0; nt < 4; nt++) {
            int cc = col0 + wn * 32 + nt * 8 + ((lane & 3) << 1);
            float bv0 = __ldg(bias + cc), bv1 = __ldg(bias + cc + 1);
            float2 v;
            v.x = fmaxf(acc[mt][nt][0] + bv0, 0.f);
            v.y = fmaxf(acc[mt][nt][1] + bv1, 0.f);
            *(float2*)(C + r0 * HH + cc) = v;
            v.x = fmaxf(acc[mt][nt][2] + bv0, 0.f);
            v.y = fmaxf(acc[mt][nt][3] + bv1, 0.f);
            *(float2*)(C + (r0 + 8) * HH + cc) = v;
        }
    }
}

// ---------------------------------------------------------------------------
// mma.sync GEMM3 + coupling, fully fused.
// BM=128, N=64 (s cols 0-31 from (H1s,W2s), t cols 32-63 from (H1t,W2t)).
// 8 warps: wm = wid&3 (4 m-tiles of 32), wn = wid>>2 (0=s, 1=t).
// Epilogue: s|t exchanged through smem, per-row coupling as before.
// smem: 2 stages x [Ash,Asl,Ath,Atl (2560 ea), Bsh,Bsl,Bth,Btl (640 ea)]
//     = 25600 floats = 102400 B.
// ---------------------------------------------------------------------------
#define STG3 12800
#define SMEM3 (2 * STG3 * 4)

__global__ __launch_bounds__(256, 1) void mma_gemm3_kernel(
    const float* __restrict__ H1s, const float* __restrict__ H1t,
    const float* __restrict__ W2s, const float* __restrict__ W2t,
    const float* __restrict__ b2s, const float* __restrict__ b2t,
    const float* __restrict__ X, float* __restrict__ Xn,
    const float* __restrict__ mu, const float* __restrict__ rstd,
    float* __restrict__ det, int x1off, int first) {
    extern __shared__ float sm[];
    const int tid = threadIdx.x;
    const int wid = tid >> 5, lane = tid & 31;
    const int wm = wid & 3, wn = wid >> 2;
    const size_t row0 = (size_t)blockIdx.x * 128;

    const int r_a[2] = {tid >> 2, (tid >> 2) + 64};
    const int c4f = (tid & 3) << 2;
    const int rb = (tid & 127) >> 2;       // 0..31
    const int cb4 = ((tid & 127) & 3) << 2;

    float4 rAs[2], rAt[2], rB;
    auto loadregs = [&](int k0) {
#pragma unroll
        for (int q = 0; q < 2; ++q) {
            rAs[q] = *(const float4*)(H1s + (row0 + r_a[q]) * HH + k0 + c4f);
            rAt[q] = *(const float4*)(H1t + (row0 + r_a[q]) * HH + k0 + c4f);
        }
        const float* Wp = (tid < 128) ? W2s : W2t;
        rB = *(const float4*)(Wp + (size_t)rb * HH + k0 + cb4);
    };
    auto storeregs = [&](int st) {
        float* base = sm + st * STG3;
#pragma unroll
        for (int q = 0; q < 2; ++q) {
            float4 h, l;
            split4(rAs[q], h, l);
            *(float4*)(base + 0 * 2560 + r_a[q] * 20 + c4f) = h;
            *(float4*)(base + 1 * 2560 + r_a[q] * 20 + c4f) = l;
            split4(rAt[q], h, l);
            *(float4*)(base + 2 * 2560 + r_a[q] * 20 + c4f) = h;
            *(float4*)(base + 3 * 2560 + r_a[q] * 20 + c4f) = l;
        }
        float4 h, l;
        split4(rB, h, l);
        float* Bb = base + 4 * 2560 + ((tid < 128) ? 0 : 2 * 640);
        *(float4*)(Bb + rb * 20 + cb4) = h;
        *(float4*)(Bb + 640 + rb * 20 + cb4) = l;
    };

    float acc[2][4][4];
#pragma unroll
    for (int mt = 0; mt < 2; mt++)
#pragma unroll
        for (int nt = 0; nt < 4; nt++)
#pragma unroll
            for (int e = 0; e < 4; e++) acc[mt][nt][e] = 0.f;

    loadregs(0);
    storeregs(0);

    for (int i = 0; i < 32; ++i) {
        const int st = i & 1;
        if (i + 1 < 32) loadregs((i + 1) * 16);
        __syncthreads();
        const float* AH = sm + st * STG3 + (wn ? 2 * 2560 : 0);
        const float* AL = AH + 2560;
        const float* BH = sm + st * STG3 + 4 * 2560 + (wn ? 2 * 640 : 0);
        const float* BL = BH + 640;
#pragma unroll
        for (int kk = 0; kk < 16; kk += 8) {
            uint32_t ah[2][4], al[2][4];
#pragma unroll
            for (int mt = 0; mt < 2; mt++) {
                int r0 = wm * 32 + mt * 16 + (lane >> 2);
                const float* p = AH + r0 * 20 + kk + (lane & 3);
                ah[mt][0] = __float_as_uint(p[0]);
                ah[mt][1] = __float_as_uint(p[160]);
                ah[mt][2] = __float_as_uint(p[4]);
                ah[mt][3] = __float_as_uint(p[164]);
                const float* q = AL + r0 * 20 + kk + (lane & 3);
                al[mt][0] = __float_as_uint(q[0]);
                al[mt][1] = __float_as_uint(q[160]);
                al[mt][2] = __float_as_uint(q[4]);
                al[mt][3] = __float_as_uint(q[164]);
            }
#pragma unroll
            for (int nt = 0; nt < 4; nt++) {
                int nr = nt * 8 + (lane >> 2);
                const float* pb = BH + nr * 20 + kk + (lane & 3);
                uint32_t bh[2] = {__float_as_uint(pb[0]),
                                  __float_as_uint(pb[4])};
                const float* qb = BL + nr * 20 + kk + (lane & 3);
                uint32_t bl[2] = {__float_as_uint(qb[0]),
                                  __float_as_uint(qb[4])};
#pragma unroll
                for (int mt = 0; mt < 2; mt++) {
                    mma_tf32(acc[mt][nt], ah[mt], bh);
                    mma_tf32(acc[mt][nt], ah[mt], bl);
                    mma_tf32(acc[mt][nt], al[mt], bh);
                }
            }
        }
        if (i + 1 < 32) storeregs(st ^ 1);
    }

    // exchange s|t (+bias) via smem (stage-0 region; last compute used stage 1)
    float* Cs = sm;  // [128][66]
    {
        const float* bp = wn ? b2t : b2s;
#pragma unroll
        for (int mt = 0; mt < 2; mt++) {
            int r = wm * 32 + mt * 16 + (lane >> 2);
#pragma unroll
            for (int nt = 0; nt < 4; nt++) {
                int ccl = nt * 8 + ((lane & 3) << 1);
                int cg = wn * 32 + ccl;
                float bv0 = __ldg(bp + ccl), bv1 = __ldg(bp + ccl + 1);
                Cs[r * 66 + cg] = acc[mt][nt][0] + bv0;
                Cs[r * 66 + cg + 1] = acc[mt][nt][1] + bv1;
                Cs[(r + 8) * 66 + cg] = acc[mt][nt][2] + bv0;
                Cs[(r + 8) * 66 + cg + 1] = acc[mt][nt][3] + bv1;
            }
        }
    }
    __syncthreads();

    if (tid < 128) {
        int r = tid;
        size_t grow = row0 + r;
        const float* xr = X + grow * DD;
        float* xo = Xn + grow * DD;
        int x2off = dH - x1off;
        float ssum = 0.f;
#pragma unroll 8
        for (int j = 0; j < dH; j++) {
            float s = Cs[r * 66 + j];
            float t = Cs[r * 66 + 32 + j];
            float x1 = xr[x1off + j];
            float x2 = xr[x2off + j];
            xo[j] = (x1 - mu[x1off + j]) * rstd[x1off + j];
            float x2n = (x2 - mu[x2off + j]) * rstd[x2off + j];
            xo[dH + j] = x2n * expf(s) + t;
            ssum += s;
        }
        det[grow] = first ? ssum : (det[grow] + ssum);
    }
}

// ---------------------------------------------------------------------------
// GMM log-likelihood + output assembly (unchanged, proven)
// ---------------------------------------------------------------------------
__global__ __launch_bounds__(256) void gmm_kernel(
    const float* __restrict__ X, const float* __restrict__ means,
    const float* __restrict__ det, float* __restrict__ out, int N, int full) {
    __shared__ float smm[KK * DD];
    int tid = threadIdx.x;
    for (int i = tid; i < KK * DD; i += 256) smm[i] = means[i];
    __syncthreads();

    size_t i = (size_t)blockIdx.x * 256 + tid;
    float4 y4[16];
    const float4* xr = (const float4*)(X + i * DD);
#pragma unroll
    for (int q = 0; q < 16; q++) y4[q] = xr[q];
    float4* yo = (float4*)(out + i * DD);
#pragma unroll
    for (int q = 0; q < 16; q++) yo[q] = y4[q];

    if (!full) return;

    const float CD = (float)(64.0 * 1.8378770664093453);
    float lp[KK];
    float mx = -1e30f;
#pragma unroll
    for (int k = 0; k < KK; k++) {
        const float* mrow = smm + k * DD;
        float accv = 0.f;
#pragma unroll
        for (int q = 0; q < 16; q++) {
            float4 m4 = *(const float4*)(mrow + q * 4);
            float dx = y4[q].x - m4.x;
            accv += dx * dx;
            dx = y4[q].y - m4.y;
            accv += dx * dx;
            dx = y4[q].z - m4.z;
            accv += dx * dx;
            dx = y4[q].w - m4.w;
            accv += dx * dx;
        }
        float v = -0.5f * (accv + CD);
        lp[k] = v;
        mx = fmaxf(mx, v);
    }
    float se = 0.f;
#pragma unroll
    for (int k = 0; k < KK; k++) se += expf(lp[k] - mx);
    float ll = mx + logf(se) - logf((float)KK);

    size_t oll = (size_t)N * DD + 1;
    out[oll + i] = ll;
    out[oll + N + i] = det[i];
}

__global__ void final_reduce_kernel(float* __restrict__ out, int N) {
    int tid = threadIdx.x;
    size_t oll = (size_t)N * DD + 1;
    size_t odet = oll + N;
    float sll = 0.f, sdet = 0.f;
    for (int i = tid; i < N; i += 1024) {
        sll += out[oll + i];
        sdet += out[odet + i];
    }
    __shared__ float a[1024], b[1024];
    a[tid] = sll;
    b[tid] = sdet;
    __syncthreads();
    for (int s = 512; s > 0; s >>= 1) {
        if (tid < s) {
            a[tid] += a[tid + s];
            b[tid] += b[tid + s];
        }
        __syncthreads();
    }
    if (tid == 0) {
        float llm = a[0] / (float)N;
        float dm = b[0] / (float)N;
        out[(size_t)N * DD] = -(dm + llm);
        out[odet + N] = llm;
        out[odet + N + 1] = dm;
    }
}

// ---------------------------------------------------------------------------
// Host launcher
// ---------------------------------------------------------------------------
static float* symaddr(const void* s) {
    void* p = nullptr;
    cudaGetSymbolAddress(&p, s);
    return (float*)p;
}

extern "C" void kernel_launch(void* const* d_in, const int* in_sizes, int n_in,
                              void* d_out, int out_size) {
    const float* x = (const float*)d_in[0];
    const float* sW0 = (const float*)d_in[1];
    const float* sb0 = (const float*)d_in[2];
    const float* sW1 = (const float*)d_in[3];
    const float* sb1 = (const float*)d_in[4];
    const float* sW2 = (const float*)d_in[5];
    const float* sb2 = (const float*)d_in[6];
    const float* tW0 = (const float*)d_in[7];
    const float* tb0 = (const float*)d_in[8];
    const float* tW1 = (const float*)d_in[9];
    const float* tb1 = (const float*)d_in[10];
    const float* tW2 = (const float*)d_in[11];
    const float* tb2 = (const float*)d_in[12];
    const float* means = (const float*)d_in[13];
    float* out = (float*)d_out;

    const int N = in_sizes[0] / (DD + 1);
    const int full = (out_size >= (long long)N * DD + 2 * N + 3) ? 1 : 0;

    cudaFuncSetAttribute(mma_gemm_kernel<dH, true>,
                         cudaFuncAttributeMaxDynamicSharedMemorySize, SMEMG);
    cudaFuncSetAttribute(mma_gemm_kernel<HH, false>,
                         cudaFuncAttributeMaxDynamicSharedMemorySize, SMEMG);
    cudaFuncSetAttribute(mma_gemm3_kernel,
                         cudaFuncAttributeMaxDynamicSharedMemorySize, SMEM3);

    float* X = symaddr(g_X);
    float* H0 = symaddr(g_H0);
    float* H1 = symaddr(g_H1);
    float* det = symaddr(g_det);
    float* part = symaddr(g_part);
    float* mu = symaddr(g_mu);
    float* rstd = symaddr(g_rstd);

    const size_t XS = (size_t)N * DD;
    const size_t HS = (size_t)N * HH;

    copy_in_kernel<<<(N * DD + 255) / 256, 256>>>(x, X, N);

    int cur = 0;
    for (int l = 0; l < LL; l++) {
        float* Xc = X + (size_t)cur * XS;
        float* Xnext = X + (size_t)(cur ^ 1) * XS;
        stats1_kernel<<<256, 256>>>(Xc, part, N / 256);
        stats2_kernel<<<1, 64>>>(part, 256, 1.0f / (float)N, mu, rstd);

        const int x1off = (l & 1) ? dH : 0;

        // GEMM1: (N x 32) -> (N x 512), BN-normalized A, relu
        mma_gemm_kernel<dH, true>
            <<<dim3(HH / 128, N / 128, 2), 256, SMEMG>>>(
                Xc + x1off, Xc + x1off, DD,
                sW0 + (size_t)l * HH * dH, tW0 + (size_t)l * HH * dH,
                sb0 + (size_t)l * HH, tb0 + (size_t)l * HH,
                H0, H0 + HS, mu + x1off, rstd + x1off);

        // GEMM2: (N x 512) -> (N x 512), relu
        mma_gemm_kernel<HH, false>
            <<<dim3(HH / 128, N / 128, 2), 256, SMEMG>>>(
                H0, H0 + HS, HH,
                sW1 + (size_t)l * HH * HH, tW1 + (size_t)l * HH * HH,
                sb1 + (size_t)l * HH, tb1 + (size_t)l * HH,
                H1, H1 + HS, nullptr, nullptr);

        // GEMM3 (s||t) + full coupling epilogue
        mma_gemm3_kernel<<<N / 128, 256, SMEM3>>>(
            H1, H1 + HS,
            sW2 + (size_t)l * dH * HH, tW2 + (size_t)l * dH * HH,
            sb2 + (size_t)l * dH, tb2 + (size_t)l * dH,
            Xc, Xnext, mu, rstd, det, x1off, (l == 0) ? 1 : 0);

        cur ^= 1;
    }

    gmm_kernel<<<N / 256, 256>>>(X + (size_t)cur * XS, means, det, out, N,
                                 full);
    if (full) final_reduce_kernel<<<1, 1024>>>(out, N);
}

// round 8
// speedup vs baseline: 1.3629x; 1.0410x over previous
#include <cuda_runtime.h>
#include <math.h>
#include <stdint.h>

// Problem constants (fixed by the reference)
#define NROWS_MAX 65536
#define DD 64
#define dH 32
#define HH 512
#define LL 8
#define KK 10

// ---------------------------------------------------------------------------
// Static device scratch (allocation-free rule: __device__ globals)
// ---------------------------------------------------------------------------
__device__ __align__(16) float g_X[2][NROWS_MAX * DD];   // ping-pong flow state
__device__ __align__(16) float g_XA[NROWS_MAX * dH];     // normalized x1
__device__ __align__(16) float g_H0[2][NROWS_MAX * HH];  // hidden 0 (s,t)
__device__ __align__(16) float g_H1[2][NROWS_MAX * HH];  // hidden 1 (s,t)
__device__ float g_det[NROWS_MAX];
__device__ float g_part[256 * 128];
__device__ __align__(16) float g_mu[DD];
__device__ __align__(16) float g_rstd[DD];

// ---------------------------------------------------------------------------
// portable PTX helpers (no "a"-features: cp.async + mma.sync are sm_80 base)
// ---------------------------------------------------------------------------
__device__ __forceinline__ uint32_t smem_u32(const void* p) {
    uint32_t a;
    asm("{ .reg .u64 t; cvta.to.shared.u64 t, %1; cvt.u32.u64 %0, t; }"
        : "=r"(a) : "l"(p));
    return a;
}
__device__ __forceinline__ float tf32r(float x) {
    float r;
    asm("cvt.rna.tf32.f32 %0, %1;" : "=f"(r) : "f"(x));
    return r;
}
__device__ __forceinline__ void mma_tf32(float* c, const uint32_t* a,
                                         const uint32_t* b) {
    asm volatile(
        "mma.sync.aligned.m16n8k8.row.col.f32.tf32.tf32.f32 "
        "{%0,%1,%2,%3}, {%4,%5,%6,%7}, {%8,%9}, {%0,%1,%2,%3};"
        : "+f"(c[0]), "+f"(c[1]), "+f"(c[2]), "+f"(c[3])
        : "r"(a[0]), "r"(a[1]), "r"(a[2]), "r"(a[3]), "r"(b[0]), "r"(b[1]));
}
#define CP8(dst, src)                                              \
    asm volatile("cp.async.ca.shared.global [%0], [%1], 8;" ::"r"( \
                     (uint32_t)(dst)),                             \
                 "l"(src))
#define CP_COMMIT() asm volatile("cp.async.commit_group;" ::: "memory")
#define CP_WAIT1() asm volatile("cp.async.wait_group 1;" ::: "memory")
#define CP_WAIT0() asm volatile("cp.async.wait_group 0;" ::: "memory")

// split scalar -> tf32 hi/lo
__device__ __forceinline__ void spl(float v, uint32_t& h, uint32_t& l) {
    float hh = tf32r(v);
    h = __float_as_uint(hh);
    l = __float_as_uint(tf32r(v - hh));
}

// ---------------------------------------------------------------------------
// small kernels
// ---------------------------------------------------------------------------
__global__ void copy_in_kernel(const float* __restrict__ x,
                               float* __restrict__ X, int N) {
    int idx = blockIdx.x * 256 + threadIdx.x;
    if (idx < N * DD) {
        int i = idx >> 6;
        int j = idx & 63;
        X[idx] = x[(size_t)i * (DD + 1) + j];
    }
}

// normalized x1 slice -> XA (N x 32, dense)
__global__ void norm_kernel(const float* __restrict__ X,
                            float* __restrict__ XA,
                            const float* __restrict__ mu,
                            const float* __restrict__ rstd, int x1off, int N) {
    int idx = blockIdx.x * 256 + threadIdx.x;  // over N*8 float4
    if (idx < N * 8) {
        int i = idx >> 3;
        int j4 = (idx & 7) << 2;
        float4 v = *(const float4*)(X + (size_t)i * DD + x1off + j4);
        float4 m = *(const float4*)(mu + x1off + j4);
        float4 s = *(const float4*)(rstd + x1off + j4);
        v.x = (v.x - m.x) * s.x;
        v.y = (v.y - m.y) * s.y;
        v.z = (v.z - m.z) * s.z;
        v.w = (v.w - m.w) * s.w;
        *(float4*)(XA + (size_t)i * dH + j4) = v;
    }
}

__global__ __launch_bounds__(256) void stats1_kernel(
    const float* __restrict__ X, float* __restrict__ part, int rowsPerBlock) {
    int tid = threadIdx.x;
    int c = tid & 63;
    int rg = tid >> 6;
    size_t base = (size_t)blockIdx.x * rowsPerBlock;
    float s = 0.f, q = 0.f;
    for (int r = rg; r < rowsPerBlock; r += 4) {
        float v = X[(base + r) * DD + c];
        s += v;
        q += v * v;
    }
    __shared__ float ss[256], sq[256];
    ss[tid] = s;
    sq[tid] = q;
    __syncthreads();
    if (tid < 64) {
        float S = ss[tid] + ss[tid + 64] + ss[tid + 128] + ss[tid + 192];
        float Q = sq[tid] + sq[tid + 64] + sq[tid + 128] + sq[tid + 192];
        part[blockIdx.x * 128 + tid] = S;
        part[blockIdx.x * 128 + 64 + tid] = Q;
    }
}

__global__ void stats2_kernel(const float* __restrict__ part, int nb,
                              float invN, float* __restrict__ muArr,
                              float* __restrict__ rstdArr) {
    int c = threadIdx.x;
    float s = 0.f, q = 0.f;
    for (int b = 0; b < nb; b++) {
        s += part[b * 128 + c];
        q += part[b * 128 + 64 + c];
    }
    float m = s * invN;
    float var = q * invN - m * m;
    muArr[c] = m;
    rstdArr[c] = rsqrtf(var + 1e-5f);
}

// ---------------------------------------------------------------------------
// mma.sync tf32x3 GEMM v2: C = relu(A @ W^T + b)
// BM=128, BN=128, BK=16, 256 threads (8 warps 2m x 4n), warp tile 64x32.
// Raw fp32 smem (pitch 20), split->tf32 after LDS. 3-stage cp.async.
// Staged coalesced epilogue (STG.128).
// smem: 3 stages x (A 2560 + B 2560 floats) = 61440 B
// ---------------------------------------------------------------------------
#define STGF 5120
#define SMEMG (3 * STGF * 4)

template <int KDIM>
__global__ __launch_bounds__(256, 2) void mma_gemm_kernel(
    const float* __restrict__ A0, const float* __restrict__ A1, int lda,
    const float* __restrict__ W0, const float* __restrict__ W1,
    const float* __restrict__ b0, const float* __restrict__ b1,
    float* __restrict__ C0, float* __restrict__ C1) {
    extern __shared__ float sm[];
    const int z = blockIdx.z;
    const float* A = z ? A1 : A0;
    const float* W = z ? W1 : W0;
    const float* bias = z ? b1 : b0;
    float* C = z ? C1 : C0;

    const int tid = threadIdx.x;
    const int wid = tid >> 5, lane = tid & 31;
    const int wm = wid & 1, wn = wid >> 1;
    const size_t row0 = (size_t)blockIdx.y * 128;
    const int col0 = blockIdx.x * 128;
    const uint32_t smb = smem_u32(sm);

    constexpr int NCH = KDIM / 16;
    const int r0f = tid >> 2;
    const int c4f = (tid & 3) << 2;

    auto issue = [&](int i) {
        const int st = i % 3;
        const int k0 = i * 16;
        const uint32_t ab = smb + st * STGF * 4;
        const uint32_t bb = ab + 2560 * 4;
#pragma unroll
        for (int q = 0; q < 2; ++q) {
            int r = r0f + q * 64;
            const float* g = A + (row0 + r) * lda + k0 + c4f;
            uint32_t d = ab + (r * 20 + c4f) * 4;
            CP8(d, g);
            CP8(d + 8, g + 2);
            g = W + (size_t)(col0 + r) * KDIM + k0 + c4f;
            d = bb + (r * 20 + c4f) * 4;
            CP8(d, g);
            CP8(d + 8, g + 2);
        }
        CP_COMMIT();
    };

    float acc[4][4][4];
#pragma unroll
    for (int mt = 0; mt < 4; mt++)
#pragma unroll
        for (int nt = 0; nt < 4; nt++)
#pragma unroll
            for (int e = 0; e < 4; e++) acc[mt][nt][e] = 0.f;

    issue(0);
    if (NCH > 1) issue(1);

    for (int i = 0; i < NCH; ++i) {
        if (i < NCH - 1) CP_WAIT1();
        else CP_WAIT0();
        __syncthreads();
        if (i + 2 < NCH) issue(i + 2);
        const float* Ab = sm + (i % 3) * STGF;
        const float* Bb = Ab + 2560;
#pragma unroll
        for (int kk = 0; kk < 16; kk += 8) {
            uint32_t ah[4][4], al[4][4];
#pragma unroll
            for (int mt = 0; mt < 4; mt++) {
                const float* p =
                    Ab + (wm * 64 + mt * 16 + (lane >> 2)) * 20 + kk +
                    (lane & 3);
                spl(p[0], ah[mt][0], al[mt][0]);
                spl(p[160], ah[mt][1], al[mt][1]);
                spl(p[4], ah[mt][2], al[mt][2]);
                spl(p[164], ah[mt][3], al[mt][3]);
            }
#pragma unroll
            for (int nt = 0; nt < 4; nt++) {
                const float* pb =
                    Bb + (wn * 32 + nt * 8 + (lane >> 2)) * 20 + kk +
                    (lane & 3);
                uint32_t bh[2], bl[2];
                spl(pb[0], bh[0], bl[0]);
                spl(pb[4], bh[1], bl[1]);
#pragma unroll
                for (int mt = 0; mt < 4; mt++) {
                    mma_tf32(acc[mt][nt], ah[mt], bh);
                    mma_tf32(acc[mt][nt], ah[mt], bl);
                    mma_tf32(acc[mt][nt], al[mt], bh);
                }
            }
        }
    }
    __syncthreads();

    // staged coalesced epilogue: frag -> warp scratch -> STG.128
    float bv[4][2];
#pragma unroll
    for (int nt = 0; nt < 4; nt++) {
        int c = col0 + wn * 32 + nt * 8 + ((lane & 3) << 1);
        bv[nt][0] = __ldg(bias + c);
        bv[nt][1] = __ldg(bias + c + 1);
    }
    float* wsc = sm + wid * 576;  // 16 x 36
#pragma unroll
    for (int mt = 0; mt < 4; mt++) {
        int r = lane >> 2, c = (lane & 3) << 1;
#pragma unroll
        for (int nt = 0; nt < 4; nt++) {
            float2 v;
            v.x = fmaxf(acc[mt][nt][0] + bv[nt][0], 0.f);
            v.y = fmaxf(acc[mt][nt][1] + bv[nt][1], 0.f);
            *(float2*)(wsc + r * 36 + nt * 8 + c) = v;
            v.x = fmaxf(acc[mt][nt][2] + bv[nt][0], 0.f);
            v.y = fmaxf(acc[mt][nt][3] + bv[nt][1], 0.f);
            *(float2*)(wsc + (r + 8) * 36 + nt * 8 + c) = v;
        }
        __syncwarp();
#pragma unroll
        for (int rr = 0; rr < 4; rr++) {
            int row = rr * 4 + (lane >> 3);
            int col4 = (lane & 7) << 2;
            float4 v = *(const float4*)(wsc + row * 36 + col4);
            *(float4*)(C + (row0 + wm * 64 + mt * 16 + row) * HH + col0 +
                       wn * 32 + col4) = v;
        }
        __syncwarp();
    }
}

// ---------------------------------------------------------------------------
// mma.sync GEMM3 v2 + fused coupling.
// BM=128, N=64 (s: cols 0-31 from (H1s,W2s); t: from (H1t,W2t)).
// 8 warps: wm=wid&3 (m-tiles of 32), wn=wid>>2 (0=s,1=t). K=512.
// Raw smem + split after LDS + 3-stage cp.async.
// smem: 3 stages x (As 2560 + At 2560 + Bs 640 + Bt 640) = 76800 B
// ---------------------------------------------------------------------------
#define STG3F 6400
#define SMEM3 (3 * STG3F * 4)

__global__ __launch_bounds__(256, 1) void mma_gemm3_kernel(
    const float* __restrict__ H1s, const float* __restrict__ H1t,
    const float* __restrict__ W2s, const float* __restrict__ W2t,
    const float* __restrict__ b2s, const float* __restrict__ b2t,
    const float* __restrict__ X, float* __restrict__ Xn,
    const float* __restrict__ mu, const float* __restrict__ rstd,
    float* __restrict__ det, int x1off, int first) {
    extern __shared__ float sm[];
    const int tid = threadIdx.x;
    const int wid = tid >> 5, lane = tid & 31;
    const int wm = wid & 3, wn = wid >> 2;
    const size_t row0 = (size_t)blockIdx.x * 128;
    const uint32_t smb = smem_u32(sm);

    const int r0f = tid >> 2;
    const int c4f = (tid & 3) << 2;
    const int rb = (tid & 127) >> 2;
    const int cb4 = ((tid & 127) & 3) << 2;
    const float* Wp = (tid < 128) ? W2s : W2t;
    const uint32_t boff = (tid < 128) ? 5120u : 5760u;

    auto issue = [&](int i) {
        const int st = i % 3;
        const int k0 = i * 16;
        const uint32_t base = smb + st * STG3F * 4;
#pragma unroll
        for (int q = 0; q < 2; ++q) {
            int r = r0f + q * 64;
            const float* g = H1s + (row0 + r) * HH + k0 + c4f;
            uint32_t d = base + (r * 20 + c4f) * 4;
            CP8(d, g);
            CP8(d + 8, g + 2);
            g = H1t + (row0 + r) * HH + k0 + c4f;
            d = base + (2560 + r * 20 + c4f) * 4;
            CP8(d, g);
            CP8(d + 8, g + 2);
        }
        {
            const float* g = Wp + (size_t)rb * HH + k0 + cb4;
            uint32_t d = base + (boff + rb * 20 + cb4) * 4;
            CP8(d, g);
            CP8(d + 8, g + 2);
        }
        CP_COMMIT();
    };

    float acc[2][4][4];
#pragma unroll
    for (int mt = 0; mt < 2; mt++)
#pragma unroll
        for (int nt = 0; nt < 4; nt++)
#pragma unroll
            for (int e = 0; e < 4; e++) acc[mt][nt][e] = 0.f;

    issue(0);
    issue(1);

    for (int i = 0; i < 32; ++i) {
        if (i < 31) CP_WAIT1();
        else CP_WAIT0();
        __syncthreads();
        if (i + 2 < 32) issue(i + 2);
        const float* base = sm + (i % 3) * STG3F;
        const float* AH = base + (wn ? 2560 : 0);
        const float* BH = base + 5120 + (wn ? 640 : 0);
#pragma unroll
        for (int kk = 0; kk < 16; kk += 8) {
            uint32_t ah[2][4], al[2][4];
#pragma unroll
            for (int mt = 0; mt < 2; mt++) {
                const float* p =
                    AH + (wm * 32 + mt * 16 + (lane >> 2)) * 20 + kk +
                    (lane & 3);
                spl(p[0], ah[mt][0], al[mt][0]);
                spl(p[160], ah[mt][1], al[mt][1]);
                spl(p[4], ah[mt][2], al[mt][2]);
                spl(p[164], ah[mt][3], al[mt][3]);
            }
#pragma unroll
            for (int nt = 0; nt < 4; nt++) {
                const float* pb =
                    BH + (nt * 8 + (lane >> 2)) * 20 + kk + (lane & 3);
                uint32_t bh[2], bl[2];
                spl(pb[0], bh[0], bl[0]);
                spl(pb[4], bh[1], bl[1]);
#pragma unroll
                for (int mt = 0; mt < 2; mt++) {
                    mma_tf32(acc[mt][nt], ah[mt], bh);
                    mma_tf32(acc[mt][nt], ah[mt], bl);
                    mma_tf32(acc[mt][nt], al[mt], bh);
                }
            }
        }
    }
    __syncthreads();

    // exchange s|t (+bias) via smem then per-row coupling
    float* Cs = sm;  // [128][66]
    {
        const float* bp = wn ? b2t : b2s;
#pragma unroll
        for (int mt = 0; mt < 2; mt++) {
            int r = wm * 32 + mt * 16 + (lane >> 2);
#pragma unroll
            for (int nt = 0; nt < 4; nt++) {
                int ccl = nt * 8 + ((lane & 3) << 1);
                int cg = wn * 32 + ccl;
                float bv0 = __ldg(bp + ccl), bv1 = __ldg(bp + ccl + 1);
                Cs[r * 66 + cg] = acc[mt][nt][0] + bv0;
                Cs[r * 66 + cg + 1] = acc[mt][nt][1] + bv1;
                Cs[(r + 8) * 66 + cg] = acc[mt][nt][2] + bv0;
                Cs[(r + 8) * 66 + cg + 1] = acc[mt][nt][3] + bv1;
            }
        }
    }
    __syncthreads();

    if (tid < 128) {
        int r = tid;
        size_t grow = row0 + r;
        const float* xr = X + grow * DD;
        float* xo = Xn + grow * DD;
        int x2off = dH - x1off;
        float ssum = 0.f;
#pragma unroll 8
        for (int j = 0; j < dH; j++) {
            float s = Cs[r * 66 + j];
            float t = Cs[r * 66 + 32 + j];
            float x1 = xr[x1off + j];
            float x2 = xr[x2off + j];
            xo[j] = (x1 - mu[x1off + j]) * rstd[x1off + j];
            float x2n = (x2 - mu[x2off + j]) * rstd[x2off + j];
            xo[dH + j] = x2n * expf(s) + t;
            ssum += s;
        }
        det[grow] = first ? ssum : (det[grow] + ssum);
    }
}

// ---------------------------------------------------------------------------
// GMM log-likelihood + output assembly (unchanged, proven)
// ---------------------------------------------------------------------------
__global__ __launch_bounds__(256) void gmm_kernel(
    const float* __restrict__ X, const float* __restrict__ means,
    const float* __restrict__ det, float* __restrict__ out, int N, int full) {
    __shared__ float smm[KK * DD];
    int tid = threadIdx.x;
    for (int i = tid; i < KK * DD; i += 256) smm[i] = means[i];
    __syncthreads();

    size_t i = (size_t)blockIdx.x * 256 + tid;
    float4 y4[16];
    const float4* xr = (const float4*)(X + i * DD);
#pragma unroll
    for (int q = 0; q < 16; q++) y4[q] = xr[q];
    float4* yo = (float4*)(out + i * DD);
#pragma unroll
    for (int q = 0; q < 16; q++) yo[q] = y4[q];

    if (!full) return;

    const float CD = (float)(64.0 * 1.8378770664093453);
    float lp[KK];
    float mx = -1e30f;
#pragma unroll
    for (int k = 0; k < KK; k++) {
        const float* mrow = smm + k * DD;
        float accv = 0.f;
#pragma unroll
        for (int q = 0; q < 16; q++) {
            float4 m4 = *(const float4*)(mrow + q * 4);
            float dx = y4[q].x - m4.x;
            accv += dx * dx;
            dx = y4[q].y - m4.y;
            accv += dx * dx;
            dx = y4[q].z - m4.z;
            accv += dx * dx;
            dx = y4[q].w - m4.w;
            accv += dx * dx;
        }
        float v = -0.5f * (accv + CD);
        lp[k] = v;
        mx = fmaxf(mx, v);
    }
    float se = 0.f;
#pragma unroll
    for (int k = 0; k < KK; k++) se += expf(lp[k] - mx);
    float ll = mx + logf(se) - logf((float)KK);

    size_t oll = (size_t)N * DD + 1;
    out[oll + i] = ll;
    out[oll + N + i] = det[i];
}

__global__ void final_reduce_kernel(float* __restrict__ out, int N) {
    int tid = threadIdx.x;
    size_t oll = (size_t)N * DD + 1;
    size_t odet = oll + N;
    float sll = 0.f, sdet = 0.f;
    for (int i = tid; i < N; i += 1024) {
        sll += out[oll + i];
        sdet += out[odet + i];
    }
    __shared__ float a[1024], b[1024];
    a[tid] = sll;
    b[tid] = sdet;
    __syncthreads();
    for (int s = 512; s > 0; s >>= 1) {
        if (tid < s) {
            a[tid] += a[tid + s];
            b[tid] += b[tid + s];
        }
        __syncthreads();
    }
    if (tid == 0) {
        float llm = a[0] / (float)N;
        float dm = b[0] / (float)N;
        out[(size_t)N * DD] = -(dm + llm);
        out[odet + N] = llm;
        out[odet + N + 1] = dm;
    }
}

// ---------------------------------------------------------------------------
// Host launcher
// ---------------------------------------------------------------------------
static float* symaddr(const void* s) {
    void* p = nullptr;
    cudaGetSymbolAddress(&p, s);
    return (float*)p;
}

extern "C" void kernel_launch(void* const* d_in, const int* in_sizes, int n_in,
                              void* d_out, int out_size) {
    const float* x = (const float*)d_in[0];
    const float* sW0 = (const float*)d_in[1];
    const float* sb0 = (const float*)d_in[2];
    const float* sW1 = (const float*)d_in[3];
    const float* sb1 = (const float*)d_in[4];
    const float* sW2 = (const float*)d_in[5];
    const float* sb2 = (const float*)d_in[6];
    const float* tW0 = (const float*)d_in[7];
    const float* tb0 = (const float*)d_in[8];
    const float* tW1 = (const float*)d_in[9];
    const float* tb1 = (const float*)d_in[10];
    const float* tW2 = (const float*)d_in[11];
    const float* tb2 = (const float*)d_in[12];
    const float* means = (const float*)d_in[13];
    float* out = (float*)d_out;

    const int N = in_sizes[0] / (DD + 1);
    const int full = (out_size >= (long long)N * DD + 2 * N + 3) ? 1 : 0;

    cudaFuncSetAttribute(mma_gemm_kernel<dH>,
                         cudaFuncAttributeMaxDynamicSharedMemorySize, SMEMG);
    cudaFuncSetAttribute(mma_gemm_kernel<HH>,
                         cudaFuncAttributeMaxDynamicSharedMemorySize, SMEMG);
    cudaFuncSetAttribute(mma_gemm3_kernel,
                         cudaFuncAttributeMaxDynamicSharedMemorySize, SMEM3);

    float* X = symaddr(g_X);
    float* XA = symaddr(g_XA);
    float* H0 = symaddr(g_H0);
    float* H1 = symaddr(g_H1);
    float* det = symaddr(g_det);
    float* part = symaddr(g_part);
    float* mu = symaddr(g_mu);
    float* rstd = symaddr(g_rstd);

    const size_t XS = (size_t)N * DD;
    const size_t HS = (size_t)N * HH;

    copy_in_kernel<<<(N * DD + 255) / 256, 256>>>(x, X, N);

    int cur = 0;
    for (int l = 0; l < LL; l++) {
        float* Xc = X + (size_t)cur * XS;
        float* Xnext = X + (size_t)(cur ^ 1) * XS;
        stats1_kernel<<<256, 256>>>(Xc, part, N / 256);
        stats2_kernel<<<1, 64>>>(part, 256, 1.0f / (float)N, mu, rstd);

        const int x1off = (l & 1) ? dH : 0;

        // pre-normalized x1 (dense N x 32)
        norm_kernel<<<(N * 8 + 255) / 256, 256>>>(Xc, XA, mu, rstd, x1off, N);

        // GEMM1: (N x 32) -> (N x 512), relu
        mma_gemm_kernel<dH><<<dim3(HH / 128, N / 128, 2), 256, SMEMG>>>(
            XA, XA, dH, sW0 + (size_t)l * HH * dH, tW0 + (size_t)l * HH * dH,
            sb0 + (size_t)l * HH, tb0 + (size_t)l * HH, H0, H0 + HS);

        // GEMM2: (N x 512) -> (N x 512), relu
        mma_gemm_kernel<HH><<<dim3(HH / 128, N / 128, 2), 256, SMEMG>>>(
            H0, H0 + HS, HH, sW1 + (size_t)l * HH * HH,
            tW1 + (size_t)l * HH * HH, sb1 + (size_t)l * HH,
            tb1 + (size_t)l * HH, H1, H1 + HS);

        // GEMM3 (s||t) + full coupling epilogue
        mma_gemm3_kernel<<<N / 128, 256, SMEM3>>>(
            H1, H1 + HS, sW2 + (size_t)l * dH * HH, tW2 + (size_t)l * dH * HH,
            sb2 + (size_t)l * dH, tb2 + (size_t)l * dH, Xc, Xnext, mu, rstd,
            det, x1off, (l == 0) ? 1 : 0);

        cur ^= 1;
    }

    gmm_kernel<<<N / 256, 256>>>(X + (size_t)cur * XS, means, det, out, N,
                                 full);
    if (full) final_reduce_kernel<<<1, 1024>>>(out, N);
}

// round 9
// speedup vs baseline: 1.9880x; 1.4587x over previous
#include <cuda_runtime.h>
#include <math.h>
#include <stdint.h>

#define NROWS_MAX 65536
#define DD 64
#define dH 32
#define HH 512
#define LL 8
#define KK 10

__device__ __align__(16) float g_X[2][NROWS_MAX * DD];
__device__ __align__(16) float g_XA[NROWS_MAX * dH];
__device__ __align__(16) float g_H0[2][NROWS_MAX * HH];
__device__ __align__(16) float g_H1[2][NROWS_MAX * HH];
__device__ float g_det[NROWS_MAX];
__device__ float g_part[256 * 128];
__device__ __align__(16) float g_mu[DD];
__device__ __align__(16) float g_rstd[DD];

// ---------------------------------------------------------------------------
// portable PTX helpers (mma.sync bf16 m16n8k16 is sm_80 base, no "a"-features)
// ---------------------------------------------------------------------------
__device__ __forceinline__ void mma_bf16(float* c, const uint32_t* a,
                                         const uint32_t* b) {
    asm volatile(
        "mma.sync.aligned.m16n8k16.row.col.f32.bf16.bf16.f32 "
        "{%0,%1,%2,%3}, {%4,%5,%6,%7}, {%8,%9}, {%0,%1,%2,%3};"
        : "+f"(c[0]), "+f"(c[1]), "+f"(c[2]), "+f"(c[3])
        : "r"(a[0]), "r"(a[1]), "r"(a[2]), "r"(a[3]), "r"(b[0]), "r"(b[1]));
}
__device__ __forceinline__ uint32_t packbf(float v1, float v0) {
    uint32_t r;
    asm("cvt.rn.bf16x2.f32 %0, %1, %2;" : "=r"(r) : "f"(v1), "f"(v0));
    return r;
}
__device__ __forceinline__ void spl2(float v0, float v1, uint32_t& h,
                                     uint32_t& l) {
    h = packbf(v1, v0);
    float h0 = __uint_as_float(h << 16);
    float h1 = __uint_as_float(h & 0xffff0000u);
    l = packbf(v1 - h1, v0 - h0);
}

// ---------------------------------------------------------------------------
// small kernels
// ---------------------------------------------------------------------------
__global__ void copy_in_kernel(const float* __restrict__ x,
                               float* __restrict__ X, int N) {
    int idx = blockIdx.x * 256 + threadIdx.x;
    if (idx < N * DD) {
        int i = idx >> 6;
        int j = idx & 63;
        X[idx] = x[(size_t)i * (DD + 1) + j];
    }
}

__global__ void norm_kernel(const float* __restrict__ X,
                            float* __restrict__ XA,
                            const float* __restrict__ mu,
                            const float* __restrict__ rstd, int x1off, int N) {
    int idx = blockIdx.x * 256 + threadIdx.x;
    if (idx < N * 8) {
        int i = idx >> 3;
        int j4 = (idx & 7) << 2;
        float4 v = *(const float4*)(X + (size_t)i * DD + x1off + j4);
        float4 m = *(const float4*)(mu + x1off + j4);
        float4 s = *(const float4*)(rstd + x1off + j4);
        v.x = (v.x - m.x) * s.x;
        v.y = (v.y - m.y) * s.y;
        v.z = (v.z - m.z) * s.z;
        v.w = (v.w - m.w) * s.w;
        *(float4*)(XA + (size_t)i * dH + j4) = v;
    }
}

__global__ __launch_bounds__(256) void stats1_kernel(
    const float* __restrict__ X, float* __restrict__ part, int rowsPerBlock) {
    int tid = threadIdx.x;
    int c = tid & 63;
    int rg = tid >> 6;
    size_t base = (size_t)blockIdx.x * rowsPerBlock;
    float s = 0.f, q = 0.f;
    for (int r = rg; r < rowsPerBlock; r += 4) {
        float v = X[(base + r) * DD + c];
        s += v;
        q += v * v;
    }
    __shared__ float ss[256], sq[256];
    ss[tid] = s;
    sq[tid] = q;
    __syncthreads();
    if (tid < 64) {
        float S = ss[tid] + ss[tid + 64] + ss[tid + 128] + ss[tid + 192];
        float Q = sq[tid] + sq[tid + 64] + sq[tid + 128] + sq[tid + 192];
        part[blockIdx.x * 128 + tid] = S;
        part[blockIdx.x * 128 + 64 + tid] = Q;
    }
}

__global__ void stats2_kernel(const float* __restrict__ part, int nb,
                              float invN, float* __restrict__ muArr,
                              float* __restrict__ rstdArr) {
    int c = threadIdx.x;
    float s = 0.f, q = 0.f;
    for (int b = 0; b < nb; b++) {
        s += part[b * 128 + c];
        q += part[b * 128 + 64 + c];
    }
    float m = s * invN;
    float var = q * invN - m * m;
    muArr[c] = m;
    rstdArr[c] = rsqrtf(var + 1e-5f);
}

// ---------------------------------------------------------------------------
// bf16x3-split mma.sync GEMM: C = relu(A @ W^T + b)
// BM=128, BN=128, BK=16, 256 thr (8 warps 2m x 4n), warp tile 64x32,
// m16n8k16, 48 MMAs per chunk per warp. Split-before-STS, packed bf16x2
// smem tiles, row pitch 12 u32 (conflict-free fragment LDS).
// ---------------------------------------------------------------------------
#define PCH 12
#define TIL4 (128 * PCH)        // 1536 u32 per full 128-row tile
#define STG4 (4 * TIL4)         // per stage: Ah, Al, Bh, Bl
#define SMEMG (2 * STG4 * 4)    // 49152 B

template <int KDIM>
__global__ __launch_bounds__(256, 2) void mma_gemm_kernel(
    const float* __restrict__ A0, const float* __restrict__ A1, int lda,
    const float* __restrict__ W0, const float* __restrict__ W1,
    const float* __restrict__ b0, const float* __restrict__ b1,
    float* __restrict__ C0, float* __restrict__ C1) {
    extern __shared__ uint32_t smu[];
    const int z = blockIdx.z;
    const float* A = z ? A1 : A0;
    const float* W = z ? W1 : W0;
    const float* bias = z ? b1 : b0;
    float* C = z ? C1 : C0;

    const int tid = threadIdx.x;
    const int wid = tid >> 5, lane = tid & 31;
    const int wm = wid & 1, wn = wid >> 1;
    const size_t row0 = (size_t)blockIdx.y * 128;
    const int col0 = blockIdx.x * 128;

    constexpr int NCH = KDIM / 16;
    const int r0f = tid >> 2;
    const int c4f = (tid & 3) << 2;
    const int cu = c4f >> 1;

    float4 rA[2], rB[2];
    auto loadregs = [&](int k0) {
#pragma unroll
        for (int q = 0; q < 2; ++q) {
            rA[q] =
                *(const float4*)(A + (row0 + r0f + q * 64) * lda + k0 + c4f);
            rB[q] = *(const float4*)(W + (size_t)(col0 + r0f + q * 64) * KDIM +
                                     k0 + c4f);
        }
    };
    auto storeregs = [&](int st) {
        uint32_t* Ah = smu + st * STG4;
        uint32_t* Al = Ah + TIL4;
        uint32_t* Bh = Ah + 2 * TIL4;
        uint32_t* Bl = Ah + 3 * TIL4;
#pragma unroll
        for (int q = 0; q < 2; ++q) {
            int r = r0f + q * 64;
            uint32_t h0, l0, h1, l1;
            spl2(rA[q].x, rA[q].y, h0, l0);
            spl2(rA[q].z, rA[q].w, h1, l1);
            *(uint2*)(Ah + r * PCH + cu) = make_uint2(h0, h1);
            *(uint2*)(Al + r * PCH + cu) = make_uint2(l0, l1);
            spl2(rB[q].x, rB[q].y, h0, l0);
            spl2(rB[q].z, rB[q].w, h1, l1);
            *(uint2*)(Bh + r * PCH + cu) = make_uint2(h0, h1);
            *(uint2*)(Bl + r * PCH + cu) = make_uint2(l0, l1);
        }
    };

    float acc[4][4][4];
#pragma unroll
    for (int mt = 0; mt < 4; mt++)
#pragma unroll
        for (int nt = 0; nt < 4; nt++)
#pragma unroll
            for (int e = 0; e < 4; e++) acc[mt][nt][e] = 0.f;

    loadregs(0);
    storeregs(0);

    const int raq = lane >> 2;
    const int kq = lane & 3;

    for (int i = 0; i < NCH; ++i) {
        if (i + 1 < NCH) loadregs((i + 1) * 16);
        __syncthreads();
        const int st = i & 1;
        const uint32_t* Ah = smu + st * STG4;
        const uint32_t* Al = Ah + TIL4;
        const uint32_t* Bh = Ah + 2 * TIL4;
        const uint32_t* Bl = Ah + 3 * TIL4;

        uint32_t ah[4][4], al[4][4];
#pragma unroll
        for (int mt = 0; mt < 4; mt++) {
            int ro = (wm * 64 + mt * 16 + raq) * PCH + kq;
            ah[mt][0] = Ah[ro];
            ah[mt][1] = Ah[ro + 8 * PCH];
            ah[mt][2] = Ah[ro + 4];
            ah[mt][3] = Ah[ro + 8 * PCH + 4];
            al[mt][0] = Al[ro];
            al[mt][1] = Al[ro + 8 * PCH];
            al[mt][2] = Al[ro + 4];
            al[mt][3] = Al[ro + 8 * PCH + 4];
        }
#pragma unroll
        for (int nt = 0; nt < 4; nt++) {
            int no = (wn * 32 + nt * 8 + raq) * PCH + kq;
            uint32_t bh[2] = {Bh[no], Bh[no + 4]};
            uint32_t bl[2] = {Bl[no], Bl[no + 4]};
#pragma unroll
            for (int mt = 0; mt < 4; mt++) {
                mma_bf16(acc[mt][nt], ah[mt], bh);
                mma_bf16(acc[mt][nt], ah[mt], bl);
                mma_bf16(acc[mt][nt], al[mt], bh);
            }
        }
        if (i + 1 < NCH) storeregs(st ^ 1);
    }
    __syncthreads();

    float bv[4][2];
#pragma unroll
    for (int nt = 0; nt < 4; nt++) {
        int c = col0 + wn * 32 + nt * 8 + ((lane & 3) << 1);
        bv[nt][0] = __ldg(bias + c);
        bv[nt][1] = __ldg(bias + c + 1);
    }
    float* wsc = (float*)smu + wid * 576;
#pragma unroll
    for (int mt = 0; mt < 4; mt++) {
        int r = lane >> 2, c = (lane & 3) << 1;
#pragma unroll
        for (int nt = 0; nt < 4; nt++) {
            float2 v;
            v.x = fmaxf(acc[mt][nt][0] + bv[nt][0], 0.f);
            v.y = fmaxf(acc[mt][nt][1] + bv[nt][1], 0.f);
            *(float2*)(wsc + r * 36 + nt * 8 + c) = v;
            v.x = fmaxf(acc[mt][nt][2] + bv[nt][0], 0.f);
            v.y = fmaxf(acc[mt][nt][3] + bv[nt][1], 0.f);
            *(float2*)(wsc + (r + 8) * 36 + nt * 8 + c) = v;
        }
        __syncwarp();
#pragma unroll
        for (int rr = 0; rr < 4; rr++) {
            int row = rr * 4 + (lane >> 3);
            int col4 = (lane & 7) << 2;
            float4 v = *(const float4*)(wsc + row * 36 + col4);
            *(float4*)(C + (row0 + wm * 64 + mt * 16 + row) * HH + col0 +
                       wn * 32 + col4) = v;
        }
        __syncwarp();
    }
}

// ---------------------------------------------------------------------------
// bf16x3 GEMM3 + fused coupling. BM=128, N=64 (s||t), K=512.
// 8 warps: wm=wid&3 (mt=2 of 16 rows), wn=wid>>2 (0=s,1=t).
// stage (u32): As_h 1536 | As_l 1536 | At_h 1536 | At_l 1536 |
//              Bs_h 384 | Bs_l 384 | Bt_h 384 | Bt_l 384  = 7680 u32
// 2 stages = 61440 B >= coupling exchange (33792 B, reused).
// ---------------------------------------------------------------------------
#define BT4 (32 * PCH)                 // 384 u32
#define STG34 (4 * TIL4 + 4 * BT4)     // 7680 u32 per stage
#define SMEM3 (2 * STG34 * 4)          // 61440 B

__global__ __launch_bounds__(256, 1) void mma_gemm3_kernel(
    const float* __restrict__ H1s, const float* __restrict__ H1t,
    const float* __restrict__ W2s, const float* __restrict__ W2t,
    const float* __restrict__ b2s, const float* __restrict__ b2t,
    const float* __restrict__ X, float* __restrict__ Xn,
    const float* __restrict__ mu, const float* __restrict__ rstd,
    float* __restrict__ det, int x1off, int first) {
    extern __shared__ uint32_t smu[];
    const int tid = threadIdx.x;
    const int wid = tid >> 5, lane = tid & 31;
    const int wm = wid & 3, wn = wid >> 2;
    const size_t row0 = (size_t)blockIdx.x * 128;

    const int r0f = tid >> 2;
    const int c4f = (tid & 3) << 2;
    const int cu = c4f >> 1;
    const int rb = (tid & 127) >> 2;
    const int cb4 = ((tid & 127) & 3) << 2;
    const int cbu = cb4 >> 1;
    const float* Wp = (tid < 128) ? W2s : W2t;
    const uint32_t bof = 4 * TIL4 + ((tid < 128) ? 0 : 2 * BT4);

    float4 rAs[2], rAt[2], rB;
    auto loadregs = [&](int k0) {
#pragma unroll
        for (int q = 0; q < 2; ++q) {
            rAs[q] = *(const float4*)(H1s + (row0 + r0f + q * 64) * HH + k0 +
                                      c4f);
            rAt[q] = *(const float4*)(H1t + (row0 + r0f + q * 64) * HH + k0 +
                                      c4f);
        }
        rB = *(const float4*)(Wp + (size_t)rb * HH + k0 + cb4);
    };
    auto storeregs = [&](int st) {
        uint32_t* base = smu + st * STG34;
#pragma unroll
        for (int q = 0; q < 2; ++q) {
            int r = r0f + q * 64;
            uint32_t h0, l0, h1, l1;
            spl2(rAs[q].x, rAs[q].y, h0, l0);
            spl2(rAs[q].z, rAs[q].w, h1, l1);
            *(uint2*)(base + r * PCH + cu) = make_uint2(h0, h1);
            *(uint2*)(base + TIL4 + r * PCH + cu) = make_uint2(l0, l1);
            spl2(rAt[q].x, rAt[q].y, h0, l0);
            spl2(rAt[q].z, rAt[q].w, h1, l1);
            *(uint2*)(base + 2 * TIL4 + r * PCH + cu) = make_uint2(h0, h1);
            *(uint2*)(base + 3 * TIL4 + r * PCH + cu) = make_uint2(l0, l1);
        }
        uint32_t h0, l0, h1, l1;
        spl2(rB.x, rB.y, h0, l0);
        spl2(rB.z, rB.w, h1, l1);
        *(uint2*)(base + bof + rb * PCH + cbu) = make_uint2(h0, h1);
        *(uint2*)(base + bof + BT4 + rb * PCH + cbu) = make_uint2(l0, l1);
    };

    float acc[2][4][4];
#pragma unroll
    for (int mt = 0; mt < 2; mt++)
#pragma unroll
        for (int nt = 0; nt < 4; nt++)
#pragma unroll
            for (int e = 0; e < 4; e++) acc[mt][nt][e] = 0.f;

    loadregs(0);
    storeregs(0);

    const int raq = lane >> 2;
    const int kq = lane & 3;

    for (int i = 0; i < 32; ++i) {
        if (i + 1 < 32) loadregs((i + 1) * 16);
        __syncthreads();
        const int st = i & 1;
        const uint32_t* base = smu + st * STG34;
        const uint32_t* AH = base + (wn ? 2 * TIL4 : 0);
        const uint32_t* AL = AH + TIL4;
        const uint32_t* BH = base + 4 * TIL4 + (wn ? 2 * BT4 : 0);
        const uint32_t* BL = BH + BT4;

        uint32_t ah[2][4], al[2][4];
#pragma unroll
        for (int mt = 0; mt < 2; mt++) {
            int ro = (wm * 32 + mt * 16 + raq) * PCH + kq;
            ah[mt][0] = AH[ro];
            ah[mt][1] = AH[ro + 8 * PCH];
            ah[mt][2] = AH[ro + 4];
            ah[mt][3] = AH[ro + 8 * PCH + 4];
            al[mt][0] = AL[ro];
            al[mt][1] = AL[ro + 8 * PCH];
            al[mt][2] = AL[ro + 4];
            al[mt][3] = AL[ro + 8 * PCH + 4];
        }
#pragma unroll
        for (int nt = 0; nt < 4; nt++) {
            int no = (nt * 8 + raq) * PCH + kq;
            uint32_t bh[2] = {BH[no], BH[no + 4]};
            uint32_t bl[2] = {BL[no], BL[no + 4]};
#pragma unroll
            for (int mt = 0; mt < 2; mt++) {
                mma_bf16(acc[mt][nt], ah[mt], bh);
                mma_bf16(acc[mt][nt], ah[mt], bl);
                mma_bf16(acc[mt][nt], al[mt], bh);
            }
        }
        if (i + 1 < 32) storeregs(st ^ 1);
    }
    __syncthreads();

    float* Cs = (float*)smu;  // [128][66]
    {
        const float* bp = wn ? b2t : b2s;
#pragma unroll
        for (int mt = 0; mt < 2; mt++) {
            int r = wm * 32 + mt * 16 + (lane >> 2);
#pragma unroll
            for (int nt = 0; nt < 4; nt++) {
                int ccl = nt * 8 + ((lane & 3) << 1);
                int cg = wn * 32 + ccl;
                float bv0 = __ldg(bp + ccl), bv1 = __ldg(bp + ccl + 1);
                Cs[r * 66 + cg] = acc[mt][nt][0] + bv0;
                Cs[r * 66 + cg + 1] = acc[mt][nt][1] + bv1;
                Cs[(r + 8) * 66 + cg] = acc[mt][nt][2] + bv0;
                Cs[(r + 8) * 66 + cg + 1] = acc[mt][nt][3] + bv1;
            }
        }
    }
    __syncthreads();

    if (tid < 128) {
        int r = tid;
        size_t grow = row0 + r;
        const float* xr = X + grow * DD;
        float* xo = Xn + grow * DD;
        int x2off = dH - x1off;
        float ssum = 0.f;
#pragma unroll 8
        for (int j = 0; j < dH; j++) {
            float s = Cs[r * 66 + j];
            float t = Cs[r * 66 + 32 + j];
            float x1 = xr[x1off + j];
            float x2 = xr[x2off + j];
            xo[j] = (x1 - mu[x1off + j]) * rstd[x1off + j];
            float x2n = (x2 - mu[x2off + j]) * rstd[x2off + j];
            xo[dH + j] = x2n * expf(s) + t;
            ssum += s;
        }
        det[grow] = first ? ssum : (det[grow] + ssum);
    }
}

// ---------------------------------------------------------------------------
// GMM log-likelihood + output assembly + final reduce (unchanged, proven)
// ---------------------------------------------------------------------------
__global__ __launch_bounds__(256) void gmm_kernel(
    const float* __restrict__ X, const float* __restrict__ means,
    const float* __restrict__ det, float* __restrict__ out, int N, int full) {
    __shared__ float smm[KK * DD];
    int tid = threadIdx.x;
    for (int i = tid; i < KK * DD; i += 256) smm[i] = means[i];
    __syncthreads();

    size_t i = (size_t)blockIdx.x * 256 + tid;
    float4 y4[16];
    const float4* xr = (const float4*)(X + i * DD);
#pragma unroll
    for (int q = 0; q < 16; q++) y4[q] = xr[q];
    float4* yo = (float4*)(out + i * DD);
#pragma unroll
    for (int q = 0; q < 16; q++) yo[q] = y4[q];

    if (!full) return;

    const float CD = (float)(64.0 * 1.8378770664093453);
    float lp[KK];
    float mx = -1e30f;
#pragma unroll
    for (int k = 0; k < KK; k++) {
        const float* mrow = smm + k * DD;
        float accv = 0.f;
#pragma unroll
        for (int q = 0; q < 16; q++) {
            float4 m4 = *(const float4*)(mrow + q * 4);
            float dx = y4[q].x - m4.x;
            accv += dx * dx;
            dx = y4[q].y - m4.y;
            accv += dx * dx;
            dx = y4[q].z - m4.z;
            accv += dx * dx;
            dx = y4[q].w - m4.w;
            accv += dx * dx;
        }
        float v = -0.5f * (accv + CD);
        lp[k] = v;
        mx = fmaxf(mx, v);
    }
    float se = 0.f;
#pragma unroll
    for (int k = 0; k < KK; k++) se += expf(lp[k] - mx);
    float ll = mx + logf(se) - logf((float)KK);

    size_t oll = (size_t)N * DD + 1;
    out[oll + i] = ll;
    out[oll + N + i] = det[i];
}

__global__ void final_reduce_kernel(float* __restrict__ out, int N) {
    int tid = threadIdx.x;
    size_t oll = (size_t)N * DD + 1;
    size_t odet = oll + N;
    float sll = 0.f, sdet = 0.f;
    for (int i = tid; i < N; i += 1024) {
        sll += out[oll + i];
        sdet += out[odet + i];
    }
    __shared__ float a[1024], b[1024];
    a[tid] = sll;
    b[tid] = sdet;
    __syncthreads();
    for (int s = 512; s > 0; s >>= 1) {
        if (tid < s) {
            a[tid] += a[tid + s];
            b[tid] += b[tid + s];
        }
        __syncthreads();
    }
    if (tid == 0) {
        float llm = a[0] / (float)N;
        float dm = b[0] / (float)N;
        out[(size_t)N * DD] = -(dm + llm);
        out[odet + N] = llm;
        out[odet + N + 1] = dm;
    }
}

// ---------------------------------------------------------------------------
// Host launcher
// ---------------------------------------------------------------------------
static float* symaddr(const void* s) {
    void* p = nullptr;
    cudaGetSymbolAddress(&p, s);
    return (float*)p;
}

extern "C" void kernel_launch(void* const* d_in, const int* in_sizes, int n_in,
                              void* d_out, int out_size) {
    const float* x = (const float*)d_in[0];
    const float* sW0 = (const float*)d_in[1];
    const float* sb0 = (const float*)d_in[2];
    const float* sW1 = (const float*)d_in[3];
    const float* sb1 = (const float*)d_in[4];
    const float* sW2 = (const float*)d_in[5];
    const float* sb2 = (const float*)d_in[6];
    const float* tW0 = (const float*)d_in[7];
    const float* tb0 = (const float*)d_in[8];
    const float* tW1 = (const float*)d_in[9];
    const float* tb1 = (const float*)d_in[10];
    const float* tW2 = (const float*)d_in[11];
    const float* tb2 = (const float*)d_in[12];
    const float* means = (const float*)d_in[13];
    float* out = (float*)d_out;

    const int N = in_sizes[0] / (DD + 1);
    const int full = (out_size >= (long long)N * DD + 2 * N + 3) ? 1 : 0;

    cudaFuncSetAttribute(mma_gemm_kernel<dH>,
                         cudaFuncAttributeMaxDynamicSharedMemorySize, SMEMG);
    cudaFuncSetAttribute(mma_gemm_kernel<HH>,
                         cudaFuncAttributeMaxDynamicSharedMemorySize, SMEMG);
    cudaFuncSetAttribute(mma_gemm3_kernel,
                         cudaFuncAttributeMaxDynamicSharedMemorySize, SMEM3);

    float* X = symaddr(g_X);
    float* XA = symaddr(g_XA);
    float* H0 = symaddr(g_H0);
    float* H1 = symaddr(g_H1);
    float* det = symaddr(g_det);
    float* part = symaddr(g_part);
    float* mu = symaddr(g_mu);
    float* rstd = symaddr(g_rstd);

    const size_t XS = (size_t)N * DD;
    const size_t HS = (size_t)N * HH;

    copy_in_kernel<<<(N * DD + 255) / 256, 256>>>(x, X, N);

    int cur = 0;
    for (int l = 0; l < LL; l++) {
        float* Xc = X + (size_t)cur * XS;
        float* Xnext = X + (size_t)(cur ^ 1) * XS;
        stats1_kernel<<<256, 256>>>(Xc, part, N / 256);
        stats2_kernel<<<1, 64>>>(part, 256, 1.0f / (float)N, mu, rstd);

        const int x1off = (l & 1) ? dH : 0;

        norm_kernel<<<(N * 8 + 255) / 256, 256>>>(Xc, XA, mu, rstd, x1off, N);

        mma_gemm_kernel<dH><<<dim3(HH / 128, N / 128, 2), 256, SMEMG>>>(
            XA, XA, dH, sW0 + (size_t)l * HH * dH, tW0 + (size_t)l * HH * dH,
            sb0 + (size_t)l * HH, tb0 + (size_t)l * HH, H0, H0 + HS);

        mma_gemm_kernel<HH><<<dim3(HH / 128, N / 128, 2), 256, SMEMG>>>(
            H0, H0 + HS, HH, sW1 + (size_t)l * HH * HH,
            tW1 + (size_t)l * HH * HH, sb1 + (size_t)l * HH,
            tb1 + (size_t)l * HH, H1, H1 + HS);

        mma_gemm3_kernel<<<N / 128, 256, SMEM3>>>(
            H1, H1 + HS, sW2 + (size_t)l * dH * HH, tW2 + (size_t)l * dH * HH,
            sb2 + (size_t)l * dH, tb2 + (size_t)l * dH, Xc, Xnext, mu, rstd,
            det, x1off, (l == 0) ? 1 : 0);

        cur ^= 1;
    }

    gmm_kernel<<<N / 256, 256>>>(X + (size_t)cur * XS, means, det, out, N,
                                 full);
    if (full) final_reduce_kernel<<<1, 1024>>>(out, N);
}

// round 10
// speedup vs baseline: 2.0594x; 1.0359x over previous
#include <cuda_runtime.h>
#include <math.h>
#include <stdint.h>

#define NROWS_MAX 65536
#define DD 64
#define dH 32
#define HH 512
#define LL 8
#define KK 10

__device__ __align__(16) float g_X[2][NROWS_MAX * DD];
__device__ __align__(16) float g_XA[NROWS_MAX * dH];
__device__ __align__(16) float g_H0[2][NROWS_MAX * HH];
__device__ __align__(16) float g_H1[2][NROWS_MAX * HH];
__device__ float g_det[NROWS_MAX];
__device__ float g_part[512 * 128];
__device__ __align__(16) float g_mu[DD];
__device__ __align__(16) float g_rstd[DD];

// ---------------------------------------------------------------------------
// portable PTX helpers (mma.sync bf16 + ldmatrix are sm_80/75 base features)
// ---------------------------------------------------------------------------
__device__ __forceinline__ uint32_t smem_u32(const void* p) {
    uint32_t a;
    asm("{ .reg .u64 t; cvta.to.shared.u64 t, %1; cvt.u32.u64 %0, t; }"
        : "=r"(a) : "l"(p));
    return a;
}
__device__ __forceinline__ void mma_bf16(float* c, const uint32_t* a,
                                         const uint32_t* b) {
    asm volatile(
        "mma.sync.aligned.m16n8k16.row.col.f32.bf16.bf16.f32 "
        "{%0,%1,%2,%3}, {%4,%5,%6,%7}, {%8,%9}, {%0,%1,%2,%3};"
        : "+f"(c[0]), "+f"(c[1]), "+f"(c[2]), "+f"(c[3])
        : "r"(a[0]), "r"(a[1]), "r"(a[2]), "r"(a[3]), "r"(b[0]), "r"(b[1]));
}
__device__ __forceinline__ void ldsm4(uint32_t* r, uint32_t addr) {
    asm volatile(
        "ldmatrix.sync.aligned.m8n8.x4.shared.b16 {%0,%1,%2,%3}, [%4];"
        : "=r"(r[0]), "=r"(r[1]), "=r"(r[2]), "=r"(r[3]) : "r"(addr));
}
__device__ __forceinline__ void ldsm2(uint32_t* r, uint32_t addr) {
    asm volatile(
        "ldmatrix.sync.aligned.m8n8.x2.shared.b16 {%0,%1}, [%2];"
        : "=r"(r[0]), "=r"(r[1]) : "r"(addr));
}
__device__ __forceinline__ uint32_t packbf(float v1, float v0) {
    uint32_t r;
    asm("cvt.rn.bf16x2.f32 %0, %1, %2;" : "=r"(r) : "f"(v1), "f"(v0));
    return r;
}
__device__ __forceinline__ void spl2(float v0, float v1, uint32_t& h,
                                     uint32_t& l) {
    h = packbf(v1, v0);
    float h0 = __uint_as_float(h << 16);
    float h1 = __uint_as_float(h & 0xffff0000u);
    l = packbf(v1 - h1, v0 - h0);
}

// ---------------------------------------------------------------------------
// small kernels
// ---------------------------------------------------------------------------
__global__ void copy_in_kernel(const float* __restrict__ x,
                               float* __restrict__ X, int N) {
    int idx = blockIdx.x * 256 + threadIdx.x;
    if (idx < N * DD) {
        int i = idx >> 6;
        int j = idx & 63;
        X[idx] = x[(size_t)i * (DD + 1) + j];
    }
}

__global__ void norm_kernel(const float* __restrict__ X,
                            float* __restrict__ XA,
                            const float* __restrict__ mu,
                            const float* __restrict__ rstd, int x1off, int N) {
    int idx = blockIdx.x * 256 + threadIdx.x;
    if (idx < N * 8) {
        int i = idx >> 3;
        int j4 = (idx & 7) << 2;
        float4 v = *(const float4*)(X + (size_t)i * DD + x1off + j4);
        float4 m = *(const float4*)(mu + x1off + j4);
        float4 s = *(const float4*)(rstd + x1off + j4);
        v.x = (v.x - m.x) * s.x;
        v.y = (v.y - m.y) * s.y;
        v.z = (v.z - m.z) * s.z;
        v.w = (v.w - m.w) * s.w;
        *(float4*)(XA + (size_t)i * dH + j4) = v;
    }
}

__global__ __launch_bounds__(256) void stats1_kernel(
    const float* __restrict__ X, float* __restrict__ part, int rowsPerBlock) {
    int tid = threadIdx.x;
    int c = tid & 63;
    int rg = tid >> 6;
    size_t base = (size_t)blockIdx.x * rowsPerBlock;
    float s = 0.f, q = 0.f;
    for (int r = rg; r < rowsPerBlock; r += 4) {
        float v = X[(base + r) * DD + c];
        s += v;
        q += v * v;
    }
    __shared__ float ss[256], sq[256];
    ss[tid] = s;
    sq[tid] = q;
    __syncthreads();
    if (tid < 64) {
        float S = ss[tid] + ss[tid + 64] + ss[tid + 128] + ss[tid + 192];
        float Q = sq[tid] + sq[tid + 64] + sq[tid + 128] + sq[tid + 192];
        part[blockIdx.x * 128 + tid] = S;
        part[blockIdx.x * 128 + 64 + tid] = Q;
    }
}

__global__ void stats2_kernel(const float* __restrict__ part, int nb,
                              float invN, float* __restrict__ muArr,
                              float* __restrict__ rstdArr) {
    int c = threadIdx.x;
    float s = 0.f, q = 0.f;
    for (int b = 0; b < nb; b++) {
        s += part[b * 128 + c];
        q += part[b * 128 + 64 + c];
    }
    float m = s * invN;
    float var = q * invN - m * m;
    muArr[c] = m;
    rstdArr[c] = rsqrtf(var + 1e-5f);
}

// ---------------------------------------------------------------------------
// bf16x3-split mma.sync GEMM: C = relu(A @ W^T + b)
// BM=128, BN=128, BK=16, 256 thr (8 warps 2m x 4n), warp tile 64x32,
// m16n8k16. Fragment loads via ldmatrix (16 LDSM vs 48 LDS per chunk).
// Packed bf16x2 smem tiles, row pitch 12 u32 (48 B) - LDSM conflict-free.
// ---------------------------------------------------------------------------
#define PCH 12
#define TIL4 (128 * PCH)        // 1536 u32 per full 128-row tile
#define STG4 (4 * TIL4)         // per stage: Ah, Al, Bh, Bl
#define SMEMG (2 * STG4 * 4)    // 49152 B

template <int KDIM>
__global__ __launch_bounds__(256, 2) void mma_gemm_kernel(
    const float* __restrict__ A0, const float* __restrict__ A1, int lda,
    const float* __restrict__ W0, const float* __restrict__ W1,
    const float* __restrict__ b0, const float* __restrict__ b1,
    float* __restrict__ C0, float* __restrict__ C1) {
    extern __shared__ uint32_t smu[];
    const int z = blockIdx.z;
    const float* A = z ? A1 : A0;
    const float* W = z ? W1 : W0;
    const float* bias = z ? b1 : b0;
    float* C = z ? C1 : C0;

    const int tid = threadIdx.x;
    const int wid = tid >> 5, lane = tid & 31;
    const int wm = wid & 1, wn = wid >> 1;
    const size_t row0 = (size_t)blockIdx.y * 128;
    const int col0 = blockIdx.x * 128;
    const uint32_t smb = smem_u32(smu);

    constexpr int NCH = KDIM / 16;
    const int r0f = tid >> 2;
    const int c4f = (tid & 3) << 2;
    const int cu = c4f >> 1;

    // ldmatrix per-lane address components
    const int rowSel = (lane & 7) | (((lane >> 3) & 1) << 3);  // 0..15
    const int kSelA = (lane >> 4) * 16;                        // 0 or 16 B
    const int lrb = lane & 15;
    const uint32_t aoff = (uint32_t)((wm * 64 + rowSel) * 48 + kSelA);
    const uint32_t boff =
        (uint32_t)((wn * 32 + (lrb & 7)) * 48 + (lrb >> 3) * 16);

    float4 rA[2], rB[2];
    auto loadregs = [&](int k0) {
#pragma unroll
        for (int q = 0; q < 2; ++q) {
            rA[q] =
                *(const float4*)(A + (row0 + r0f + q * 64) * lda + k0 + c4f);
            rB[q] = *(const float4*)(W + (size_t)(col0 + r0f + q * 64) * KDIM +
                                     k0 + c4f);
        }
    };
    auto storeregs = [&](int st) {
        uint32_t* Ah = smu + st * STG4;
        uint32_t* Al = Ah + TIL4;
        uint32_t* Bh = Ah + 2 * TIL4;
        uint32_t* Bl = Ah + 3 * TIL4;
#pragma unroll
        for (int q = 0; q < 2; ++q) {
            int r = r0f + q * 64;
            uint32_t h0, l0, h1, l1;
            spl2(rA[q].x, rA[q].y, h0, l0);
            spl2(rA[q].z, rA[q].w, h1, l1);
            *(uint2*)(Ah + r * PCH + cu) = make_uint2(h0, h1);
            *(uint2*)(Al + r * PCH + cu) = make_uint2(l0, l1);
            spl2(rB[q].x, rB[q].y, h0, l0);
            spl2(rB[q].z, rB[q].w, h1, l1);
            *(uint2*)(Bh + r * PCH + cu) = make_uint2(h0, h1);
            *(uint2*)(Bl + r * PCH + cu) = make_uint2(l0, l1);
        }
    };

    float acc[4][4][4];
#pragma unroll
    for (int mt = 0; mt < 4; mt++)
#pragma unroll
        for (int nt = 0; nt < 4; nt++)
#pragma unroll
            for (int e = 0; e < 4; e++) acc[mt][nt][e] = 0.f;

    loadregs(0);
    storeregs(0);

    for (int i = 0; i < NCH; ++i) {
        if (i + 1 < NCH) loadregs((i + 1) * 16);
        __syncthreads();
        const int st = i & 1;
        const uint32_t AhB = smb + st * STG4 * 4;
        const uint32_t AlB = AhB + TIL4 * 4;
        const uint32_t BhB = AhB + 2 * TIL4 * 4;
        const uint32_t BlB = AhB + 3 * TIL4 * 4;

        uint32_t ah[4][4], al[4][4];
#pragma unroll
        for (int mt = 0; mt < 4; mt++) {
            ldsm4(ah[mt], AhB + aoff + mt * 16 * 48);
            ldsm4(al[mt], AlB + aoff + mt * 16 * 48);
        }
#pragma unroll
        for (int nt = 0; nt < 4; nt++) {
            uint32_t bh[2], bl[2];
            ldsm2(bh, BhB + boff + nt * 8 * 48);
            ldsm2(bl, BlB + boff + nt * 8 * 48);
#pragma unroll
            for (int mt = 0; mt < 4; mt++) {
                mma_bf16(acc[mt][nt], ah[mt], bh);
                mma_bf16(acc[mt][nt], ah[mt], bl);
                mma_bf16(acc[mt][nt], al[mt], bh);
            }
        }
        if (i + 1 < NCH) storeregs(st ^ 1);
    }
    __syncthreads();

    float bv[4][2];
#pragma unroll
    for (int nt = 0; nt < 4; nt++) {
        int c = col0 + wn * 32 + nt * 8 + ((lane & 3) << 1);
        bv[nt][0] = __ldg(bias + c);
        bv[nt][1] = __ldg(bias + c + 1);
    }
    float* wsc = (float*)smu + wid * 576;
#pragma unroll
    for (int mt = 0; mt < 4; mt++) {
        int r = lane >> 2, c = (lane & 3) << 1;
#pragma unroll
        for (int nt = 0; nt < 4; nt++) {
            float2 v;
            v.x = fmaxf(acc[mt][nt][0] + bv[nt][0], 0.f);
            v.y = fmaxf(acc[mt][nt][1] + bv[nt][1], 0.f);
            *(float2*)(wsc + r * 36 + nt * 8 + c) = v;
            v.x = fmaxf(acc[mt][nt][2] + bv[nt][0], 0.f);
            v.y = fmaxf(acc[mt][nt][3] + bv[nt][1], 0.f);
            *(float2*)(wsc + (r + 8) * 36 + nt * 8 + c) = v;
        }
        __syncwarp();
#pragma unroll
        for (int rr = 0; rr < 4; rr++) {
            int row = rr * 4 + (lane >> 3);
            int col4 = (lane & 7) << 2;
            float4 v = *(const float4*)(wsc + row * 36 + col4);
            *(float4*)(C + (row0 + wm * 64 + mt * 16 + row) * HH + col0 +
                       wn * 32 + col4) = v;
        }
        __syncwarp();
    }
}

// ---------------------------------------------------------------------------
// bf16x3 GEMM3 + fused coupling + fused next-layer batchnorm partials.
// BM=128, N=64 (s||t), K=512. 8 warps: wm=wid&3, wn=wid>>2 (0=s,1=t).
// After the coupling epilogue, Cs holds Xnext block values; the CTA reduces
// per-column sum/sumsq and writes them to part[bid*128 + ...] (stats1-free).
// ---------------------------------------------------------------------------
#define BT4 (32 * PCH)
#define STG34 (4 * TIL4 + 4 * BT4)
#define SMEM3 (2 * STG34 * 4)  // 61440 B

__global__ __launch_bounds__(256, 1) void mma_gemm3_kernel(
    const float* __restrict__ H1s, const float* __restrict__ H1t,
    const float* __restrict__ W2s, const float* __restrict__ W2t,
    const float* __restrict__ b2s, const float* __restrict__ b2t,
    const float* __restrict__ X, float* __restrict__ Xn,
    const float* __restrict__ mu, const float* __restrict__ rstd,
    float* __restrict__ det, float* __restrict__ part, int x1off, int first) {
    extern __shared__ uint32_t smu[];
    const int tid = threadIdx.x;
    const int wid = tid >> 5, lane = tid & 31;
    const int wm = wid & 3, wn = wid >> 2;
    const size_t row0 = (size_t)blockIdx.x * 128;
    const uint32_t smb = smem_u32(smu);

    const int r0f = tid >> 2;
    const int c4f = (tid & 3) << 2;
    const int cu = c4f >> 1;
    const int rb = (tid & 127) >> 2;
    const int cb4 = ((tid & 127) & 3) << 2;
    const int cbu = cb4 >> 1;
    const float* Wp = (tid < 128) ? W2s : W2t;
    const uint32_t bof = 4 * TIL4 + ((tid < 128) ? 0 : 2 * BT4);

    const int rowSel = (lane & 7) | (((lane >> 3) & 1) << 3);
    const int kSelA = (lane >> 4) * 16;
    const int lrb = lane & 15;
    const uint32_t aoff = (uint32_t)((wm * 32 + rowSel) * 48 + kSelA);
    const uint32_t boff = (uint32_t)(((lrb & 7)) * 48 + (lrb >> 3) * 16);

    float4 rAs[2], rAt[2], rB;
    auto loadregs = [&](int k0) {
#pragma unroll
        for (int q = 0; q < 2; ++q) {
            rAs[q] = *(const float4*)(H1s + (row0 + r0f + q * 64) * HH + k0 +
                                      c4f);
            rAt[q] = *(const float4*)(H1t + (row0 + r0f + q * 64) * HH + k0 +
                                      c4f);
        }
        rB = *(const float4*)(Wp + (size_t)rb * HH + k0 + cb4);
    };
    auto storeregs = [&](int st) {
        uint32_t* base = smu + st * STG34;
#pragma unroll
        for (int q = 0; q < 2; ++q) {
            int r = r0f + q * 64;
            uint32_t h0, l0, h1, l1;
            spl2(rAs[q].x, rAs[q].y, h0, l0);
            spl2(rAs[q].z, rAs[q].w, h1, l1);
            *(uint2*)(base + r * PCH + cu) = make_uint2(h0, h1);
            *(uint2*)(base + TIL4 + r * PCH + cu) = make_uint2(l0, l1);
            spl2(rAt[q].x, rAt[q].y, h0, l0);
            spl2(rAt[q].z, rAt[q].w, h1, l1);
            *(uint2*)(base + 2 * TIL4 + r * PCH + cu) = make_uint2(h0, h1);
            *(uint2*)(base + 3 * TIL4 + r * PCH + cu) = make_uint2(l0, l1);
        }
        uint32_t h0, l0, h1, l1;
        spl2(rB.x, rB.y, h0, l0);
        spl2(rB.z, rB.w, h1, l1);
        *(uint2*)(base + bof + rb * PCH + cbu) = make_uint2(h0, h1);
        *(uint2*)(base + bof + BT4 + rb * PCH + cbu) = make_uint2(l0, l1);
    };

    float acc[2][4][4];
#pragma unroll
    for (int mt = 0; mt < 2; mt++)
#pragma unroll
        for (int nt = 0; nt < 4; nt++)
#pragma unroll
            for (int e = 0; e < 4; e++) acc[mt][nt][e] = 0.f;

    loadregs(0);
    storeregs(0);

    for (int i = 0; i < 32; ++i) {
        if (i + 1 < 32) loadregs((i + 1) * 16);
        __syncthreads();
        const int st = i & 1;
        const uint32_t baseB = smb + st * STG34 * 4;
        const uint32_t AHB = baseB + (wn ? 2 * TIL4 * 4 : 0);
        const uint32_t ALB = AHB + TIL4 * 4;
        const uint32_t BHB = baseB + 4 * TIL4 * 4 + (wn ? 2 * BT4 * 4 : 0);
        const uint32_t BLB = BHB + BT4 * 4;

        uint32_t ah[2][4], al[2][4];
#pragma unroll
        for (int mt = 0; mt < 2; mt++) {
            ldsm4(ah[mt], AHB + aoff + mt * 16 * 48);
            ldsm4(al[mt], ALB + aoff + mt * 16 * 48);
        }
#pragma unroll
        for (int nt = 0; nt < 4; nt++) {
            uint32_t bh[2], bl[2];
            ldsm2(bh, BHB + boff + nt * 8 * 48);
            ldsm2(bl, BLB + boff + nt * 8 * 48);
#pragma unroll
            for (int mt = 0; mt < 2; mt++) {
                mma_bf16(acc[mt][nt], ah[mt], bh);
                mma_bf16(acc[mt][nt], ah[mt], bl);
                mma_bf16(acc[mt][nt], al[mt], bh);
            }
        }
        if (i + 1 < 32) storeregs(st ^ 1);
    }
    __syncthreads();

    float* Cs = (float*)smu;  // [128][66]
    {
        const float* bp = wn ? b2t : b2s;
#pragma unroll
        for (int mt = 0; mt < 2; mt++) {
            int r = wm * 32 + mt * 16 + (lane >> 2);
#pragma unroll
            for (int nt = 0; nt < 4; nt++) {
                int ccl = nt * 8 + ((lane & 3) << 1);
                int cg = wn * 32 + ccl;
                float bv0 = __ldg(bp + ccl), bv1 = __ldg(bp + ccl + 1);
                Cs[r * 66 + cg] = acc[mt][nt][0] + bv0;
                Cs[r * 66 + cg + 1] = acc[mt][nt][1] + bv1;
                Cs[(r + 8) * 66 + cg] = acc[mt][nt][2] + bv0;
                Cs[(r + 8) * 66 + cg + 1] = acc[mt][nt][3] + bv1;
            }
        }
    }
    __syncthreads();

    if (tid < 128) {
        int r = tid;
        size_t grow = row0 + r;
        const float* xr = X + grow * DD;
        float* xo = Xn + grow * DD;
        int x2off = dH - x1off;
        float ssum = 0.f;
#pragma unroll 8
        for (int j = 0; j < dH; j++) {
            float s = Cs[r * 66 + j];
            float t = Cs[r * 66 + 32 + j];
            float x1 = xr[x1off + j];
            float x2 = xr[x2off + j];
            float x1n = (x1 - mu[x1off + j]) * rstd[x1off + j];
            float x2n = (x2 - mu[x2off + j]) * rstd[x2off + j];
            float y2 = x2n * expf(s) + t;
            xo[j] = x1n;
            xo[dH + j] = y2;
            // overwrite Cs in place with Xnext values for the stats pass
            Cs[r * 66 + j] = x1n;
            Cs[r * 66 + 32 + j] = y2;
            ssum += s;
        }
        det[grow] = first ? ssum : (det[grow] + ssum);
    }
    __syncthreads();

    // fused next-layer batchnorm partials (per-column sum / sumsq)
    float* red = (float*)smu + 128 * 66;
    if (tid < 128) {
        int c = tid & 63;
        int half = tid >> 6;
        float s = 0.f, q = 0.f;
        int rbeg = half * 64;
#pragma unroll 4
        for (int r = rbeg; r < rbeg + 64; ++r) {
            float v = Cs[r * 66 + c];
            s += v;
            q += v * v;
        }
        red[tid] = s;
        red[128 + tid] = q;
    }
    __syncthreads();
    if (tid < 64) {
        part[blockIdx.x * 128 + tid] = red[tid] + red[64 + tid];
        part[blockIdx.x * 128 + 64 + tid] =
            red[128 + tid] + red[128 + 64 + tid];
    }
}

// ---------------------------------------------------------------------------
// GMM log-likelihood + output assembly + final reduce (unchanged, proven)
// ---------------------------------------------------------------------------
__global__ __launch_bounds__(256) void gmm_kernel(
    const float* __restrict__ X, const float* __restrict__ means,
    const float* __restrict__ det, float* __restrict__ out, int N, int full) {
    __shared__ float smm[KK * DD];
    int tid = threadIdx.x;
    for (int i = tid; i < KK * DD; i += 256) smm[i] = means[i];
    __syncthreads();

    size_t i = (size_t)blockIdx.x * 256 + tid;
    float4 y4[16];
    const float4* xr = (const float4*)(X + i * DD);
#pragma unroll
    for (int q = 0; q < 16; q++) y4[q] = xr[q];
    float4* yo = (float4*)(out + i * DD);
#pragma unroll
    for (int q = 0; q < 16; q++) yo[q] = y4[q];

    if (!full) return;

    const float CD = (float)(64.0 * 1.8378770664093453);
    float lp[KK];
    float mx = -1e30f;
#pragma unroll
    for (int k = 0; k < KK; k++) {
        const float* mrow = smm + k * DD;
        float accv = 0.f;
#pragma unroll
        for (int q = 0; q < 16; q++) {
            float4 m4 = *(const float4*)(mrow + q * 4);
            float dx = y4[q].x - m4.x;
            accv += dx * dx;
            dx = y4[q].y - m4.y;
            accv += dx * dx;
            dx = y4[q].z - m4.z;
            accv += dx * dx;
            dx = y4[q].w - m4.w;
            accv += dx * dx;
        }
        float v = -0.5f * (accv + CD);
        lp[k] = v;
        mx = fmaxf(mx, v);
    }
    float se = 0.f;
#pragma unroll
    for (int k = 0; k < KK; k++) se += expf(lp[k] - mx);
    float ll = mx + logf(se) - logf((float)KK);

    size_t oll = (size_t)N * DD + 1;
    out[oll + i] = ll;
    out[oll + N + i] = det[i];
}

__global__ void final_reduce_kernel(float* __restrict__ out, int N) {
    int tid = threadIdx.x;
    size_t oll = (size_t)N * DD + 1;
    size_t odet = oll + N;
    float sll = 0.f, sdet = 0.f;
    for (int i = tid; i < N; i += 1024) {
        sll += out[oll + i];
        sdet += out[odet + i];
    }
    __shared__ float a[1024], b[1024];
    a[tid] = sll;
    b[tid] = sdet;
    __syncthreads();
    for (int s = 512; s > 0; s >>= 1) {
        if (tid < s) {
            a[tid] += a[tid + s];
            b[tid] += b[tid + s];
        }
        __syncthreads();
    }
    if (tid == 0) {
        float llm = a[0] / (float)N;
        float dm = b[0] / (float)N;
        out[(size_t)N * DD] = -(dm + llm);
        out[odet + N] = llm;
        out[odet + N + 1] = dm;
    }
}

// ---------------------------------------------------------------------------
// Host launcher
// ---------------------------------------------------------------------------
static float* symaddr(const void* s) {
    void* p = nullptr;
    cudaGetSymbolAddress(&p, s);
    return (float*)p;
}

extern "C" void kernel_launch(void* const* d_in, const int* in_sizes, int n_in,
                              void* d_out, int out_size) {
    const float* x = (const float*)d_in[0];
    const float* sW0 = (const float*)d_in[1];
    const float* sb0 = (const float*)d_in[2];
    const float* sW1 = (const float*)d_in[3];
    const float* sb1 = (const float*)d_in[4];
    const float* sW2 = (const float*)d_in[5];
    const float* sb2 = (const float*)d_in[6];
    const float* tW0 = (const float*)d_in[7];
    const float* tb0 = (const float*)d_in[8];
    const float* tW1 = (const float*)d_in[9];
    const float* tb1 = (const float*)d_in[10];
    const float* tW2 = (const float*)d_in[11];
    const float* tb2 = (const float*)d_in[12];
    const float* means = (const float*)d_in[13];
    float* out = (float*)d_out;

    const int N = in_sizes[0] / (DD + 1);
    const int full = (out_size >= (long long)N * DD + 2 * N + 3) ? 1 : 0;

    cudaFuncSetAttribute(mma_gemm_kernel<dH>,
                         cudaFuncAttributeMaxDynamicSharedMemorySize, SMEMG);
    cudaFuncSetAttribute(mma_gemm_kernel<HH>,
                         cudaFuncAttributeMaxDynamicSharedMemorySize, SMEMG);
    cudaFuncSetAttribute(mma_gemm3_kernel,
                         cudaFuncAttributeMaxDynamicSharedMemorySize, SMEM3);

    float* X = symaddr(g_X);
    float* XA = symaddr(g_XA);
    float* H0 = symaddr(g_H0);
    float* H1 = symaddr(g_H1);
    float* det = symaddr(g_det);
    float* part = symaddr(g_part);
    float* mu = symaddr(g_mu);
    float* rstd = symaddr(g_rstd);

    const size_t XS = (size_t)N * DD;
    const size_t HS = (size_t)N * HH;

    copy_in_kernel<<<(N * DD + 255) / 256, 256>>>(x, X, N);

    int cur = 0;
    for (int l = 0; l < LL; l++) {
        float* Xc = X + (size_t)cur * XS;
        float* Xnext = X + (size_t)(cur ^ 1) * XS;

        if (l == 0) {
            stats1_kernel<<<256, 256>>>(Xc, part, N / 256);
            stats2_kernel<<<1, 64>>>(part, 256, 1.0f / (float)N, mu, rstd);
        } else {
            // partials were produced by the previous layer's gemm3 (N/128 blocks)
            stats2_kernel<<<1, 64>>>(part, N / 128, 1.0f / (float)N, mu, rstd);
        }

        const int x1off = (l & 1) ? dH : 0;

        norm_kernel<<<(N * 8 + 255) / 256, 256>>>(Xc, XA, mu, rstd, x1off, N);

        mma_gemm_kernel<dH><<<dim3(HH / 128, N / 128, 2), 256, SMEMG>>>(
            XA, XA, dH, sW0 + (size_t)l * HH * dH, tW0 + (size_t)l * HH * dH,
            sb0 + (size_t)l * HH, tb0 + (size_t)l * HH, H0, H0 + HS);

        mma_gemm_kernel<HH><<<dim3(HH / 128, N / 128, 2), 256, SMEMG>>>(
            H0, H0 + HS, HH, sW1 + (size_t)l * HH * HH,
            tW1 + (size_t)l * HH * HH, sb1 + (size_t)l * HH,
            tb1 + (size_t)l * HH, H1, H1 + HS);

        mma_gemm3_kernel<<<N / 128, 256, SMEM3>>>(
            H1, H1 + HS, sW2 + (size_t)l * dH * HH, tW2 + (size_t)l * dH * HH,
            sb2 + (size_t)l * dH, tb2 + (size_t)l * dH, Xc, Xnext, mu, rstd,
            det, part, x1off, (l == 0) ? 1 : 0);

        cur ^= 1;
    }

    gmm_kernel<<<N / 256, 256>>>(X + (size_t)cur * XS, means, det, out, N,
                                 full);
    if (full) final_reduce_kernel<<<1, 1024>>>(out, N);
}

// round 12
// speedup vs baseline: 2.0967x; 1.0181x over previous
#include <cuda_runtime.h>
#include <math.h>
#include <stdint.h>

#define NROWS_MAX 65536
#define DD 64
#define dH 32
#define HH 512
#define LL 8
#define KK 10

// ---------------------------------------------------------------------------
// Static device scratch
// ---------------------------------------------------------------------------
__device__ __align__(16) float g_X[2][NROWS_MAX * DD];
__device__ float g_det[NROWS_MAX];
__device__ float g_part[512 * 128];
__device__ __align__(16) float g_mu[DD];
__device__ __align__(16) float g_rstd[DD];

// pre-split bf16 buffers (hi / lo)
#define WTOT 4718592
#define OFF_SW0 0
#define OFF_TW0 131072
#define OFF_SW1 262144
#define OFF_TW1 2359296
#define OFF_SW2 4456448
#define OFF_TW2 4587520
__device__ __align__(16) unsigned short g_Wh[WTOT];
__device__ __align__(16) unsigned short g_Wl[WTOT];
__device__ __align__(16) unsigned short g_XAh[NROWS_MAX * dH];
__device__ __align__(16) unsigned short g_XAl[NROWS_MAX * dH];
__device__ __align__(16) unsigned short g_H0h[2 * NROWS_MAX * HH];
__device__ __align__(16) unsigned short g_H0l[2 * NROWS_MAX * HH];
__device__ __align__(16) unsigned short g_H1h[2 * NROWS_MAX * HH];
__device__ __align__(16) unsigned short g_H1l[2 * NROWS_MAX * HH];

// ---------------------------------------------------------------------------
// portable PTX helpers
// ---------------------------------------------------------------------------
__device__ __forceinline__ uint32_t smem_u32(const void* p) {
    uint32_t a;
    asm("{ .reg .u64 t; cvta.to.shared.u64 t, %1; cvt.u32.u64 %0, t; }"
        : "=r"(a) : "l"(p));
    return a;
}
__device__ __forceinline__ void mma_bf16(float* c, const uint32_t* a,
                                         const uint32_t* b) {
    asm volatile(
        "mma.sync.aligned.m16n8k16.row.col.f32.bf16.bf16.f32 "
        "{%0,%1,%2,%3}, {%4,%5,%6,%7}, {%8,%9}, {%0,%1,%2,%3};"
        : "+f"(c[0]), "+f"(c[1]), "+f"(c[2]), "+f"(c[3])
        : "r"(a[0]), "r"(a[1]), "r"(a[2]), "r"(a[3]), "r"(b[0]), "r"(b[1]));
}
__device__ __forceinline__ void ldsm4(uint32_t* r, uint32_t addr) {
    asm volatile(
        "ldmatrix.sync.aligned.m8n8.x4.shared.b16 {%0,%1,%2,%3}, [%4];"
        : "=r"(r[0]), "=r"(r[1]), "=r"(r[2]), "=r"(r[3]) : "r"(addr));
}
__device__ __forceinline__ void ldsm2(uint32_t* r, uint32_t addr) {
    asm volatile(
        "ldmatrix.sync.aligned.m8n8.x2.shared.b16 {%0,%1}, [%2];"
        : "=r"(r[0]), "=r"(r[1]) : "r"(addr));
}
__device__ __forceinline__ uint32_t packbf(float v1, float v0) {
    uint32_t r;
    asm("cvt.rn.bf16x2.f32 %0, %1, %2;" : "=r"(r) : "f"(v1), "f"(v0));
    return r;
}
__device__ __forceinline__ void spl2(float v0, float v1, uint32_t& h,
                                     uint32_t& l) {
    h = packbf(v1, v0);
    float h0 = __uint_as_float(h << 16);
    float h1 = __uint_as_float(h & 0xffff0000u);
    l = packbf(v1 - h1, v0 - h0);
}
#define CP16(dst, src)                                                        \
    asm volatile("cp.async.ca.shared.global [%0], [%1], 16;" ::"r"(           \
                     (uint32_t)(dst)),                                        \
                 "l"(src))
#define CP_COMMIT() asm volatile("cp.async.commit_group;" ::: "memory")
#define CP_WAIT1() asm volatile("cp.async.wait_group 1;" ::: "memory")
#define CP_WAIT0() asm volatile("cp.async.wait_group 0;" ::: "memory")

// ---------------------------------------------------------------------------
// small kernels
// ---------------------------------------------------------------------------
__global__ void copy_in_kernel(const float* __restrict__ x,
                               float* __restrict__ X, int N) {
    int idx = blockIdx.x * 256 + threadIdx.x;
    if (idx < N * DD) {
        int i = idx >> 6;
        int j = idx & 63;
        X[idx] = x[(size_t)i * (DD + 1) + j];
    }
}

// generic fp32 -> (bf16 hi, bf16 lo) split over n2 pairs
__global__ void wsplit_kernel(const float* __restrict__ src,
                              unsigned short* __restrict__ dh,
                              unsigned short* __restrict__ dl, int n2) {
    int i = blockIdx.x * 256 + threadIdx.x;
    if (i < n2) {
        float2 v = ((const float2*)src)[i];
        uint32_t h, l;
        spl2(v.x, v.y, h, l);
        ((uint32_t*)dh)[i] = h;
        ((uint32_t*)dl)[i] = l;
    }
}

// normalized x1 slice -> pre-split XA (N x 32 bf16 hi/lo)
__global__ void norm_kernel(const float* __restrict__ X,
                            unsigned short* __restrict__ XAh,
                            unsigned short* __restrict__ XAl,
                            const float* __restrict__ mu,
                            const float* __restrict__ rstd, int x1off, int N) {
    int idx = blockIdx.x * 256 + threadIdx.x;
    if (idx < N * 8) {
        int i = idx >> 3;
        int j4 = (idx & 7) << 2;
        float4 v = *(const float4*)(X + (size_t)i * DD + x1off + j4);
        float4 m = *(const float4*)(mu + x1off + j4);
        float4 s = *(const float4*)(rstd + x1off + j4);
        v.x = (v.x - m.x) * s.x;
        v.y = (v.y - m.y) * s.y;
        v.z = (v.z - m.z) * s.z;
        v.w = (v.w - m.w) * s.w;
        uint32_t h0, l0, h1, l1;
        spl2(v.x, v.y, h0, l0);
        spl2(v.z, v.w, h1, l1);
        int u = ((size_t)i * dH + j4) >> 1;
        *(uint2*)((uint32_t*)XAh + u) = make_uint2(h0, h1);
        *(uint2*)((uint32_t*)XAl + u) = make_uint2(l0, l1);
    }
}

__global__ __launch_bounds__(256) void stats1_kernel(
    const float* __restrict__ X, float* __restrict__ part, int rowsPerBlock) {
    int tid = threadIdx.x;
    int c = tid & 63;
    int rg = tid >> 6;
    size_t base = (size_t)blockIdx.x * rowsPerBlock;
    float s = 0.f, q = 0.f;
    for (int r = rg; r < rowsPerBlock; r += 4) {
        float v = X[(base + r) * DD + c];
        s += v;
        q += v * v;
    }
    __shared__ float ss[256], sq[256];
    ss[tid] = s;
    sq[tid] = q;
    __syncthreads();
    if (tid < 64) {
        float S = ss[tid] + ss[tid + 64] + ss[tid + 128] + ss[tid + 192];
        float Q = sq[tid] + sq[tid + 64] + sq[tid + 128] + sq[tid + 192];
        part[blockIdx.x * 128 + tid] = S;
        part[blockIdx.x * 128 + 64 + tid] = Q;
    }
}

__global__ void stats2_kernel(const float* __restrict__ part, int nb,
                              float invN, float* __restrict__ muArr,
                              float* __restrict__ rstdArr) {
    int c = threadIdx.x;
    float s = 0.f, q = 0.f;
    for (int b = 0; b < nb; b++) {
        s += part[b * 128 + c];
        q += part[b * 128 + 64 + c];
    }
    float m = s * invN;
    float var = q * invN - m * m;
    muArr[c] = m;
    rstdArr[c] = rsqrtf(var + 1e-5f);
}

// ---------------------------------------------------------------------------
// bf16x3 GEMM, pre-split inputs: C(hi,lo) = split(relu(A @ W^T + b))
// BM=128, BN=128, BK=16, 256 thr (8 warps 2m x 4n). Mainloop: 4 cp.async
// (16B) + 16 LDSM + 48 MMA per warp-chunk. 3-stage cp.async pipeline.
// smem: 3 stages x 4 tiles x 6144 B = 73728 B. Tile row pitch 48 B.
// ---------------------------------------------------------------------------
#define TILB 6144
#define STGB (4 * TILB)
#define SMEMG (3 * STGB)

template <int KDIM>
__global__ __launch_bounds__(256, 2) void mma_gemm_kernel(
    const unsigned short* __restrict__ Ah0,
    const unsigned short* __restrict__ Al0,
    const unsigned short* __restrict__ Ah1,
    const unsigned short* __restrict__ Al1, int lda,
    const unsigned short* __restrict__ Wh0,
    const unsigned short* __restrict__ Wl0,
    const unsigned short* __restrict__ Wh1,
    const unsigned short* __restrict__ Wl1, const float* __restrict__ b0,
    const float* __restrict__ b1, unsigned short* __restrict__ Ch0,
    unsigned short* __restrict__ Cl0, unsigned short* __restrict__ Ch1,
    unsigned short* __restrict__ Cl1) {
    extern __shared__ uint32_t smu[];
    const int z = blockIdx.z;
    const unsigned short* Ah = z ? Ah1 : Ah0;
    const unsigned short* Al = z ? Al1 : Al0;
    const unsigned short* Wh = z ? Wh1 : Wh0;
    const unsigned short* Wl = z ? Wl1 : Wl0;
    const float* bias = z ? b1 : b0;
    unsigned short* Ch = z ? Ch1 : Ch0;
    unsigned short* Cl = z ? Cl1 : Cl0;

    const int tid = threadIdx.x;
    const int wid = tid >> 5, lane = tid & 31;
    const int wm = wid & 1, wn = wid >> 1;
    const size_t row0 = (size_t)blockIdx.y * 128;
    const int col0 = blockIdx.x * 128;
    const uint32_t smb = smem_u32(smu);

    constexpr int NCH = KDIM / 16;
    const int cr = tid >> 1;   // 0..127 row
    const int ch = tid & 1;    // 16B half

    const int rowSel = (lane & 7) | (((lane >> 3) & 1) << 3);
    const int kSelA = (lane >> 4) * 16;
    const int lrb = lane & 15;
    const uint32_t aoff = (uint32_t)((wm * 64 + rowSel) * 48 + kSelA);
    const uint32_t boff =
        (uint32_t)((wn * 32 + (lrb & 7)) * 48 + (lrb >> 3) * 16);

    auto issue = [&](int i) {
        const uint32_t base = smb + (i % 3) * STGB;
        const int k0 = i * 16;
        const uint32_t d = cr * 48 + ch * 16;
        const size_t asrc = (row0 + cr) * (size_t)lda + k0 + ch * 8;
        const size_t bsrc = (size_t)(col0 + cr) * KDIM + k0 + ch * 8;
        CP16(base + d, Ah + asrc);
        CP16(base + TILB + d, Al + asrc);
        CP16(base + 2 * TILB + d, Wh + bsrc);
        CP16(base + 3 * TILB + d, Wl + bsrc);
        CP_COMMIT();
    };

    float acc[4][4][4];
#pragma unroll
    for (int mt = 0; mt < 4; mt++)
#pragma unroll
        for (int nt = 0; nt < 4; nt++)
#pragma unroll
            for (int e = 0; e < 4; e++) acc[mt][nt][e] = 0.f;

    issue(0);
    if (NCH > 1) issue(1);

    for (int i = 0; i < NCH; ++i) {
        if (i == NCH - 1) { CP_WAIT0(); } else { CP_WAIT1(); }
        __syncthreads();
        const uint32_t AhB = smb + (i % 3) * STGB;
        const uint32_t AlB = AhB + TILB;
        const uint32_t BhB = AhB + 2 * TILB;
        const uint32_t BlB = AhB + 3 * TILB;

        uint32_t ah[4][4], al[4][4];
#pragma unroll
        for (int mt = 0; mt < 4; mt++) {
            ldsm4(ah[mt], AhB + aoff + mt * 16 * 48);
            ldsm4(al[mt], AlB + aoff + mt * 16 * 48);
        }
#pragma unroll
        for (int nt = 0; nt < 4; nt++) {
            uint32_t bh[2], bl[2];
            ldsm2(bh, BhB + boff + nt * 8 * 48);
            ldsm2(bl, BlB + boff + nt * 8 * 48);
#pragma unroll
            for (int mt = 0; mt < 4; mt++) {
                mma_bf16(acc[mt][nt], ah[mt], bh);
                mma_bf16(acc[mt][nt], ah[mt], bl);
                mma_bf16(acc[mt][nt], al[mt], bh);
            }
        }
        if (i + 2 < NCH) issue(i + 2);
    }

    // epilogue: bias + relu + split -> direct u32 stores into Ch/Cl
    float bv[4][2];
#pragma unroll
    for (int nt = 0; nt < 4; nt++) {
        int c = col0 + wn * 32 + nt * 8 + ((lane & 3) << 1);
        bv[nt][0] = __ldg(bias + c);
        bv[nt][1] = __ldg(bias + c + 1);
    }
    uint32_t* Chu = (uint32_t*)Ch;
    uint32_t* Clu = (uint32_t*)Cl;
#pragma unroll
    for (int mt = 0; mt < 4; mt++) {
        size_t r0 = row0 + wm * 64 + mt * 16 + (lane >> 2);
#pragma unroll
        for (int nt = 0; nt < 4; nt++) {
            int cc = col0 + wn * 32 + nt * 8 + ((lane & 3) << 1);
            float v0 = fmaxf(acc[mt][nt][0] + bv[nt][0], 0.f);
            float v1 = fmaxf(acc[mt][nt][1] + bv[nt][1], 0.f);
            uint32_t h, l;
            spl2(v0, v1, h, l);
            size_t u = (r0 * HH + cc) >> 1;
            Chu[u] = h;
            Clu[u] = l;
            v0 = fmaxf(acc[mt][nt][2] + bv[nt][0], 0.f);
            v1 = fmaxf(acc[mt][nt][3] + bv[nt][1], 0.f);
            spl2(v0, v1, h, l);
            u = ((r0 + 8) * HH + cc) >> 1;
            Chu[u] = h;
            Clu[u] = l;
        }
    }
}

// ---------------------------------------------------------------------------
// bf16x3 GEMM3 + fused coupling + fused next-layer batchnorm partials.
// BM=128, N=64 (s||t), K=512. Pre-split A (H1 h/l) and B (W2 h/l).
// stage: 4 A tiles (6144 B) + 4 B tiles (1536 B) = 30720 B; 3 stages.
// ---------------------------------------------------------------------------
#define BTB 1536
#define STG3B (4 * TILB + 4 * BTB)
#define SMEM3 (3 * STG3B)  // 92160 B

__global__ __launch_bounds__(256, 1) void mma_gemm3_kernel(
    const unsigned short* __restrict__ H1sh,
    const unsigned short* __restrict__ H1sl,
    const unsigned short* __restrict__ H1th,
    const unsigned short* __restrict__ H1tl,
    const unsigned short* __restrict__ W2sh,
    const unsigned short* __restrict__ W2sl,
    const unsigned short* __restrict__ W2th,
    const unsigned short* __restrict__ W2tl, const float* __restrict__ b2s,
    const float* __restrict__ b2t, const float* __restrict__ X,
    float* __restrict__ Xn, const float* __restrict__ mu,
    const float* __restrict__ rstd, float* __restrict__ det,
    float* __restrict__ part, int x1off, int first) {
    extern __shared__ uint32_t smu[];
    const int tid = threadIdx.x;
    const int wid = tid >> 5, lane = tid & 31;
    const int wm = wid & 3, wn = wid >> 2;
    const size_t row0 = (size_t)blockIdx.x * 128;
    const uint32_t smb = smem_u32(smu);

    const int cr = tid >> 1;
    const int ch = tid & 1;
    const int bt = tid >> 6;            // 0..3: sh, sl, th, tl
    const int brow = (tid & 63) >> 1;   // 0..31
    const int bh2 = tid & 1;
    const unsigned short* bsrc =
        (bt == 0) ? W2sh : (bt == 1) ? W2sl : (bt == 2) ? W2th : W2tl;

    const int rowSel = (lane & 7) | (((lane >> 3) & 1) << 3);
    const int kSelA = (lane >> 4) * 16;
    const int lrb = lane & 15;
    const uint32_t aoff = (uint32_t)((wm * 32 + rowSel) * 48 + kSelA);
    const uint32_t boff = (uint32_t)(((lrb & 7)) * 48 + (lrb >> 3) * 16);

    auto issue = [&](int i) {
        const uint32_t base = smb + (i % 3) * STG3B;
        const int k0 = i * 16;
        const uint32_t d = cr * 48 + ch * 16;
        const size_t asrc = (row0 + cr) * (size_t)HH + k0 + ch * 8;
        CP16(base + d, H1sh + asrc);
        CP16(base + TILB + d, H1sl + asrc);
        CP16(base + 2 * TILB + d, H1th + asrc);
        CP16(base + 3 * TILB + d, H1tl + asrc);
        CP16(base + 4 * TILB + bt * BTB + brow * 48 + bh2 * 16,
             bsrc + (size_t)brow * HH + k0 + bh2 * 8);
        CP_COMMIT();
    };

    float acc[2][4][4];
#pragma unroll
    for (int mt = 0; mt < 2; mt++)
#pragma unroll
        for (int nt = 0; nt < 4; nt++)
#pragma unroll
            for (int e = 0; e < 4; e++) acc[mt][nt][e] = 0.f;

    issue(0);
    issue(1);

    for (int i = 0; i < 32; ++i) {
        if (i == 31) { CP_WAIT0(); } else { CP_WAIT1(); }
        __syncthreads();
        const uint32_t base = smb + (i % 3) * STG3B;
        const uint32_t AHB = base + (wn ? 2 * TILB : 0);
        const uint32_t ALB = AHB + TILB;
        const uint32_t BHB = base + 4 * TILB + (wn ? 2 * BTB : 0);
        const uint32_t BLB = BHB + BTB;

        uint32_t ah[2][4], al[2][4];
#pragma unroll
        for (int mt = 0; mt < 2; mt++) {
            ldsm4(ah[mt], AHB + aoff + mt * 16 * 48);
            ldsm4(al[mt], ALB + aoff + mt * 16 * 48);
        }
#pragma unroll
        for (int nt = 0; nt < 4; nt++) {
            uint32_t bh[2], bl[2];
            ldsm2(bh, BHB + boff + nt * 8 * 48);
            ldsm2(bl, BLB + boff + nt * 8 * 48);
#pragma unroll
            for (int mt = 0; mt < 2; mt++) {
                mma_bf16(acc[mt][nt], ah[mt], bh);
                mma_bf16(acc[mt][nt], ah[mt], bl);
                mma_bf16(acc[mt][nt], al[mt], bh);
            }
        }
        if (i + 2 < 32) issue(i + 2);
    }
    __syncthreads();

    float* Cs = (float*)smu;  // [128][66]
    {
        const float* bp = wn ? b2t : b2s;
#pragma unroll
        for (int mt = 0; mt < 2; mt++) {
            int r = wm * 32 + mt * 16 + (lane >> 2);
#pragma unroll
            for (int nt = 0; nt < 4; nt++) {
                int ccl = nt * 8 + ((lane & 3) << 1);
                int cg = wn * 32 + ccl;
                float bv0 = __ldg(bp + ccl), bv1 = __ldg(bp + ccl + 1);
                Cs[r * 66 + cg] = acc[mt][nt][0] + bv0;
                Cs[r * 66 + cg + 1] = acc[mt][nt][1] + bv1;
                Cs[(r + 8) * 66 + cg] = acc[mt][nt][2] + bv0;
                Cs[(r + 8) * 66 + cg + 1] = acc[mt][nt][3] + bv1;
            }
        }
    }
    __syncthreads();

    if (tid < 128) {
        int r = tid;
        size_t grow = row0 + r;
        const float* xr = X + grow * DD;
        float* xo = Xn + grow * DD;
        int x2off = dH - x1off;
        float ssum = 0.f;
#pragma unroll 8
        for (int j = 0; j < dH; j++) {
            float s = Cs[r * 66 + j];
            float t = Cs[r * 66 + 32 + j];
            float x1 = xr[x1off + j];
            float x2 = xr[x2off + j];
            float x1n = (x1 - mu[x1off + j]) * rstd[x1off + j];
            float x2n = (x2 - mu[x2off + j]) * rstd[x2off + j];
            float y2 = x2n * expf(s) + t;
            xo[j] = x1n;
            xo[dH + j] = y2;
            Cs[r * 66 + j] = x1n;
            Cs[r * 66 + 32 + j] = y2;
            ssum += s;
        }
        det[grow] = first ? ssum : (det[grow] + ssum);
    }
    __syncthreads();

    float* red = (float*)smu + 128 * 66;
    if (tid < 128) {
        int c = tid & 63;
        int half = tid >> 6;
        float s = 0.f, q = 0.f;
        int rbeg = half * 64;
#pragma unroll 4
        for (int r = rbeg; r < rbeg + 64; ++r) {
            float v = Cs[r * 66 + c];
            s += v;
            q += v * v;
        }
        red[tid] = s;
        red[128 + tid] = q;
    }
    __syncthreads();
    if (tid < 64) {
        part[blockIdx.x * 128 + tid] = red[tid] + red[64 + tid];
        part[blockIdx.x * 128 + 64 + tid] =
            red[128 + tid] + red[128 + 64 + tid];
    }
}

// ---------------------------------------------------------------------------
// GMM log-likelihood + output assembly + final reduce (unchanged, proven)
// ---------------------------------------------------------------------------
__global__ __launch_bounds__(256) void gmm_kernel(
    const float* __restrict__ X, const float* __restrict__ means,
    const float* __restrict__ det, float* __restrict__ out, int N, int full) {
    __shared__ float smm[KK * DD];
    int tid = threadIdx.x;
    for (int i = tid; i < KK * DD; i += 256) smm[i] = means[i];
    __syncthreads();

    size_t i = (size_t)blockIdx.x * 256 + tid;
    float4 y4[16];
    const float4* xr = (const float4*)(X + i * DD);
#pragma unroll
    for (int q = 0; q < 16; q++) y4[q] = xr[q];
    float4* yo = (float4*)(out + i * DD);
#pragma unroll
    for (int q = 0; q < 16; q++) yo[q] = y4[q];

    if (!full) return;

    const float CD = (float)(64.0 * 1.8378770664093453);
    float lp[KK];
    float mx = -1e30f;
#pragma unroll
    for (int k = 0; k < KK; k++) {
        const float* mrow = smm + k * DD;
        float accv = 0.f;
#pragma unroll
        for (int q = 0; q < 16; q++) {
            float4 m4 = *(const float4*)(mrow + q * 4);
            float dx = y4[q].x - m4.x;
            accv += dx * dx;
            dx = y4[q].y - m4.y;
            accv += dx * dx;
            dx = y4[q].z - m4.z;
            accv += dx * dx;
            dx = y4[q].w - m4.w;
            accv += dx * dx;
        }
        float v = -0.5f * (accv + CD);
        lp[k] = v;
        mx = fmaxf(mx, v);
    }
    float se = 0.f;
#pragma unroll
    for (int k = 0; k < KK; k++) se += expf(lp[k] - mx);
    float ll = mx + logf(se) - logf((float)KK);

    size_t oll = (size_t)N * DD + 1;
    out[oll + i] = ll;
    out[oll + N + i] = det[i];
}

__global__ void final_reduce_kernel(float* __restrict__ out, int N) {
    int tid = threadIdx.x;
    size_t oll = (size_t)N * DD + 1;
    size_t odet = oll + N;
    float sll = 0.f, sdet = 0.f;
    for (int i = tid; i < N; i += 1024) {
        sll += out[oll + i];
        sdet += out[odet + i];
    }
    __shared__ float a[1024], b[1024];
    a[tid] = sll;
    b[tid] = sdet;
    __syncthreads();
    for (int s = 512; s > 0; s >>= 1) {
        if (tid < s) {
            a[tid] += a[tid + s];
            b[tid] += b[tid + s];
        }
        __syncthreads();
    }
    if (tid == 0) {
        float llm = a[0] / (float)N;
        float dm = b[0] / (float)N;
        out[(size_t)N * DD] = -(dm + llm);
        out[odet + N] = llm;
        out[odet + N + 1] = dm;
    }
}

// ---------------------------------------------------------------------------
// Host launcher
// ---------------------------------------------------------------------------
static void* symaddr_v(const void* s) {
    void* p = nullptr;
    cudaGetSymbolAddress(&p, s);
    return p;
}

extern "C" void kernel_launch(void* const* d_in, const int* in_sizes, int n_in,
                              void* d_out, int out_size) {
    const float* x = (const float*)d_in[0];
    const float* sW0 = (const float*)d_in[1];
    const float* sb0 = (const float*)d_in[2];
    const float* sW1 = (const float*)d_in[3];
    const float* sb1 = (const float*)d_in[4];
    const float* sW2 = (const float*)d_in[5];
    const float* sb2 = (const float*)d_in[6];
    const float* tW0 = (const float*)d_in[7];
    const float* tb0 = (const float*)d_in[8];
    const float* tW1 = (const float*)d_in[9];
    const float* tb1 = (const float*)d_in[10];
    const float* tW2 = (const float*)d_in[11];
    const float* tb2 = (const float*)d_in[12];
    const float* means = (const float*)d_in[13];
    float* out = (float*)d_out;

    const int N = in_sizes[0] / (DD + 1);
    const int full = (out_size >= (long long)N * DD + 2 * N + 3) ? 1 : 0;

    cudaFuncSetAttribute(mma_gemm_kernel<dH>,
                         cudaFuncAttributeMaxDynamicSharedMemorySize, SMEMG);
    cudaFuncSetAttribute(mma_gemm_kernel<HH>,
                         cudaFuncAttributeMaxDynamicSharedMemorySize, SMEMG);
    cudaFuncSetAttribute(mma_gemm3_kernel,
                         cudaFuncAttributeMaxDynamicSharedMemorySize, SMEM3);

    float* X = (float*)symaddr_v(g_X);
    float* det = (float*)symaddr_v(g_det);
    float* part = (float*)symaddr_v(g_part);
    float* mu = (float*)symaddr_v(g_mu);
    float* rstd = (float*)symaddr_v(g_rstd);
    unsigned short* Wh = (unsigned short*)symaddr_v(g_Wh);
    unsigned short* Wl = (unsigned short*)symaddr_v(g_Wl);
    unsigned short* XAh = (unsigned short*)symaddr_v(g_XAh);
    unsigned short* XAl = (unsigned short*)symaddr_v(g_XAl);
    unsigned short* H0h = (unsigned short*)symaddr_v(g_H0h);
    unsigned short* H0l = (unsigned short*)symaddr_v(g_H0l);
    unsigned short* H1h = (unsigned short*)symaddr_v(g_H1h);
    unsigned short* H1l = (unsigned short*)symaddr_v(g_H1l);

    const size_t XS = (size_t)N * DD;
    const size_t HS = (size_t)N * HH;

    copy_in_kernel<<<(N * DD + 255) / 256, 256>>>(x, X, N);

    // one-time weight splits (cheap; reused by 512 row-blocks x 8 layers)
    wsplit_kernel<<<(65536 + 255) / 256, 256>>>(sW0, Wh + OFF_SW0,
                                                Wl + OFF_SW0, 65536);
    wsplit_kernel<<<(65536 + 255) / 256, 256>>>(tW0, Wh + OFF_TW0,
                                                Wl + OFF_TW0, 65536);
    wsplit_kernel<<<(1048576 + 255) / 256, 256>>>(sW1, Wh + OFF_SW1,
                                                  Wl + OFF_SW1, 1048576);
    wsplit_kernel<<<(1048576 + 255) / 256, 256>>>(tW1, Wh + OFF_TW1,
                                                  Wl + OFF_TW1, 1048576);
    wsplit_kernel<<<(65536 + 255) / 256, 256>>>(sW2, Wh + OFF_SW2,
                                                Wl + OFF_SW2, 65536);
    wsplit_kernel<<<(65536 + 255) / 256, 256>>>(tW2, Wh + OFF_TW2,
                                                Wl + OFF_TW2, 65536);

    int cur = 0;
    for (int l = 0; l < LL; l++) {
        float* Xc = X + (size_t)cur * XS;
        float* Xnext = X + (size_t)(cur ^ 1) * XS;

        if (l == 0) {
            stats1_kernel<<<256, 256>>>(Xc, part, N / 256);
            stats2_kernel<<<1, 64>>>(part, 256, 1.0f / (float)N, mu, rstd);
        } else {
            stats2_kernel<<<1, 64>>>(part, N / 128, 1.0f / (float)N, mu, rstd);
        }

        const int x1off = (l & 1) ? dH : 0;

        norm_kernel<<<(N * 8 + 255) / 256, 256>>>(Xc, XAh, XAl, mu, rstd,
                                                  x1off, N);

        // GEMM1: (N x 32) -> (N x 512), relu, pre-split output
        mma_gemm_kernel<dH><<<dim3(HH / 128, N / 128, 2), 256, SMEMG>>>(
            XAh, XAl, XAh, XAl, dH,
            Wh + OFF_SW0 + (size_t)l * HH * dH, Wl + OFF_SW0 + (size_t)l * HH * dH,
            Wh + OFF_TW0 + (size_t)l * HH * dH, Wl + OFF_TW0 + (size_t)l * HH * dH,
            sb0 + (size_t)l * HH, tb0 + (size_t)l * HH,
            H0h, H0l, H0h + HS, H0l + HS);

        // GEMM2: (N x 512) -> (N x 512), relu, pre-split output
        mma_gemm_kernel<HH><<<dim3(HH / 128, N / 128, 2), 256, SMEMG>>>(
            H0h, H0l, H0h + HS, H0l + HS, HH,
            Wh + OFF_SW1 + (size_t)l * HH * HH, Wl + OFF_SW1 + (size_t)l * HH * HH,
            Wh + OFF_TW1 + (size_t)l * HH * HH, Wl + OFF_TW1 + (size_t)l * HH * HH,
            sb1 + (size_t)l * HH, tb1 + (size_t)l * HH,
            H1h, H1l, H1h + HS, H1l + HS);

        // GEMM3 (s||t) + coupling + fused stats partials
        mma_gemm3_kernel<<<N / 128, 256, SMEM3>>>(
            H1h, H1l, H1h + HS, H1l + HS,
            Wh + OFF_SW2 + (size_t)l * dH * HH, Wl + OFF_SW2 + (size_t)l * dH * HH,
            Wh + OFF_TW2 + (size_t)l * dH * HH, Wl + OFF_TW2 + (size_t)l * dH * HH,
            sb2 + (size_t)l * dH, tb2 + (size_t)l * dH, Xc, Xnext, mu, rstd,
            det, part, x1off, (l == 0) ? 1 : 0);

        cur ^= 1;
    }

    gmm_kernel<<<N / 256, 256>>>(X + (size_t)cur * XS, means, det, out, N,
                                 full);
    if (full) final_reduce_kernel<<<1, 1024>>>(out, N);
}

// round 13
// speedup vs baseline: 2.2192x; 1.0584x over previous
#include <cuda_runtime.h>
#include <math.h>
#include <stdint.h>

#define NROWS_MAX 65536
#define DD 64
#define dH 32
#define HH 512
#define LL 8
#define KK 10

// ---------------------------------------------------------------------------
// Static device scratch
// ---------------------------------------------------------------------------
__device__ __align__(16) float g_X[2][NROWS_MAX * DD];
__device__ float g_det[NROWS_MAX];
__device__ float g_part[512 * 128];
__device__ __align__(16) float g_mu[DD];
__device__ __align__(16) float g_rstd[DD];

// pre-split bf16 buffers (hi / lo)
#define WTOT 4718592
#define OFF_SW0 0
#define OFF_TW0 131072
#define OFF_SW1 262144
#define OFF_TW1 2359296
#define OFF_SW2 4456448
#define OFF_TW2 4587520
__device__ __align__(16) unsigned short g_Wh[WTOT];
__device__ __align__(16) unsigned short g_Wl[WTOT];
__device__ __align__(16) unsigned short g_XAh[NROWS_MAX * dH];
__device__ __align__(16) unsigned short g_XAl[NROWS_MAX * dH];
__device__ __align__(16) unsigned short g_H0h[2 * NROWS_MAX * HH];
__device__ __align__(16) unsigned short g_H0l[2 * NROWS_MAX * HH];
__device__ __align__(16) unsigned short g_H1h[2 * NROWS_MAX * HH];
__device__ __align__(16) unsigned short g_H1l[2 * NROWS_MAX * HH];

// ---------------------------------------------------------------------------
// portable PTX helpers
// ---------------------------------------------------------------------------
__device__ __forceinline__ uint32_t smem_u32(const void* p) {
    uint32_t a;
    asm("{ .reg .u64 t; cvta.to.shared.u64 t, %1; cvt.u32.u64 %0, t; }"
        : "=r"(a) : "l"(p));
    return a;
}
__device__ __forceinline__ void mma_bf16(float* c, const uint32_t* a,
                                         const uint32_t* b) {
    asm volatile(
        "mma.sync.aligned.m16n8k16.row.col.f32.bf16.bf16.f32 "
        "{%0,%1,%2,%3}, {%4,%5,%6,%7}, {%8,%9}, {%0,%1,%2,%3};"
        : "+f"(c[0]), "+f"(c[1]), "+f"(c[2]), "+f"(c[3])
        : "r"(a[0]), "r"(a[1]), "r"(a[2]), "r"(a[3]), "r"(b[0]), "r"(b[1]));
}
__device__ __forceinline__ void ldsm4(uint32_t* r, uint32_t addr) {
    asm volatile(
        "ldmatrix.sync.aligned.m8n8.x4.shared.b16 {%0,%1,%2,%3}, [%4];"
        : "=r"(r[0]), "=r"(r[1]), "=r"(r[2]), "=r"(r[3]) : "r"(addr));
}
__device__ __forceinline__ void ldsm2(uint32_t* r, uint32_t addr) {
    asm volatile(
        "ldmatrix.sync.aligned.m8n8.x2.shared.b16 {%0,%1}, [%2];"
        : "=r"(r[0]), "=r"(r[1]) : "r"(addr));
}
__device__ __forceinline__ uint32_t packbf(float v1, float v0) {
    uint32_t r;
    asm("cvt.rn.bf16x2.f32 %0, %1, %2;" : "=r"(r) : "f"(v1), "f"(v0));
    return r;
}
__device__ __forceinline__ void spl2(float v0, float v1, uint32_t& h,
                                     uint32_t& l) {
    h = packbf(v1, v0);
    float h0 = __uint_as_float(h << 16);
    float h1 = __uint_as_float(h & 0xffff0000u);
    l = packbf(v1 - h1, v0 - h0);
}
#define CP16(dst, src)                                                        \
    asm volatile("cp.async.ca.shared.global [%0], [%1], 16;" ::"r"(           \
                     (uint32_t)(dst)),                                        \
                 "l"(src))
#define CP_COMMIT() asm volatile("cp.async.commit_group;" ::: "memory")
#define CP_WAIT0() asm volatile("cp.async.wait_group 0;" ::: "memory")

// ---------------------------------------------------------------------------
// small kernels
// ---------------------------------------------------------------------------
__global__ void copy_in_kernel(const float* __restrict__ x,
                               float* __restrict__ X, int N) {
    int idx = blockIdx.x * 256 + threadIdx.x;
    if (idx < N * DD) {
        int i = idx >> 6;
        int j = idx & 63;
        X[idx] = x[(size_t)i * (DD + 1) + j];
    }
}

__global__ void wsplit_kernel(const float* __restrict__ src,
                              unsigned short* __restrict__ dh,
                              unsigned short* __restrict__ dl, int n2) {
    int i = blockIdx.x * 256 + threadIdx.x;
    if (i < n2) {
        float2 v = ((const float2*)src)[i];
        uint32_t h, l;
        spl2(v.x, v.y, h, l);
        ((uint32_t*)dh)[i] = h;
        ((uint32_t*)dl)[i] = l;
    }
}

__global__ void norm_kernel(const float* __restrict__ X,
                            unsigned short* __restrict__ XAh,
                            unsigned short* __restrict__ XAl,
                            const float* __restrict__ mu,
                            const float* __restrict__ rstd, int x1off, int N) {
    int idx = blockIdx.x * 256 + threadIdx.x;
    if (idx < N * 8) {
        int i = idx >> 3;
        int j4 = (idx & 7) << 2;
        float4 v = *(const float4*)(X + (size_t)i * DD + x1off + j4);
        float4 m = *(const float4*)(mu + x1off + j4);
        float4 s = *(const float4*)(rstd + x1off + j4);
        v.x = (v.x - m.x) * s.x;
        v.y = (v.y - m.y) * s.y;
        v.z = (v.z - m.z) * s.z;
        v.w = (v.w - m.w) * s.w;
        uint32_t h0, l0, h1, l1;
        spl2(v.x, v.y, h0, l0);
        spl2(v.z, v.w, h1, l1);
        int u = ((size_t)i * dH + j4) >> 1;
        *(uint2*)((uint32_t*)XAh + u) = make_uint2(h0, h1);
        *(uint2*)((uint32_t*)XAl + u) = make_uint2(l0, l1);
    }
}

__global__ __launch_bounds__(256) void stats1_kernel(
    const float* __restrict__ X, float* __restrict__ part, int rowsPerBlock) {
    int tid = threadIdx.x;
    int c = tid & 63;
    int rg = tid >> 6;
    size_t base = (size_t)blockIdx.x * rowsPerBlock;
    float s = 0.f, q = 0.f;
    for (int r = rg; r < rowsPerBlock; r += 4) {
        float v = X[(base + r) * DD + c];
        s += v;
        q += v * v;
    }
    __shared__ float ss[256], sq[256];
    ss[tid] = s;
    sq[tid] = q;
    __syncthreads();
    if (tid < 64) {
        float S = ss[tid] + ss[tid + 64] + ss[tid + 128] + ss[tid + 192];
        float Q = sq[tid] + sq[tid + 64] + sq[tid + 128] + sq[tid + 192];
        part[blockIdx.x * 128 + tid] = S;
        part[blockIdx.x * 128 + 64 + tid] = Q;
    }
}

__global__ void stats2_kernel(const float* __restrict__ part, int nb,
                              float invN, float* __restrict__ muArr,
                              float* __restrict__ rstdArr) {
    int c = threadIdx.x;
    float s = 0.f, q = 0.f;
    for (int b = 0; b < nb; b++) {
        s += part[b * 128 + c];
        q += part[b * 128 + 64 + c];
    }
    float m = s * invN;
    float var = q * invN - m * m;
    muArr[c] = m;
    rstdArr[c] = rsqrtf(var + 1e-5f);
}

// ---------------------------------------------------------------------------
// bf16x3 GEMM, pre-split inputs, BK=32 stages (half the barriers).
// BM=128, BN=128, 256 thr (8 warps 2m x 4n), warp tile 64x32.
// Row pitch 80 B (32 k bf16 = 64 B data + 16 B pad) -> ldmatrix reads
// conflict-free (20-bank step), cp.async stores at the 4-wavefront minimum.
// 2-stage pipeline: wait0 -> sync -> issue(next) overlaps MMA window.
// smem: 2 stages x 4 tiles x 10240 B = 81920 B (2 CTAs/SM).
// ---------------------------------------------------------------------------
#define PCHB 80
#define TILB2 (128 * PCHB)     // 10240 B
#define STGB2 (4 * TILB2)      // 40960 B
#define SMEMG2 (2 * STGB2)     // 81920 B

template <int KDIM>
__global__ __launch_bounds__(256, 2) void mma_gemm_kernel(
    const unsigned short* __restrict__ Ah0,
    const unsigned short* __restrict__ Al0,
    const unsigned short* __restrict__ Ah1,
    const unsigned short* __restrict__ Al1, int lda,
    const unsigned short* __restrict__ Wh0,
    const unsigned short* __restrict__ Wl0,
    const unsigned short* __restrict__ Wh1,
    const unsigned short* __restrict__ Wl1, const float* __restrict__ b0,
    const float* __restrict__ b1, unsigned short* __restrict__ Ch0,
    unsigned short* __restrict__ Cl0, unsigned short* __restrict__ Ch1,
    unsigned short* __restrict__ Cl1) {
    extern __shared__ uint32_t smu[];
    const int z = blockIdx.z;
    const unsigned short* Ah = z ? Ah1 : Ah0;
    const unsigned short* Al = z ? Al1 : Al0;
    const unsigned short* Wh = z ? Wh1 : Wh0;
    const unsigned short* Wl = z ? Wl1 : Wl0;
    const float* bias = z ? b1 : b0;
    unsigned short* Ch = z ? Ch1 : Ch0;
    unsigned short* Cl = z ? Cl1 : Cl0;

    const int tid = threadIdx.x;
    const int wid = tid >> 5, lane = tid & 31;
    const int wm = wid & 1, wn = wid >> 1;
    const size_t row0 = (size_t)blockIdx.y * 128;
    const int col0 = blockIdx.x * 128;
    const uint32_t smb = smem_u32(smu);

    constexpr int NCH = KDIM / 32;

    const int rowSel = (lane & 7) | (((lane >> 3) & 1) << 3);
    const int kSelA = (lane >> 4) * 16;
    const int lrb = lane & 15;
    const uint32_t aoff = (uint32_t)((wm * 64 + rowSel) * PCHB + kSelA);
    const uint32_t boff =
        (uint32_t)((wn * 32 + (lrb & 7)) * PCHB + (lrb >> 3) * 16);

    auto issue = [&](int i) {
        const uint32_t base = smb + (i & 1) * STGB2;
        const int k0 = i * 32;
#pragma unroll
        for (int q = 0; q < 2; ++q) {
            int slot = tid + q * 256;
            int row = slot >> 2;
            int quarter = slot & 3;
            uint32_t d = row * PCHB + quarter * 16;
            size_t asrc = (row0 + row) * (size_t)lda + k0 + quarter * 8;
            size_t bsrc = (size_t)(col0 + row) * KDIM + k0 + quarter * 8;
            CP16(base + d, Ah + asrc);
            CP16(base + TILB2 + d, Al + asrc);
            CP16(base + 2 * TILB2 + d, Wh + bsrc);
            CP16(base + 3 * TILB2 + d, Wl + bsrc);
        }
        CP_COMMIT();
    };

    float acc[4][4][4];
#pragma unroll
    for (int mt = 0; mt < 4; mt++)
#pragma unroll
        for (int nt = 0; nt < 4; nt++)
#pragma unroll
            for (int e = 0; e < 4; e++) acc[mt][nt][e] = 0.f;

    issue(0);

    for (int i = 0; i < NCH; ++i) {
        CP_WAIT0();
        __syncthreads();
        if (i + 1 < NCH) issue(i + 1);
        const uint32_t AhB = smb + (i & 1) * STGB2;
        const uint32_t AlB = AhB + TILB2;
        const uint32_t BhB = AhB + 2 * TILB2;
        const uint32_t BlB = AhB + 3 * TILB2;
#pragma unroll
        for (int kh = 0; kh < 2; ++kh) {
            uint32_t ah[4][4], al[4][4];
#pragma unroll
            for (int mt = 0; mt < 4; mt++) {
                ldsm4(ah[mt], AhB + aoff + mt * 16 * PCHB + kh * 32);
                ldsm4(al[mt], AlB + aoff + mt * 16 * PCHB + kh * 32);
            }
#pragma unroll
            for (int nt = 0; nt < 4; nt++) {
                uint32_t bh[2], bl[2];
                ldsm2(bh, BhB + boff + nt * 8 * PCHB + kh * 32);
                ldsm2(bl, BlB + boff + nt * 8 * PCHB + kh * 32);
#pragma unroll
                for (int mt = 0; mt < 4; mt++) {
                    mma_bf16(acc[mt][nt], ah[mt], bh);
                    mma_bf16(acc[mt][nt], ah[mt], bl);
                    mma_bf16(acc[mt][nt], al[mt], bh);
                }
            }
        }
    }

    // epilogue: bias + relu + split -> direct u32 stores into Ch/Cl
    float bv[4][2];
#pragma unroll
    for (int nt = 0; nt < 4; nt++) {
        int c = col0 + wn * 32 + nt * 8 + ((lane & 3) << 1);
        bv[nt][0] = __ldg(bias + c);
        bv[nt][1] = __ldg(bias + c + 1);
    }
    uint32_t* Chu = (uint32_t*)Ch;
    uint32_t* Clu = (uint32_t*)Cl;
#pragma unroll
    for (int mt = 0; mt < 4; mt++) {
        size_t r0 = row0 + wm * 64 + mt * 16 + (lane >> 2);
#pragma unroll
        for (int nt = 0; nt < 4; nt++) {
            int cc = col0 + wn * 32 + nt * 8 + ((lane & 3) << 1);
            float v0 = fmaxf(acc[mt][nt][0] + bv[nt][0], 0.f);
            float v1 = fmaxf(acc[mt][nt][1] + bv[nt][1], 0.f);
            uint32_t h, l;
            spl2(v0, v1, h, l);
            size_t u = (r0 * HH + cc) >> 1;
            Chu[u] = h;
            Clu[u] = l;
            v0 = fmaxf(acc[mt][nt][2] + bv[nt][0], 0.f);
            v1 = fmaxf(acc[mt][nt][3] + bv[nt][1], 0.f);
            spl2(v0, v1, h, l);
            u = ((r0 + 8) * HH + cc) >> 1;
            Chu[u] = h;
            Clu[u] = l;
        }
    }
}

// ---------------------------------------------------------------------------
// bf16x3 GEMM3 + fused coupling + fused next-layer batchnorm partials.
// BM=128, N=64 (s||t), K=512, BK=32 stages (16 barrier windows).
// stage: 4 A tiles (10240 B) + 4 B tiles (2560 B) = 51200 B; 2 stages.
// ---------------------------------------------------------------------------
#define BTB2 (32 * PCHB)                // 2560 B
#define STG3B2 (4 * TILB2 + 4 * BTB2)   // 51200 B
#define SMEM3B (2 * STG3B2)             // 102400 B

__global__ __launch_bounds__(256, 1) void mma_gemm3_kernel(
    const unsigned short* __restrict__ H1sh,
    const unsigned short* __restrict__ H1sl,
    const unsigned short* __restrict__ H1th,
    const unsigned short* __restrict__ H1tl,
    const unsigned short* __restrict__ W2sh,
    const unsigned short* __restrict__ W2sl,
    const unsigned short* __restrict__ W2th,
    const unsigned short* __restrict__ W2tl, const float* __restrict__ b2s,
    const float* __restrict__ b2t, const float* __restrict__ X,
    float* __restrict__ Xn, const float* __restrict__ mu,
    const float* __restrict__ rstd, float* __restrict__ det,
    float* __restrict__ part, int x1off, int first) {
    extern __shared__ uint32_t smu[];
    const int tid = threadIdx.x;
    const int wid = tid >> 5, lane = tid & 31;
    const int wm = wid & 3, wn = wid >> 2;
    const size_t row0 = (size_t)blockIdx.x * 128;
    const uint32_t smb = smem_u32(smu);

    const int rowSel = (lane & 7) | (((lane >> 3) & 1) << 3);
    const int kSelA = (lane >> 4) * 16;
    const int lrb = lane & 15;
    const uint32_t aoff = (uint32_t)((wm * 32 + rowSel) * PCHB + kSelA);
    const uint32_t boff = (uint32_t)(((lrb & 7)) * PCHB + (lrb >> 3) * 16);

    auto issue = [&](int i) {
        const uint32_t base = smb + (i & 1) * STG3B2;
        const int k0 = i * 32;
#pragma unroll
        for (int q = 0; q < 2; ++q) {
            int slot = tid + q * 256;
            int row = slot >> 2;
            int quarter = slot & 3;
            uint32_t d = row * PCHB + quarter * 16;
            size_t asrc = (row0 + row) * (size_t)HH + k0 + quarter * 8;
            CP16(base + d, H1sh + asrc);
            CP16(base + TILB2 + d, H1sl + asrc);
            CP16(base + 2 * TILB2 + d, H1th + asrc);
            CP16(base + 3 * TILB2 + d, H1tl + asrc);
        }
        // B: 4 tiles x 128 16B-chunks = 512 chunks over 256 thr x 2
#pragma unroll
        for (int q = 0; q < 2; ++q) {
            int j = tid + q * 256;
            int tile = j >> 7;
            int within = j & 127;
            int row = within >> 2;
            int quarter = within & 3;
            const unsigned short* bs = (tile == 0)   ? W2sh
                                       : (tile == 1) ? W2sl
                                       : (tile == 2) ? W2th
                                                     : W2tl;
            CP16(base + 4 * TILB2 + tile * BTB2 + row * PCHB + quarter * 16,
                 bs + (size_t)row * HH + k0 + quarter * 8);
        }
        CP_COMMIT();
    };

    float acc[2][4][4];
#pragma unroll
    for (int mt = 0; mt < 2; mt++)
#pragma unroll
        for (int nt = 0; nt < 4; nt++)
#pragma unroll
            for (int e = 0; e < 4; e++) acc[mt][nt][e] = 0.f;

    issue(0);

    for (int i = 0; i < 16; ++i) {
        CP_WAIT0();
        __syncthreads();
        if (i + 1 < 16) issue(i + 1);
        const uint32_t base = smb + (i & 1) * STG3B2;
        const uint32_t AHB = base + (wn ? 2 * TILB2 : 0);
        const uint32_t ALB = AHB + TILB2;
        const uint32_t BHB = base + 4 * TILB2 + (wn ? 2 * BTB2 : 0);
        const uint32_t BLB = BHB + BTB2;
#pragma unroll
        for (int kh = 0; kh < 2; ++kh) {
            uint32_t ah[2][4], al[2][4];
#pragma unroll
            for (int mt = 0; mt < 2; mt++) {
                ldsm4(ah[mt], AHB + aoff + mt * 16 * PCHB + kh * 32);
                ldsm4(al[mt], ALB + aoff + mt * 16 * PCHB + kh * 32);
            }
#pragma unroll
            for (int nt = 0; nt < 4; nt++) {
                uint32_t bh[2], bl[2];
                ldsm2(bh, BHB + boff + nt * 8 * PCHB + kh * 32);
                ldsm2(bl, BLB + boff + nt * 8 * PCHB + kh * 32);
#pragma unroll
                for (int mt = 0; mt < 2; mt++) {
                    mma_bf16(acc[mt][nt], ah[mt], bh);
                    mma_bf16(acc[mt][nt], ah[mt], bl);
                    mma_bf16(acc[mt][nt], al[mt], bh);
                }
            }
        }
    }
    __syncthreads();

    float* Cs = (float*)smu;  // [128][66]
    {
        const float* bp = wn ? b2t : b2s;
#pragma unroll
        for (int mt = 0; mt < 2; mt++) {
            int r = wm * 32 + mt * 16 + (lane >> 2);
#pragma unroll
            for (int nt = 0; nt < 4; nt++) {
                int ccl = nt * 8 + ((lane & 3) << 1);
                int cg = wn * 32 + ccl;
                float bv0 = __ldg(bp + ccl), bv1 = __ldg(bp + ccl + 1);
                Cs[r * 66 + cg] = acc[mt][nt][0] + bv0;
                Cs[r * 66 + cg + 1] = acc[mt][nt][1] + bv1;
                Cs[(r + 8) * 66 + cg] = acc[mt][nt][2] + bv0;
                Cs[(r + 8) * 66 + cg + 1] = acc[mt][nt][3] + bv1;
            }
        }
    }
    __syncthreads();

    if (tid < 128) {
        int r = tid;
        size_t grow = row0 + r;
        const float* xr = X + grow * DD;
        float* xo = Xn + grow * DD;
        int x2off = dH - x1off;
        float ssum = 0.f;
#pragma unroll 8
        for (int j = 0; j < dH; j++) {
            float s = Cs[r * 66 + j];
            float t = Cs[r * 66 + 32 + j];
            float x1 = xr[x1off + j];
            float x2 = xr[x2off + j];
            float x1n = (x1 - mu[x1off + j]) * rstd[x1off + j];
            float x2n = (x2 - mu[x2off + j]) * rstd[x2off + j];
            float y2 = x2n * expf(s) + t;
            xo[j] = x1n;
            xo[dH + j] = y2;
            Cs[r * 66 + j] = x1n;
            Cs[r * 66 + 32 + j] = y2;
            ssum += s;
        }
        det[grow] = first ? ssum : (det[grow] + ssum);
    }
    __syncthreads();

    float* red = (float*)smu + 128 * 66;
    if (tid < 128) {
        int c = tid & 63;
        int half = tid >> 6;
        float s = 0.f, q = 0.f;
        int rbeg = half * 64;
#pragma unroll 4
        for (int r = rbeg; r < rbeg + 64; ++r) {
            float v = Cs[r * 66 + c];
            s += v;
            q += v * v;
        }
        red[tid] = s;
        red[128 + tid] = q;
    }
    __syncthreads();
    if (tid < 64) {
        part[blockIdx.x * 128 + tid] = red[tid] + red[64 + tid];
        part[blockIdx.x * 128 + 64 + tid] =
            red[128 + tid] + red[128 + 64 + tid];
    }
}

// ---------------------------------------------------------------------------
// GMM log-likelihood + output assembly + final reduce (unchanged, proven)
// ---------------------------------------------------------------------------
__global__ __launch_bounds__(256) void gmm_kernel(
    const float* __restrict__ X, const float* __restrict__ means,
    const float* __restrict__ det, float* __restrict__ out, int N, int full) {
    __shared__ float smm[KK * DD];
    int tid = threadIdx.x;
    for (int i = tid; i < KK * DD; i += 256) smm[i] = means[i];
    __syncthreads();

    size_t i = (size_t)blockIdx.x * 256 + tid;
    float4 y4[16];
    const float4* xr = (const float4*)(X + i * DD);
#pragma unroll
    for (int q = 0; q < 16; q++) y4[q] = xr[q];
    float4* yo = (float4*)(out + i * DD);
#pragma unroll
    for (int q = 0; q < 16; q++) yo[q] = y4[q];

    if (!full) return;

    const float CD = (float)(64.0 * 1.8378770664093453);
    float lp[KK];
    float mx = -1e30f;
#pragma unroll
    for (int k = 0; k < KK; k++) {
        const float* mrow = smm + k * DD;
        float accv = 0.f;
#pragma unroll
        for (int q = 0; q < 16; q++) {
            float4 m4 = *(const float4*)(mrow + q * 4);
            float dx = y4[q].x - m4.x;
            accv += dx * dx;
            dx = y4[q].y - m4.y;
            accv += dx * dx;
            dx = y4[q].z - m4.z;
            accv += dx * dx;
            dx = y4[q].w - m4.w;
            accv += dx * dx;
        }
        float v = -0.5f * (accv + CD);
        lp[k] = v;
        mx = fmaxf(mx, v);
    }
    float se = 0.f;
#pragma unroll
    for (int k = 0; k < KK; k++) se += expf(lp[k] - mx);
    float ll = mx + logf(se) - logf((float)KK);

    size_t oll = (size_t)N * DD + 1;
    out[oll + i] = ll;
    out[oll + N + i] = det[i];
}

__global__ void final_reduce_kernel(float* __restrict__ out, int N) {
    int tid = threadIdx.x;
    size_t oll = (size_t)N * DD + 1;
    size_t odet = oll + N;
    float sll = 0.f, sdet = 0.f;
    for (int i = tid; i < N; i += 1024) {
        sll += out[oll + i];
        sdet += out[odet + i];
    }
    __shared__ float a[1024], b[1024];
    a[tid] = sll;
    b[tid] = sdet;
    __syncthreads();
    for (int s = 512; s > 0; s >>= 1) {
        if (tid < s) {
            a[tid] += a[tid + s];
            b[tid] += b[tid + s];
        }
        __syncthreads();
    }
    if (tid == 0) {
        float llm = a[0] / (float)N;
        float dm = b[0] / (float)N;
        out[(size_t)N * DD] = -(dm + llm);
        out[odet + N] = llm;
        out[odet + N + 1] = dm;
    }
}

// ---------------------------------------------------------------------------
// Host launcher
// ---------------------------------------------------------------------------
static void* symaddr_v(const void* s) {
    void* p = nullptr;
    cudaGetSymbolAddress(&p, s);
    return p;
}

extern "C" void kernel_launch(void* const* d_in, const int* in_sizes, int n_in,
                              void* d_out, int out_size) {
    const float* x = (const float*)d_in[0];
    const float* sW0 = (const float*)d_in[1];
    const float* sb0 = (const float*)d_in[2];
    const float* sW1 = (const float*)d_in[3];
    const float* sb1 = (const float*)d_in[4];
    const float* sW2 = (const float*)d_in[5];
    const float* sb2 = (const float*)d_in[6];
    const float* tW0 = (const float*)d_in[7];
    const float* tb0 = (const float*)d_in[8];
    const float* tW1 = (const float*)d_in[9];
    const float* tb1 = (const float*)d_in[10];
    const float* tW2 = (const float*)d_in[11];
    const float* tb2 = (const float*)d_in[12];
    const float* means = (const float*)d_in[13];
    float* out = (float*)d_out;

    const int N = in_sizes[0] / (DD + 1);
    const int full = (out_size >= (long long)N * DD + 2 * N + 3) ? 1 : 0;

    cudaFuncSetAttribute(mma_gemm_kernel<dH>,
                         cudaFuncAttributeMaxDynamicSharedMemorySize, SMEMG2);
    cudaFuncSetAttribute(mma_gemm_kernel<HH>,
                         cudaFuncAttributeMaxDynamicSharedMemorySize, SMEMG2);
    cudaFuncSetAttribute(mma_gemm3_kernel,
                         cudaFuncAttributeMaxDynamicSharedMemorySize, SMEM3B);

    float* X = (float*)symaddr_v(g_X);
    float* det = (float*)symaddr_v(g_det);
    float* part = (float*)symaddr_v(g_part);
    float* mu = (float*)symaddr_v(g_mu);
    float* rstd = (float*)symaddr_v(g_rstd);
    unsigned short* Wh = (unsigned short*)symaddr_v(g_Wh);
    unsigned short* Wl = (unsigned short*)symaddr_v(g_Wl);
    unsigned short* XAh = (unsigned short*)symaddr_v(g_XAh);
    unsigned short* XAl = (unsigned short*)symaddr_v(g_XAl);
    unsigned short* H0h = (unsigned short*)symaddr_v(g_H0h);
    unsigned short* H0l = (unsigned short*)symaddr_v(g_H0l);
    unsigned short* H1h = (unsigned short*)symaddr_v(g_H1h);
    unsigned short* H1l = (unsigned short*)symaddr_v(g_H1l);

    const size_t XS = (size_t)N * DD;
    const size_t HS = (size_t)N * HH;

    copy_in_kernel<<<(N * DD + 255) / 256, 256>>>(x, X, N);

    wsplit_kernel<<<(65536 + 255) / 256, 256>>>(sW0, Wh + OFF_SW0,
                                                Wl + OFF_SW0, 65536);
    wsplit_kernel<<<(65536 + 255) / 256, 256>>>(tW0, Wh + OFF_TW0,
                                                Wl + OFF_TW0, 65536);
    wsplit_kernel<<<(1048576 + 255) / 256, 256>>>(sW1, Wh + OFF_SW1,
                                                  Wl + OFF_SW1, 1048576);
    wsplit_kernel<<<(1048576 + 255) / 256, 256>>>(tW1, Wh + OFF_TW1,
                                                  Wl + OFF_TW1, 1048576);
    wsplit_kernel<<<(65536 + 255) / 256, 256>>>(sW2, Wh + OFF_SW2,
                                                Wl + OFF_SW2, 65536);
    wsplit_kernel<<<(65536 + 255) / 256, 256>>>(tW2, Wh + OFF_TW2,
                                                Wl + OFF_TW2, 65536);

    int cur = 0;
    for (int l = 0; l < LL; l++) {
        float* Xc = X + (size_t)cur * XS;
        float* Xnext = X + (size_t)(cur ^ 1) * XS;

        if (l == 0) {
            stats1_kernel<<<256, 256>>>(Xc, part, N / 256);
            stats2_kernel<<<1, 64>>>(part, 256, 1.0f / (float)N, mu, rstd);
        } else {
            stats2_kernel<<<1, 64>>>(part, N / 128, 1.0f / (float)N, mu, rstd);
        }

        const int x1off = (l & 1) ? dH : 0;

        norm_kernel<<<(N * 8 + 255) / 256, 256>>>(Xc, XAh, XAl, mu, rstd,
                                                  x1off, N);

        mma_gemm_kernel<dH><<<dim3(HH / 128, N / 128, 2), 256, SMEMG2>>>(
            XAh, XAl, XAh, XAl, dH,
            Wh + OFF_SW0 + (size_t)l * HH * dH, Wl + OFF_SW0 + (size_t)l * HH * dH,
            Wh + OFF_TW0 + (size_t)l * HH * dH, Wl + OFF_TW0 + (size_t)l * HH * dH,
            sb0 + (size_t)l * HH, tb0 + (size_t)l * HH,
            H0h, H0l, H0h + HS, H0l + HS);

        mma_gemm_kernel<HH><<<dim3(HH / 128, N / 128, 2), 256, SMEMG2>>>(
            H0h, H0l, H0h + HS, H0l + HS, HH,
            Wh + OFF_SW1 + (size_t)l * HH * HH, Wl + OFF_SW1 + (size_t)l * HH * HH,
            Wh + OFF_TW1 + (size_t)l * HH * HH, Wl + OFF_TW1 + (size_t)l * HH * HH,
            sb1 + (size_t)l * HH, tb1 + (size_t)l * HH,
            H1h, H1l, H1h + HS, H1l + HS);

        mma_gemm3_kernel<<<N / 128, 256, SMEM3B>>>(
            H1h, H1l, H1h + HS, H1l + HS,
            Wh + OFF_SW2 + (size_t)l * dH * HH, Wl + OFF_SW2 + (size_t)l * dH * HH,
            Wh + OFF_TW2 + (size_t)l * dH * HH, Wl + OFF_TW2 + (size_t)l * dH * HH,
            sb2 + (size_t)l * dH, tb2 + (size_t)l * dH, Xc, Xnext, mu, rstd,
            det, part, x1off, (l == 0) ? 1 : 0);

        cur ^= 1;
    }

    gmm_kernel<<<N / 256, 256>>>(X + (size_t)cur * XS, means, det, out, N,
                                 full);
    if (full) final_reduce_kernel<<<1, 1024>>>(out, N);
}